// round 3
// baseline (speedup 1.0000x reference)
#include <cuda_runtime.h>
#include <math.h>

#define BB 2
#define NN 2048
#define DMODEL 512
#define HH 8
#define DK 64
#define MTOT (BB*NN)                 // 4096
#define HEADELEMS (BB*HH*NN*DK)      // 2097152
#define OUTHALF (MTOT*DMODEL)        // 2097152

// Scratch (allocation-free rule: __device__ globals)
__device__ float g_q [HEADELEMS];
__device__ float g_q1[HEADELEMS];
__device__ float g_q2[HEADELEMS];
__device__ float g_K1[HEADELEMS];
__device__ float g_K2[HEADELEMS];
__device__ float g_V1[HEADELEMS];
__device__ float g_V2[HEADELEMS];
__device__ float g_O1[OUTHALF];
__device__ float g_O2[OUTHALF];

typedef unsigned long long u64;

__device__ __forceinline__ u64 pack2(float lo, float hi) {
    u64 r; asm("mov.b64 %0, {%1, %2};" : "=l"(r) : "f"(lo), "f"(hi)); return r;
}
__device__ __forceinline__ void unpack2(u64 v, float& lo, float& hi) {
    asm("mov.b64 {%0, %1}, %2;" : "=f"(lo), "=f"(hi) : "l"(v));
}
// d.lo += a.lo*b.lo ; d.hi += a.hi*b.hi   (FFMA2 — 2 fp32 FMA per issue)
__device__ __forceinline__ void ffma2(u64& d, u64 a, u64 b) {
    asm("fma.rn.f32x2 %0, %1, %2, %0;" : "+l"(d) : "l"(a), "l"(b));
}
__device__ __forceinline__ void fmul2(u64& d, u64 a) {
    asm("mul.rn.f32x2 %0, %0, %1;" : "+l"(d) : "l"(a));
}

// ---------------------------------------------------------------------------
// Batched SGEMM: Y[m,o] = sum_k X[m,k] * W[o,k] + bias[o]
// M=4096, N=512, K=512. BM=BN=128, BK=16, 256 threads, 8x8 micro-tile,
// inner loop in fma.rn.f32x2. grid.z selects the (X,W,bias,D) tuple.
// ---------------------------------------------------------------------------
#define GBM 128
#define GBN 128
#define GBK 16

#define MODE_HEADS 0   // D[b,h,n,d]
#define MODE_ROW   1   // D[m*512+o]

struct GB {
    const float* X[7]; const float* W[7]; const float* Bi[7]; float* D[7];
};

template<int MODE>
__global__ __launch_bounds__(256)
void gemm_k(GB gb)
{
    const float* __restrict__ X    = gb.X[blockIdx.z];
    const float* __restrict__ W    = gb.W[blockIdx.z];
    const float* __restrict__ bias = gb.Bi[blockIdx.z];
    float* __restrict__ D          = gb.D[blockIdx.z];

    __shared__ float As[GBK][GBM + 4];
    __shared__ float Bs[GBK][GBN + 4];

    const int tid  = threadIdx.x;
    const int m0   = blockIdx.y * GBM;
    const int n0   = blockIdx.x * GBN;
    const int tRow = tid >> 4;     // 0..15
    const int tCol = tid & 15;     // 0..15

    u64 acc2[8][4];
#pragma unroll
    for (int i = 0; i < 8; i++)
#pragma unroll
        for (int jp = 0; jp < 4; jp++) acc2[i][jp] = 0ull;

    const int lr = tid >> 2;          // 0..63
    const int lc = (tid & 3) << 2;    // 0,4,8,12
    const float* Xp = X + (size_t)(m0 + lr) * DMODEL + lc;
    const float* Wp = W + (size_t)(n0 + lr) * DMODEL + lc;

    for (int k0 = 0; k0 < DMODEL; k0 += GBK) {
#pragma unroll
        for (int p = 0; p < 2; p++) {
            const int row = lr + p * 64;
            float4 a = *(const float4*)(Xp + (size_t)p * 64 * DMODEL + k0);
            As[lc + 0][row] = a.x;
            As[lc + 1][row] = a.y;
            As[lc + 2][row] = a.z;
            As[lc + 3][row] = a.w;
            float4 b = *(const float4*)(Wp + (size_t)p * 64 * DMODEL + k0);
            Bs[lc + 0][row] = b.x;
            Bs[lc + 1][row] = b.y;
            Bs[lc + 2][row] = b.z;
            Bs[lc + 3][row] = b.w;
        }
        __syncthreads();

#pragma unroll
        for (int k = 0; k < GBK; k++) {
            float4 a0 = *(const float4*)&As[k][tRow * 8];
            float4 a1 = *(const float4*)&As[k][tRow * 8 + 4];
            ulonglong2 b0 = *(const ulonglong2*)&Bs[k][tCol * 8];
            ulonglong2 b1 = *(const ulonglong2*)&Bs[k][tCol * 8 + 4];
            u64 kk[4] = {b0.x, b0.y, b1.x, b1.y};
            float aa[8] = {a0.x, a0.y, a0.z, a0.w, a1.x, a1.y, a1.z, a1.w};
#pragma unroll
            for (int i = 0; i < 8; i++) {
                u64 ad = pack2(aa[i], aa[i]);
#pragma unroll
                for (int jp = 0; jp < 4; jp++)
                    ffma2(acc2[i][jp], ad, kk[jp]);
            }
        }
        __syncthreads();
    }

    // epilogue
#pragma unroll
    for (int i = 0; i < 8; i++) {
        const int m  = m0 + tRow * 8 + i;
        const int bb = m >> 11;
        const int n  = m & 2047;
#pragma unroll
        for (int jp = 0; jp < 4; jp++) {
            float v0, v1;
            unpack2(acc2[i][jp], v0, v1);
            const int o0 = n0 + tCol * 8 + jp * 2;
            const float r0v = v0 + bias[o0];
            const float r1v = v1 + bias[o0 + 1];
            if (MODE == MODE_ROW) {
                D[(size_t)m * DMODEL + o0]     = r0v;
                D[(size_t)m * DMODEL + o0 + 1] = r1v;
            } else {
                const int h0 = o0 >> 6, d0 = o0 & 63;
                const size_t idx = (((size_t)(bb * HH + h0)) * NN + n) * DK + d0;
                D[idx]     = r0v;
                D[idx + 1] = r1v;   // o0 even, so same head
            }
        }
    }
}

// ---------------------------------------------------------------------------
// Flash-style attention, f32x2 inner loops.
// One block = 128 Q rows of one (b,h,variant). 128 threads, 16x8 thread grid,
// 8x8 micro-tiles. K-tile = 64 keys. Online softmax, fused scale*weights+mask.
// Q tile is q + q{1,2} fused at load time (removes inter-GEMM dependency).
// Smem: Qt[64][128] (d-major), Kt[64][64] (d-major), Vs[64][64] (c-major),
//       Pt[64][132] (c-major, 4-row XOR flip by key-block), cf[64], mk[64]
// ---------------------------------------------------------------------------
#define QTILE 128
#define KTILE 64
#define PTSTR 132

__global__ __launch_bounds__(128)
void attn_k(const int* __restrict__ mR, const int* __restrict__ mG,
            const float* __restrict__ wts)
{
    extern __shared__ float sm[];
    float* Qt = sm;                    // 8192
    float* Kt = sm + 8192;             // 4096
    float* Vs = sm + 12288;            // 4096
    float* Pt = sm + 16384;            // 8448
    float* cf = sm + 24832;            // 64
    float* mk = sm + 24896;            // 64

    const int var = blockIdx.z;
    const int bh  = blockIdx.y;
    const int bb  = bh >> 3;
    const int h   = bh & 7;
    const int qt  = blockIdx.x;

    const float* Q  = g_q + (size_t)bh * NN * DK + (size_t)qt * QTILE * DK;
    const float* Qx = (var ? g_q1 : g_q2) + (size_t)bh * NN * DK + (size_t)qt * QTILE * DK;
    const float* K  = (var ? g_K2 : g_K1) + (size_t)bh * NN * DK;
    const float* V  = (var ? g_V2 : g_V1) + (size_t)bh * NN * DK;
    const int*   msk = (var ? mG : mR) + bb * NN;
    const float* w   = wts + bb * NN;
    float* O = (var ? g_O2 : g_O1);

    const int tid  = threadIdx.x;
    const int tRow = tid >> 3;   // 0..15
    const int tCol = tid & 7;    // 0..7
    const int r0 = tRow * 8;
    const int c0 = tCol * 8;

    // Load Q tile transposed with fused add: row = tid, 16 float4 per row.
#pragma unroll
    for (int p = 0; p < 16; p++) {
        const int c4 = p * 4;
        float4 a = *(const float4*)(Q  + tid * DK + c4);
        float4 b = *(const float4*)(Qx + tid * DK + c4);
        Qt[(c4 + 0) * QTILE + tid] = a.x + b.x;
        Qt[(c4 + 1) * QTILE + tid] = a.y + b.y;
        Qt[(c4 + 2) * QTILE + tid] = a.z + b.z;
        Qt[(c4 + 3) * QTILE + tid] = a.w + b.w;
    }

    float m_i[8], l_i[8];
    u64 o2[8][4];
#pragma unroll
    for (int i = 0; i < 8; i++) {
        m_i[i] = -INFINITY; l_i[i] = 0.f;
#pragma unroll
        for (int jp = 0; jp < 4; jp++) o2[i][jp] = 0ull;
    }
    const float scale = 0.125f;
    const int pflip = (tCol & 1) * 4;   // Pt store flip for this thread's cols

    for (int kt = 0; kt < NN / KTILE; kt++) {
        __syncthreads();   // prev PV (Vs/Pt readers) done

        // K tile transposed: 2 threads/row, coalesced global, conflict-light STS
        {
            const int r  = tid >> 1;
            const int ch = (tid & 1) * 32;
#pragma unroll
            for (int p = 0; p < 8; p++) {
                const int c4 = ch + p * 4;
                float4 kv = *(const float4*)(K + (size_t)(kt * KTILE + r) * DK + c4);
                Kt[(c4 + 0) * KTILE + r] = kv.x;
                Kt[(c4 + 1) * KTILE + r] = kv.y;
                Kt[(c4 + 2) * KTILE + r] = kv.z;
                Kt[(c4 + 3) * KTILE + r] = kv.w;
            }
        }
        // V tile natural
#pragma unroll
        for (int p = 0; p < 8; p++) {
            const int fi = tid + p * 128;
            const int r  = fi >> 4;
            const int c4 = (fi & 15) << 2;
            float4 vv = *(const float4*)(V + (size_t)(kt * KTILE + r) * DK + c4);
            *(float4*)(Vs + r * DK + c4) = vv;
        }
        if (tid < 64) {
            cf[tid] = scale * w[kt * KTILE + tid];
            mk[tid] = (float)msk[kt * KTILE + tid];
        }
        __syncthreads();

        // S = Q K^T, pairs along key-cols
        u64 s2[8][4];
#pragma unroll
        for (int i = 0; i < 8; i++)
#pragma unroll
            for (int jp = 0; jp < 4; jp++) s2[i][jp] = 0ull;

#pragma unroll 4
        for (int d = 0; d < DK; d++) {
            float4 a0 = *(const float4*)&Qt[d * QTILE + r0];
            float4 a1 = *(const float4*)&Qt[d * QTILE + r0 + 4];
            ulonglong2 k0 = *(const ulonglong2*)&Kt[d * KTILE + c0];
            ulonglong2 k1 = *(const ulonglong2*)&Kt[d * KTILE + c0 + 4];
            u64 kk[4] = {k0.x, k0.y, k1.x, k1.y};
            float aa[8] = {a0.x, a0.y, a0.z, a0.w, a1.x, a1.y, a1.z, a1.w};
#pragma unroll
            for (int i = 0; i < 8; i++) {
                u64 ad = pack2(aa[i], aa[i]);
#pragma unroll
                for (int jp = 0; jp < 4; jp++)
                    ffma2(s2[i][jp], ad, kk[jp]);
            }
        }

        // scale/mask coefficients for this thread's 8 key-cols
        float cfj[8], mkj[8];
#pragma unroll
        for (int j = 0; j < 8; j++) { cfj[j] = cf[c0 + j]; mkj[j] = mk[c0 + j]; }

        // online softmax, two halves of 4 rows (bounds P-register pressure)
#pragma unroll
        for (int half = 0; half < 2; half++) {
            float ph[4][8];
#pragma unroll
            for (int ii = 0; ii < 4; ii++) {
                const int i = half * 4 + ii;
                float s[8];
#pragma unroll
                for (int jp = 0; jp < 4; jp++)
                    unpack2(s2[i][jp], s[jp * 2], s[jp * 2 + 1]);
#pragma unroll
                for (int j = 0; j < 8; j++)
                    s[j] = (mkj[j] != 0.f) ? -INFINITY : s[j] * cfj[j];

                float t = s[0];
#pragma unroll
                for (int j = 1; j < 8; j++) t = fmaxf(t, s[j]);
                t = fmaxf(t, __shfl_xor_sync(0xffffffffu, t, 4));
                t = fmaxf(t, __shfl_xor_sync(0xffffffffu, t, 2));
                t = fmaxf(t, __shfl_xor_sync(0xffffffffu, t, 1));
                const float mn = fmaxf(m_i[i], t);
                const float mx = fmaxf(mn, -1e30f);
                const float f  = __expf(m_i[i] - mx);
                m_i[i] = mn;

                float rs = 0.f;
#pragma unroll
                for (int j = 0; j < 8; j++) {
                    const float pv = __expf(s[j] - mx);
                    ph[ii][j] = pv;
                    rs += pv;
                }
                rs += __shfl_xor_sync(0xffffffffu, rs, 4);
                rs += __shfl_xor_sync(0xffffffffu, rs, 2);
                rs += __shfl_xor_sync(0xffffffffu, rs, 1);
                l_i[i] = l_i[i] * f + rs;

                u64 fd = pack2(f, f);
#pragma unroll
                for (int jp = 0; jp < 4; jp++) fmul2(o2[i][jp], fd);
            }
            // store this half's P, transposed with 4-row flip
            const int rbase = r0 + (half * 4 ^ pflip);
#pragma unroll
            for (int j = 0; j < 8; j++) {
                float4 pv = make_float4(ph[0][j], ph[1][j], ph[2][j], ph[3][j]);
                *(float4*)&Pt[(c0 + j) * PTSTR + rbase] = pv;
            }
        }
        __syncthreads();

        // O += P V, pairs along value-cols
#pragma unroll 2
        for (int c = 0; c < KTILE; c++) {
            const int fc = ((c >> 3) & 1) * 4;
            float4 lo = *(const float4*)&Pt[c * PTSTR + r0 + fc];
            float4 hi = *(const float4*)&Pt[c * PTSTR + r0 + (fc ^ 4)];
            ulonglong2 v0 = *(const ulonglong2*)&Vs[c * DK + c0];
            ulonglong2 v1 = *(const ulonglong2*)&Vs[c * DK + c0 + 4];
            u64 vv[4] = {v0.x, v0.y, v1.x, v1.y};
            float pp[8] = {lo.x, lo.y, lo.z, lo.w, hi.x, hi.y, hi.z, hi.w};
#pragma unroll
            for (int i = 0; i < 8; i++) {
                u64 pd = pack2(pp[i], pp[i]);
#pragma unroll
                for (int jp = 0; jp < 4; jp++)
                    ffma2(o2[i][jp], pd, vv[jp]);
            }
        }
    }

    // epilogue: normalize, write [B, N, H*64]
#pragma unroll
    for (int i = 0; i < 8; i++) {
        const float inv = 1.f / l_i[i];
        float o[8];
#pragma unroll
        for (int jp = 0; jp < 4; jp++)
            unpack2(o2[i][jp], o[jp * 2], o[jp * 2 + 1]);
        const int n = qt * QTILE + r0 + i;
        float* dst = O + ((size_t)bb * NN + n) * DMODEL + h * DK + c0;
        *(float4*)(dst)     = make_float4(o[0] * inv, o[1] * inv, o[2] * inv, o[3] * inv);
        *(float4*)(dst + 4) = make_float4(o[4] * inv, o[5] * inv, o[6] * inv, o[7] * inv);
    }
}

// ---------------------------------------------------------------------------
extern "C" void kernel_launch(void* const* d_in, const int* in_sizes, int n_in,
                              void* d_out, int out_size)
{
    const float* regions   = (const float*)d_in[0];
    const float* grids     = (const float*)d_in[1];
    const float* interests = (const float*)d_in[2];
    const int*   maskR     = (const int*)d_in[3];
    const int*   maskG     = (const int*)d_in[4];
    const float* wts       = (const float*)d_in[5];
    const float* Wq   = (const float*)d_in[6];
    const float* bq   = (const float*)d_in[7];
    const float* Wk   = (const float*)d_in[8];
    const float* bk   = (const float*)d_in[9];
    const float* Wv   = (const float*)d_in[10];
    const float* bv   = (const float*)d_in[11];
    const float* Wq12 = (const float*)d_in[12];
    const float* bq12 = (const float*)d_in[13];
    const float* Wo1  = (const float*)d_in[14];
    const float* bo1  = (const float*)d_in[15];
    const float* Wo2  = (const float*)d_in[16];
    const float* bo2  = (const float*)d_in[17];
    float* out = (float*)d_out;

    float *q, *q1, *q2, *K1, *K2, *V1, *V2, *O1, *O2;
    cudaGetSymbolAddress((void**)&q,  g_q);
    cudaGetSymbolAddress((void**)&q1, g_q1);
    cudaGetSymbolAddress((void**)&q2, g_q2);
    cudaGetSymbolAddress((void**)&K1, g_K1);
    cudaGetSymbolAddress((void**)&K2, g_K2);
    cudaGetSymbolAddress((void**)&V1, g_V1);
    cudaGetSymbolAddress((void**)&V2, g_V2);
    cudaGetSymbolAddress((void**)&O1, g_O1);
    cudaGetSymbolAddress((void**)&O2, g_O2);

    const int ASMEM = 24960 * (int)sizeof(float);   // 99840 B
    cudaFuncSetAttribute(attn_k, cudaFuncAttributeMaxDynamicSharedMemorySize, ASMEM);

    // All 7 projections — ONE launch (independent outputs, no intra-launch deps)
    GB pj;
    pj.X[0] = interests; pj.W[0] = Wq;   pj.Bi[0] = bq;   pj.D[0] = q;
    pj.X[1] = regions;   pj.W[1] = Wq12; pj.Bi[1] = bq12; pj.D[1] = q1;
    pj.X[2] = grids;     pj.W[2] = Wq12; pj.Bi[2] = bq12; pj.D[2] = q2;
    pj.X[3] = regions;   pj.W[3] = Wk;   pj.Bi[3] = bk;   pj.D[3] = K1;
    pj.X[4] = grids;     pj.W[4] = Wk;   pj.Bi[4] = bk;   pj.D[4] = K2;
    pj.X[5] = regions;   pj.W[5] = Wv;   pj.Bi[5] = bv;   pj.D[5] = V1;
    pj.X[6] = grids;     pj.W[6] = Wv;   pj.Bi[6] = bv;   pj.D[6] = V2;
    gemm_k<MODE_HEADS><<<dim3(DMODEL / GBN, MTOT / GBM, 7), 256>>>(pj);

    // Both attentions in one launch
    attn_k<<<dim3(NN / QTILE, BB * HH, 2), 128, ASMEM>>>(maskR, maskG, wts);

    // Output projections — one launch
    GB po;
    po.X[0] = O1; po.W[0] = Wo1; po.Bi[0] = bo1; po.D[0] = out;
    po.X[1] = O2; po.W[1] = Wo2; po.Bi[1] = bo2; po.D[1] = out + OUTHALF;
    for (int i = 2; i < 7; i++) { po.X[i] = O1; po.W[i] = Wo1; po.Bi[i] = bo1; po.D[i] = out; }
    gemm_k<MODE_ROW><<<dim3(DMODEL / GBN, MTOT / GBM, 2), 256>>>(po);
}

// round 5
// speedup vs baseline: 1.8146x; 1.8146x over previous
#include <cuda_runtime.h>
#include <cuda_bf16.h>
#include <math.h>
#include <stdint.h>

#define BB 2
#define NN 2048
#define DMODEL 512
#define HH 8
#define DK 64
#define MTOT (BB*NN)                 // 4096
#define HEADELEMS (BB*HH*NN*DK)      // 2097152
#define OUTHALF (MTOT*DMODEL)        // 2097152

// Scratch (allocation-free rule: __device__ globals)
__device__ float g_q [HEADELEMS];
__device__ float g_q1[HEADELEMS];
__device__ float g_q2[HEADELEMS];
__device__ float g_K1[HEADELEMS];
__device__ float g_K2[HEADELEMS];
__device__ float g_V1[HEADELEMS];
__device__ float g_V2[HEADELEMS];
__device__ float g_O1[OUTHALF];
__device__ float g_O2[OUTHALF];

__device__ __forceinline__ uint32_t smem_u32(const void* p) {
    uint32_t a;
    asm("{ .reg .u64 t; cvta.to.shared.u64 t, %1; cvt.u32.u64 %0, t; }"
        : "=r"(a) : "l"(p));
    return a;
}

// ---- warp-level tensor core primitives (family-common PTX, no 'a' features)
__device__ __forceinline__ void ldm4(unsigned r[4], uint32_t addr) {
    asm volatile("ldmatrix.sync.aligned.m8n8.x4.shared.b16 {%0,%1,%2,%3}, [%4];"
        : "=r"(r[0]), "=r"(r[1]), "=r"(r[2]), "=r"(r[3]) : "r"(addr));
}
__device__ __forceinline__ void mma16816(float c[4], const unsigned a[4],
                                         const unsigned b0, const unsigned b1) {
    asm volatile(
        "mma.sync.aligned.m16n8k16.row.col.f32.bf16.bf16.f32 "
        "{%0,%1,%2,%3}, {%4,%5,%6,%7}, {%8,%9}, {%0,%1,%2,%3};"
        : "+f"(c[0]), "+f"(c[1]), "+f"(c[2]), "+f"(c[3])
        : "r"(a[0]), "r"(a[1]), "r"(a[2]), "r"(a[3]), "r"(b0), "r"(b1));
}

// split 8 fp32 -> 8 bf16 hi + 8 bf16 lo (residual)
__device__ __forceinline__ void split8(float4 a, float4 b, uint4& hi, uint4& lo) {
    float x[8] = {a.x, a.y, a.z, a.w, b.x, b.y, b.z, b.w};
    unsigned hw[4], lw[4];
#pragma unroll
    for (int i = 0; i < 4; i++) {
        __nv_bfloat16 h0 = __float2bfloat16_rn(x[2*i]);
        __nv_bfloat16 h1 = __float2bfloat16_rn(x[2*i+1]);
        float l0 = x[2*i]   - __bfloat162float(h0);
        float l1 = x[2*i+1] - __bfloat162float(h1);
        __nv_bfloat162 hp; hp.x = h0; hp.y = h1;
        __nv_bfloat162 lp; lp.x = __float2bfloat16_rn(l0); lp.y = __float2bfloat16_rn(l1);
        hw[i] = *reinterpret_cast<unsigned*>(&hp);
        lw[i] = *reinterpret_cast<unsigned*>(&lp);
    }
    hi = make_uint4(hw[0], hw[1], hw[2], hw[3]);
    lo = make_uint4(lw[0], lw[1], lw[2], lw[3]);
}

// ===========================================================================
// HMMA split-bf16 SGEMM: C[m,o] = sum_k X[m,k]*W[o,k] + bias[o]
// Block tile 128x128, 8 warps (2M x 4N), warp tile 64x32, K-chunk 32.
// Smem rows padded to 80B (5 x 16B groups) -> conflict-free ldmatrix.
// 3-term split: C = Xh*Wh + Xh*Wl + Xl*Wh, fp32 accum in registers.
// ===========================================================================
#define MODE_HEADS 0
#define MODE_ROW   1
#define RSTR 80                       // bytes per smem row (32 bf16 + 8 pad)
#define TILEB (128 * RSTR)            // 10240 B per tile

struct GB {
    const float* X[7]; const float* W[7]; const float* Bi[7]; float* D[7];
};

template<int MODE>
__global__ __launch_bounds__(256)
void gemm_mma(GB gb)
{
    __shared__ __align__(16) char smc[4 * TILEB];   // 40 KB: Ah, Al, Bh, Bl
    const uint32_t sb = smem_u32(smc);
    const uint32_t sAh = sb, sAl = sb + TILEB, sBh = sb + 2*TILEB, sBl = sb + 3*TILEB;

    const float* __restrict__ X    = gb.X[blockIdx.z];
    const float* __restrict__ W    = gb.W[blockIdx.z];
    const float* __restrict__ bias = gb.Bi[blockIdx.z];
    float* __restrict__ D          = gb.D[blockIdx.z];
    const int m0 = blockIdx.y * 128;
    const int n0 = blockIdx.x * 128;

    const int tid  = threadIdx.x;
    const int wid  = tid >> 5;
    const int lane = tid & 31;
    const int warpM = wid >> 2;          // 0..1
    const int warpN = wid & 3;           // 0..3

    // ldmatrix per-lane row/koffset decomposition
    const int arow  = (lane & 7) + ((lane >> 3) & 1) * 8;   // A: rows, k-half by bit4
    const int akoff = ((lane >> 4) & 1) * 16;
    const int brow  = (lane & 7) + ((lane >> 4) & 1) * 8;   // B: n-rows, k-half by bit3
    const int bkoff = ((lane >> 3) & 1) * 16;

    float c[4][4][4];
#pragma unroll
    for (int im = 0; im < 4; im++)
#pragma unroll
        for (int jn = 0; jn < 4; jn++)
#pragma unroll
            for (int e = 0; e < 4; e++) c[im][jn][e] = 0.f;

    const int lrow = tid >> 2;          // 0..63 ... wait: 256 threads -> s>>2 below
#pragma unroll 1
    for (int kc = 0; kc < 16; kc++) {
        __syncthreads();
        // load + split chunk: A 128x32, B 128x32 (each thread: 2 rows-of-8 per matrix)
#pragma unroll
        for (int p = 0; p < 2; p++) {
            const int s   = tid + p * 256;       // 0..511
            const int row = s >> 2;              // 0..127
            const int k8  = (s & 3) * 8;         // 0,8,16,24
            const uint32_t soff = (uint32_t)(row * RSTR + k8 * 2);
            {
                const float* xp = X + (size_t)(m0 + row) * DMODEL + kc * 32 + k8;
                uint4 hi, lo;
                split8(*(const float4*)xp, *(const float4*)(xp + 4), hi, lo);
                *(uint4*)(smc + (soff))         = hi;
                *(uint4*)(smc + (TILEB + soff)) = lo;
            }
            {
                const float* wp = W + (size_t)(n0 + row) * DMODEL + kc * 32 + k8;
                uint4 hi, lo;
                split8(*(const float4*)wp, *(const float4*)(wp + 4), hi, lo);
                *(uint4*)(smc + (2*TILEB + soff)) = hi;
                *(uint4*)(smc + (3*TILEB + soff)) = lo;
            }
        }
        __syncthreads();

#pragma unroll
        for (int ks = 0; ks < 2; ks++) {
            // B fragments: 2 pairs of n-frags (hi & lo)
            unsigned bh[2][4], bl[2][4];
#pragma unroll
            for (int jp = 0; jp < 2; jp++) {
                const uint32_t bo = (uint32_t)((warpN * 32 + jp * 16 + brow) * RSTR
                                               + ks * 32 + bkoff);
                ldm4(bh[jp], sBh + bo);
                ldm4(bl[jp], sBl + bo);
            }
#pragma unroll
            for (int im = 0; im < 4; im++) {
                const uint32_t ao = (uint32_t)((warpM * 64 + im * 16 + arow) * RSTR
                                               + ks * 32 + akoff);
                unsigned ah[4], al[4];
                ldm4(ah, sAh + ao);
                ldm4(al, sAl + ao);
#pragma unroll
                for (int jn = 0; jn < 4; jn++) {
                    const int jp = jn >> 1, jo = (jn & 1) * 2;
                    mma16816(c[im][jn], ah, bh[jp][jo], bh[jp][jo + 1]);
                    mma16816(c[im][jn], ah, bl[jp][jo], bl[jp][jo + 1]);
                    mma16816(c[im][jn], al, bh[jp][jo], bh[jp][jo + 1]);
                }
            }
        }
    }
    (void)lrow;

    // epilogue: c0,c1 -> (row, col..col+1); c2,c3 -> (row+8, ...)
    const int rbase = m0 + warpM * 64 + (lane >> 2);
    const int cbase = n0 + warpN * 32 + (lane & 3) * 2;
#pragma unroll
    for (int im = 0; im < 4; im++) {
#pragma unroll
        for (int jn = 0; jn < 4; jn++) {
            const int col = cbase + jn * 8;
            const float b0 = bias[col], b1 = bias[col + 1];
#pragma unroll
            for (int half = 0; half < 2; half++) {
                const int m  = rbase + im * 16 + half * 8;
                const float v0 = c[im][jn][half * 2]     + b0;
                const float v1 = c[im][jn][half * 2 + 1] + b1;
                if (MODE == MODE_ROW) {
                    *(float2*)(D + (size_t)m * DMODEL + col) = make_float2(v0, v1);
                } else {
                    const int bb = m >> 11;
                    const int n  = m & 2047;
                    const int h  = col >> 6, d = col & 63;
                    *(float2*)(D + (((size_t)(bb * HH + h)) * NN + n) * DK + d) =
                        make_float2(v0, v1);
                }
            }
        }
    }
}

// ===========================================================================
// Flash-style attention (proven R1 kernel, exact fp32), q+q{1,2} fused at
// Q-tile load. One block = 64 Q rows of one (b,h,variant).
// grid = (N/64, B*H, 2), 256 threads, 16x16 layout, 4x4 micro-tiles.
// ===========================================================================
__global__ __launch_bounds__(256)
void attn_k(const int* __restrict__ mR, const int* __restrict__ mG,
            const float* __restrict__ wts)
{
    extern __shared__ float sm[];
    float* Qt = sm;              // [64][64] transposed: Qt[d*64 + r]
    float* Kt = sm + 4096;       // [64][64] transposed
    float* Vs = sm + 8192;       // [64][64] natural
    float* Ps = sm + 12288;      // [64][64]
    float* cf = sm + 16384;      // 64
    float* mk = sm + 16448;      // 64

    const int var = blockIdx.z;
    const int bh  = blockIdx.y;
    const int bb  = bh >> 3;
    const int h   = bh & 7;
    const int qt  = blockIdx.x;

    const float* Q  = g_q + (size_t)bh * NN * DK + (size_t)qt * 64 * DK;
    const float* Qx = (var ? g_q1 : g_q2) + (size_t)bh * NN * DK + (size_t)qt * 64 * DK;
    const float* K  = (var ? g_K2 : g_K1) + (size_t)bh * NN * DK;
    const float* V  = (var ? g_V2 : g_V1) + (size_t)bh * NN * DK;
    const int*   msk = (var ? mG : mR) + bb * NN;
    const float* w   = wts + bb * NN;
    float* O = (var ? g_O2 : g_O1);

    const int tid  = threadIdx.x;
    const int tRow = tid >> 4;
    const int tCol = tid & 15;
    const int r0 = tRow * 4;
    const int c0 = tCol * 4;

#pragma unroll
    for (int p = 0; p < 4; p++) {
        const int fi = tid + p * 256;
        const int r  = fi >> 4;
        const int c4 = (fi & 15) << 2;
        float4 a = *(const float4*)(Q  + r * DK + c4);
        float4 b = *(const float4*)(Qx + r * DK + c4);
        Qt[(c4 + 0) * 64 + r] = a.x + b.x;
        Qt[(c4 + 1) * 64 + r] = a.y + b.y;
        Qt[(c4 + 2) * 64 + r] = a.z + b.z;
        Qt[(c4 + 3) * 64 + r] = a.w + b.w;
    }

    float m_i[4], l_i[4], o[4][4];
#pragma unroll
    for (int i = 0; i < 4; i++) {
        m_i[i] = -INFINITY;
        l_i[i] = 0.f;
#pragma unroll
        for (int j = 0; j < 4; j++) o[i][j] = 0.f;
    }
    const float scale = 0.125f;

    for (int kt = 0; kt < NN / 64; kt++) {
        __syncthreads();
#pragma unroll
        for (int p = 0; p < 4; p++) {
            const int fi = tid + p * 256;
            const int r  = fi >> 4;
            const int c4 = (fi & 15) << 2;
            float4 kv = *(const float4*)(K + (size_t)(kt * 64 + r) * DK + c4);
            Kt[(c4 + 0) * 64 + r] = kv.x;
            Kt[(c4 + 1) * 64 + r] = kv.y;
            Kt[(c4 + 2) * 64 + r] = kv.z;
            Kt[(c4 + 3) * 64 + r] = kv.w;
            float4 vv = *(const float4*)(V + (size_t)(kt * 64 + r) * DK + c4);
            *(float4*)(Vs + r * 64 + c4) = vv;
        }
        if (tid < 64) {
            cf[tid] = scale * w[kt * 64 + tid];
            mk[tid] = (float)msk[kt * 64 + tid];
        }
        __syncthreads();

        float s[4][4];
#pragma unroll
        for (int i = 0; i < 4; i++)
#pragma unroll
            for (int j = 0; j < 4; j++) s[i][j] = 0.f;

#pragma unroll 8
        for (int d = 0; d < 64; d++) {
            float4 q4 = *(const float4*)(Qt + d * 64 + r0);
            float4 k4 = *(const float4*)(Kt + d * 64 + c0);
            float aq[4] = {q4.x, q4.y, q4.z, q4.w};
            float ak[4] = {k4.x, k4.y, k4.z, k4.w};
#pragma unroll
            for (int i = 0; i < 4; i++)
#pragma unroll
                for (int j = 0; j < 4; j++)
                    s[i][j] += aq[i] * ak[j];
        }

        float cfj[4], mkj[4];
#pragma unroll
        for (int j = 0; j < 4; j++) { cfj[j] = cf[c0 + j]; mkj[j] = mk[c0 + j]; }
#pragma unroll
        for (int i = 0; i < 4; i++)
#pragma unroll
            for (int j = 0; j < 4; j++)
                s[i][j] = (mkj[j] != 0.f) ? -INFINITY : s[i][j] * cfj[j];

        float f[4], mx[4];
#pragma unroll
        for (int i = 0; i < 4; i++) {
            float t = fmaxf(fmaxf(s[i][0], s[i][1]), fmaxf(s[i][2], s[i][3]));
            t = fmaxf(t, __shfl_xor_sync(0xffffffffu, t, 8));
            t = fmaxf(t, __shfl_xor_sync(0xffffffffu, t, 4));
            t = fmaxf(t, __shfl_xor_sync(0xffffffffu, t, 2));
            t = fmaxf(t, __shfl_xor_sync(0xffffffffu, t, 1));
            const float mn = fmaxf(m_i[i], t);
            mx[i] = fmaxf(mn, -1e30f);
            f[i]  = __expf(m_i[i] - mx[i]);
            m_i[i] = mn;
        }

#pragma unroll
        for (int i = 0; i < 4; i++) {
            float p0 = __expf(s[i][0] - mx[i]);
            float p1 = __expf(s[i][1] - mx[i]);
            float p2 = __expf(s[i][2] - mx[i]);
            float p3 = __expf(s[i][3] - mx[i]);
            float rs = (p0 + p1) + (p2 + p3);
            rs += __shfl_xor_sync(0xffffffffu, rs, 8);
            rs += __shfl_xor_sync(0xffffffffu, rs, 4);
            rs += __shfl_xor_sync(0xffffffffu, rs, 2);
            rs += __shfl_xor_sync(0xffffffffu, rs, 1);
            l_i[i] = l_i[i] * f[i] + rs;
            *(float4*)(Ps + (r0 + i) * 64 + c0) = make_float4(p0, p1, p2, p3);
        }
        __syncthreads();

#pragma unroll
        for (int i = 0; i < 4; i++)
#pragma unroll
            for (int j = 0; j < 4; j++) o[i][j] *= f[i];

#pragma unroll 4
        for (int c = 0; c < 64; c++) {
            float4 v4 = *(const float4*)(Vs + c * 64 + c0);
            float av[4] = {v4.x, v4.y, v4.z, v4.w};
            float pv[4];
#pragma unroll
            for (int i = 0; i < 4; i++) pv[i] = Ps[(r0 + i) * 64 + c];
#pragma unroll
            for (int i = 0; i < 4; i++)
#pragma unroll
                for (int j = 0; j < 4; j++)
                    o[i][j] += pv[i] * av[j];
        }
    }

#pragma unroll
    for (int i = 0; i < 4; i++) {
        const float inv = 1.f / l_i[i];
        const int n = qt * 64 + r0 + i;
        const size_t base = ((size_t)bb * NN + n) * DMODEL + h * DK + c0;
        *(float4*)(O + base) =
            make_float4(o[i][0] * inv, o[i][1] * inv, o[i][2] * inv, o[i][3] * inv);
    }
}

// ===========================================================================
extern "C" void kernel_launch(void* const* d_in, const int* in_sizes, int n_in,
                              void* d_out, int out_size)
{
    const float* regions   = (const float*)d_in[0];
    const float* grids     = (const float*)d_in[1];
    const float* interests = (const float*)d_in[2];
    const int*   maskR     = (const int*)d_in[3];
    const int*   maskG     = (const int*)d_in[4];
    const float* wts       = (const float*)d_in[5];
    const float* Wq   = (const float*)d_in[6];
    const float* bq   = (const float*)d_in[7];
    const float* Wk   = (const float*)d_in[8];
    const float* bk   = (const float*)d_in[9];
    const float* Wv   = (const float*)d_in[10];
    const float* bv   = (const float*)d_in[11];
    const float* Wq12 = (const float*)d_in[12];
    const float* bq12 = (const float*)d_in[13];
    const float* Wo1  = (const float*)d_in[14];
    const float* bo1  = (const float*)d_in[15];
    const float* Wo2  = (const float*)d_in[16];
    const float* bo2  = (const float*)d_in[17];
    float* out = (float*)d_out;

    float *q, *q1, *q2, *K1, *K2, *V1, *V2, *O1, *O2;
    cudaGetSymbolAddress((void**)&q,  g_q);
    cudaGetSymbolAddress((void**)&q1, g_q1);
    cudaGetSymbolAddress((void**)&q2, g_q2);
    cudaGetSymbolAddress((void**)&K1, g_K1);
    cudaGetSymbolAddress((void**)&K2, g_K2);
    cudaGetSymbolAddress((void**)&V1, g_V1);
    cudaGetSymbolAddress((void**)&V2, g_V2);
    cudaGetSymbolAddress((void**)&O1, g_O1);
    cudaGetSymbolAddress((void**)&O2, g_O2);

    const int ASMEM = (4 * 64 * 64 + 128) * (int)sizeof(float);  // 66048 B
    cudaFuncSetAttribute(attn_k, cudaFuncAttributeMaxDynamicSharedMemorySize, ASMEM);

    // All 7 projections — one HMMA launch (z selects GEMM)
    GB pj;
    pj.X[0] = interests; pj.W[0] = Wq;   pj.Bi[0] = bq;   pj.D[0] = q;
    pj.X[1] = regions;   pj.W[1] = Wq12; pj.Bi[1] = bq12; pj.D[1] = q1;
    pj.X[2] = grids;     pj.W[2] = Wq12; pj.Bi[2] = bq12; pj.D[2] = q2;
    pj.X[3] = regions;   pj.W[3] = Wk;   pj.Bi[3] = bk;   pj.D[3] = K1;
    pj.X[4] = grids;     pj.W[4] = Wk;   pj.Bi[4] = bk;   pj.D[4] = K2;
    pj.X[5] = regions;   pj.W[5] = Wv;   pj.Bi[5] = bv;   pj.D[5] = V1;
    pj.X[6] = grids;     pj.W[6] = Wv;   pj.Bi[6] = bv;   pj.D[6] = V2;
    gemm_mma<MODE_HEADS><<<dim3(DMODEL / 128, MTOT / 128, 7), 256>>>(pj);

    // Both attentions in one launch (exact fp32)
    attn_k<<<dim3(NN / 64, BB * HH, 2), 256, ASMEM>>>(maskR, maskG, wts);

    // Output projections — one HMMA launch
    GB po;
    po.X[0] = O1; po.W[0] = Wo1; po.Bi[0] = bo1; po.D[0] = out;
    po.X[1] = O2; po.W[1] = Wo2; po.Bi[1] = bo2; po.D[1] = out + OUTHALF;
    for (int i = 2; i < 7; i++) { po.X[i] = O1; po.W[i] = Wo1; po.Bi[i] = bo1; po.D[i] = out; }
    gemm_mma<MODE_ROW><<<dim3(DMODEL / 128, MTOT / 128, 2), 256>>>(po);
}

// round 7
// speedup vs baseline: 3.7589x; 2.0714x over previous
#include <cuda_runtime.h>
#include <cuda_bf16.h>
#include <math.h>
#include <stdint.h>

#define BB 2
#define NN 2048
#define DMODEL 512
#define HH 8
#define DK 64
#define MTOT (BB*NN)                 // 4096
#define HEADELEMS (BB*HH*NN*DK)      // 2097152
#define OUTHALF (MTOT*DMODEL)        // 2097152

// Scratch (allocation-free rule: __device__ globals)
__device__ float g_q [HEADELEMS];
__device__ float g_q1[HEADELEMS];
__device__ float g_q2[HEADELEMS];
__device__ float g_K1[HEADELEMS];
__device__ float g_K2[HEADELEMS];
__device__ float g_V1[HEADELEMS];
__device__ float g_V2[HEADELEMS];
__device__ float g_O1[OUTHALF];
__device__ float g_O2[OUTHALF];

__device__ __forceinline__ uint32_t smem_u32(const void* p) {
    uint32_t a;
    asm("{ .reg .u64 t; cvta.to.shared.u64 t, %1; cvt.u32.u64 %0, t; }"
        : "=r"(a) : "l"(p));
    return a;
}

// ---- warp-level tensor core primitives (family-common PTX, no 'a' features)
__device__ __forceinline__ void ldm4(unsigned r[4], uint32_t addr) {
    asm volatile("ldmatrix.sync.aligned.m8n8.x4.shared.b16 {%0,%1,%2,%3}, [%4];"
        : "=r"(r[0]), "=r"(r[1]), "=r"(r[2]), "=r"(r[3]) : "r"(addr));
}
__device__ __forceinline__ void ldm4t(unsigned r[4], uint32_t addr) {
    asm volatile("ldmatrix.sync.aligned.m8n8.x4.trans.shared.b16 {%0,%1,%2,%3}, [%4];"
        : "=r"(r[0]), "=r"(r[1]), "=r"(r[2]), "=r"(r[3]) : "r"(addr));
}
__device__ __forceinline__ void mma16816(float c[4], const unsigned a[4],
                                         const unsigned b0, const unsigned b1) {
    asm volatile(
        "mma.sync.aligned.m16n8k16.row.col.f32.bf16.bf16.f32 "
        "{%0,%1,%2,%3}, {%4,%5,%6,%7}, {%8,%9}, {%0,%1,%2,%3};"
        : "+f"(c[0]), "+f"(c[1]), "+f"(c[2]), "+f"(c[3])
        : "r"(a[0]), "r"(a[1]), "r"(a[2]), "r"(a[3]), "r"(b0), "r"(b1));
}

// split 8 fp32 -> 8 bf16 hi + 8 bf16 lo (residual)
__device__ __forceinline__ void split8(float4 a, float4 b, uint4& hi, uint4& lo) {
    float x[8] = {a.x, a.y, a.z, a.w, b.x, b.y, b.z, b.w};
    unsigned hw[4], lw[4];
#pragma unroll
    for (int i = 0; i < 4; i++) {
        __nv_bfloat16 h0 = __float2bfloat16_rn(x[2*i]);
        __nv_bfloat16 h1 = __float2bfloat16_rn(x[2*i+1]);
        float l0 = x[2*i]   - __bfloat162float(h0);
        float l1 = x[2*i+1] - __bfloat162float(h1);
        __nv_bfloat162 hp; hp.x = h0; hp.y = h1;
        __nv_bfloat162 lp; lp.x = __float2bfloat16_rn(l0); lp.y = __float2bfloat16_rn(l1);
        hw[i] = *reinterpret_cast<unsigned*>(&hp);
        lw[i] = *reinterpret_cast<unsigned*>(&lp);
    }
    hi = make_uint4(hw[0], hw[1], hw[2], hw[3]);
    lo = make_uint4(lw[0], lw[1], lw[2], lw[3]);
}

// ===========================================================================
// HMMA split-bf16 SGEMM (unchanged from R4 — proven): C = X W^T + bias
// ===========================================================================
#define MODE_HEADS 0
#define MODE_ROW   1
#define RSTR 80
#define TILEB (128 * RSTR)

struct GB {
    const float* X[7]; const float* W[7]; const float* Bi[7]; float* D[7];
};

template<int MODE>
__global__ __launch_bounds__(256)
void gemm_mma(GB gb)
{
    __shared__ __align__(16) char smc[4 * TILEB];
    const uint32_t sb = smem_u32(smc);
    const uint32_t sAh = sb, sAl = sb + TILEB, sBh = sb + 2*TILEB, sBl = sb + 3*TILEB;

    const float* __restrict__ X    = gb.X[blockIdx.z];
    const float* __restrict__ W    = gb.W[blockIdx.z];
    const float* __restrict__ bias = gb.Bi[blockIdx.z];
    float* __restrict__ D          = gb.D[blockIdx.z];
    const int m0 = blockIdx.y * 128;
    const int n0 = blockIdx.x * 128;

    const int tid  = threadIdx.x;
    const int wid  = tid >> 5;
    const int lane = tid & 31;
    const int warpM = wid >> 2;
    const int warpN = wid & 3;

    const int arow  = (lane & 7) + ((lane >> 3) & 1) * 8;
    const int akoff = ((lane >> 4) & 1) * 16;
    const int brow  = (lane & 7) + ((lane >> 4) & 1) * 8;
    const int bkoff = ((lane >> 3) & 1) * 16;

    float c[4][4][4];
#pragma unroll
    for (int im = 0; im < 4; im++)
#pragma unroll
        for (int jn = 0; jn < 4; jn++)
#pragma unroll
            for (int e = 0; e < 4; e++) c[im][jn][e] = 0.f;

#pragma unroll 1
    for (int kc = 0; kc < 16; kc++) {
        __syncthreads();
#pragma unroll
        for (int p = 0; p < 2; p++) {
            const int s   = tid + p * 256;
            const int row = s >> 2;
            const int k8  = (s & 3) * 8;
            const uint32_t soff = (uint32_t)(row * RSTR + k8 * 2);
            {
                const float* xp = X + (size_t)(m0 + row) * DMODEL + kc * 32 + k8;
                uint4 hi, lo;
                split8(*(const float4*)xp, *(const float4*)(xp + 4), hi, lo);
                *(uint4*)(smc + (soff))         = hi;
                *(uint4*)(smc + (TILEB + soff)) = lo;
            }
            {
                const float* wp = W + (size_t)(n0 + row) * DMODEL + kc * 32 + k8;
                uint4 hi, lo;
                split8(*(const float4*)wp, *(const float4*)(wp + 4), hi, lo);
                *(uint4*)(smc + (2*TILEB + soff)) = hi;
                *(uint4*)(smc + (3*TILEB + soff)) = lo;
            }
        }
        __syncthreads();

#pragma unroll
        for (int ks = 0; ks < 2; ks++) {
            unsigned bh[2][4], bl[2][4];
#pragma unroll
            for (int jp = 0; jp < 2; jp++) {
                const uint32_t bo = (uint32_t)((warpN * 32 + jp * 16 + brow) * RSTR
                                               + ks * 32 + bkoff);
                ldm4(bh[jp], sBh + bo);
                ldm4(bl[jp], sBl + bo);
            }
#pragma unroll
            for (int im = 0; im < 4; im++) {
                const uint32_t ao = (uint32_t)((warpM * 64 + im * 16 + arow) * RSTR
                                               + ks * 32 + akoff);
                unsigned ah[4], al[4];
                ldm4(ah, sAh + ao);
                ldm4(al, sAl + ao);
#pragma unroll
                for (int jn = 0; jn < 4; jn++) {
                    const int jp = jn >> 1, jo = (jn & 1) * 2;
                    mma16816(c[im][jn], ah, bh[jp][jo], bh[jp][jo + 1]);
                    mma16816(c[im][jn], ah, bl[jp][jo], bl[jp][jo + 1]);
                    mma16816(c[im][jn], al, bh[jp][jo], bh[jp][jo + 1]);
                }
            }
        }
    }

    const int rbase = m0 + warpM * 64 + (lane >> 2);
    const int cbase = n0 + warpN * 32 + (lane & 3) * 2;
#pragma unroll
    for (int im = 0; im < 4; im++) {
#pragma unroll
        for (int jn = 0; jn < 4; jn++) {
            const int col = cbase + jn * 8;
            const float b0 = bias[col], b1 = bias[col + 1];
#pragma unroll
            for (int half = 0; half < 2; half++) {
                const int m  = rbase + im * 16 + half * 8;
                const float v0 = c[im][jn][half * 2]     + b0;
                const float v1 = c[im][jn][half * 2 + 1] + b1;
                if (MODE == MODE_ROW) {
                    *(float2*)(D + (size_t)m * DMODEL + col) = make_float2(v0, v1);
                } else {
                    const int bb = m >> 11;
                    const int n  = m & 2047;
                    const int h  = col >> 6, d = col & 63;
                    *(float2*)(D + (((size_t)(bb * HH + h)) * NN + n) * DK + d) =
                        make_float2(v0, v1);
                }
            }
        }
    }
}

// ===========================================================================
// HMMA FlashAttention: block = 128 Q rows of one (b,h,var), 8 warps x 16 rows.
// Key tiles of 64, 32 iterations. 3-term split-bf16 on QK^T and PV.
// P stays in registers (S-accum layout == PV A-frag layout).
// Smem stride 144B rows (16B aligned, conflict-free ldmatrix).
// ===========================================================================
#define AQROWS 128
#define AKT 64
#define ASTRB 144                    // bytes per row (64 bf16 + 8 pad)
// smem offsets (bytes)
#define AQH 0
#define AQL (AQH + 128*ASTRB)        // 18432
#define AKH (AQL + 128*ASTRB)        // 36864
#define AKL (AKH + 64*ASTRB)         // 46080
#define AVH (AKL + 64*ASTRB)         // 55296
#define AVL (AVH + 64*ASTRB)         // 64512
#define ACF (AVL + 64*ASTRB)         // 73728
#define ASMEMB (ACF + 64*8)          // 74240

__global__ __launch_bounds__(256)
void attn_mma(const int* __restrict__ mR, const int* __restrict__ mG,
              const float* __restrict__ wts)
{
    extern __shared__ __align__(16) char smn[];
    const uint32_t sb = smem_u32(smn);

    const int var = blockIdx.z;
    const int bh  = blockIdx.y;
    const int bb  = bh >> 3;
    const int h   = bh & 7;
    const int qt  = blockIdx.x;

    const float* Q  = g_q + (size_t)bh * NN * DK + (size_t)qt * AQROWS * DK;
    const float* Qx = (var ? g_q1 : g_q2) + (size_t)bh * NN * DK + (size_t)qt * AQROWS * DK;
    const float* K  = (var ? g_K2 : g_K1) + (size_t)bh * NN * DK;
    const float* V  = (var ? g_V2 : g_V1) + (size_t)bh * NN * DK;
    const int*   msk = (var ? mG : mR) + bb * NN;
    const float* w   = wts + bb * NN;
    float* O = (var ? g_O2 : g_O1);

    const int tid  = threadIdx.x;
    const int wq   = tid >> 5;
    const int lane = tid & 31;
    const int lr   = lane & 7;
    const int g    = lane >> 3;

    // per-lane ldmatrix row/col offsets (bytes)
    const uint32_t qoff = (uint32_t)((wq * 16 + lr + (g & 1) * 8) * ASTRB + (g >> 1) * 16);
    const uint32_t koff = (uint32_t)((lr + (g >> 1) * 8) * ASTRB + (g & 1) * 16);
    const uint32_t voff = (uint32_t)((lr + (g & 1) * 8) * ASTRB + (g >> 1) * 16);

    // load Q tile (128 rows x 64 cols), fused q + q{1,2}, split hi/lo
    // 1024 items x 8 floats: row = s>>3, c8 = (s&7)*8
#pragma unroll
    for (int p = 0; p < 4; p++) {
        const int s   = tid + p * 256;       // 0..1023
        const int row = s >> 3;              // 0..127
        const int c8  = (s & 7) * 8;         // 0..56
        float4 a0 = *(const float4*)(Q  + (size_t)row * DK + c8);
        float4 a1 = *(const float4*)(Q  + (size_t)row * DK + c8 + 4);
        float4 b0 = *(const float4*)(Qx + (size_t)row * DK + c8);
        float4 b1 = *(const float4*)(Qx + (size_t)row * DK + c8 + 4);
        a0.x += b0.x; a0.y += b0.y; a0.z += b0.z; a0.w += b0.w;
        a1.x += b1.x; a1.y += b1.y; a1.z += b1.z; a1.w += b1.w;
        uint4 hi, lo; split8(a0, a1, hi, lo);
        const uint32_t soff = (uint32_t)(row * ASTRB + c8 * 2);
        *(uint4*)(smn + AQH + soff) = hi;
        *(uint4*)(smn + AQL + soff) = lo;
    }

    float o[8][4];
#pragma unroll
    for (int j = 0; j < 8; j++)
#pragma unroll
        for (int e = 0; e < 4; e++) o[j][e] = 0.f;
    float m0 = -INFINITY, m1 = -INFINITY, l0 = 0.f, l1 = 0.f;

#pragma unroll 1
    for (int kt = 0; kt < NN / AKT; kt++) {
        __syncthreads();
        // load K, V tiles (64 rows x 64 cols each), split hi/lo
        // 512 items per matrix: row = s>>3, c8 = (s&7)*8
#pragma unroll
        for (int p = 0; p < 2; p++) {
            const int s   = tid + p * 256;   // 0..511
            const int row = s >> 3;          // 0..63
            const int c8  = (s & 7) * 8;     // 0..56
            const uint32_t soff = (uint32_t)(row * ASTRB + c8 * 2);
            {
                const float* kp = K + (size_t)(kt * AKT + row) * DK + c8;
                uint4 hi, lo; split8(*(const float4*)kp, *(const float4*)(kp + 4), hi, lo);
                *(uint4*)(smn + AKH + soff) = hi;
                *(uint4*)(smn + AKL + soff) = lo;
            }
            {
                const float* vp = V + (size_t)(kt * AKT + row) * DK + c8;
                uint4 hi, lo; split8(*(const float4*)vp, *(const float4*)(vp + 4), hi, lo);
                *(uint4*)(smn + AVH + soff) = hi;
                *(uint4*)(smn + AVL + soff) = lo;
            }
        }
        if (tid < 64) {
            const int key = kt * AKT + tid;
            float mul, add;
            if (msk[key]) { mul = 0.f; add = -1e38f; }
            else          { mul = 0.125f * w[key]; add = 0.f; }
            *(float2*)(smn + ACF + tid * 8) = make_float2(mul, add);
        }
        __syncthreads();

        // ---- S = (q+qx) K^T, 3-term split
        float s[8][4];
#pragma unroll
        for (int j = 0; j < 8; j++)
#pragma unroll
            for (int e = 0; e < 4; e++) s[j][e] = 0.f;

#pragma unroll
        for (int t = 0; t < 4; t++) {
            unsigned aqh[4], aql[4];
            ldm4(aqh, sb + AQH + qoff + 32 * t);
            ldm4(aql, sb + AQL + qoff + 32 * t);
#pragma unroll
            for (int u = 0; u < 4; u++) {
                unsigned bkh[4], bkl[4];
                const uint32_t ka = sb + koff + (uint32_t)(u * 16 * ASTRB + 32 * t);
                ldm4(bkh, ka + AKH);
                ldm4(bkl, ka + AKL);
                mma16816(s[2*u],   aqh, bkh[0], bkh[1]);
                mma16816(s[2*u],   aqh, bkl[0], bkl[1]);
                mma16816(s[2*u],   aql, bkh[0], bkh[1]);
                mma16816(s[2*u+1], aqh, bkh[2], bkh[3]);
                mma16816(s[2*u+1], aqh, bkl[2], bkl[3]);
                mma16816(s[2*u+1], aql, bkh[2], bkh[3]);
            }
        }

        // ---- fused scale*weight + mask:  s' = s*mul + add
#pragma unroll
        for (int j = 0; j < 8; j++) {
            float4 cc = *(const float4*)(smn + ACF + (8 * j + (lane & 3) * 2) * 8);
            s[j][0] = fmaf(s[j][0], cc.x, cc.y);
            s[j][1] = fmaf(s[j][1], cc.z, cc.w);
            s[j][2] = fmaf(s[j][2], cc.x, cc.y);
            s[j][3] = fmaf(s[j][3], cc.z, cc.w);
        }

        // ---- online softmax (rows r = wq*16 + lane/4 and r+8)
        float mt0 = -INFINITY, mt1 = -INFINITY;
#pragma unroll
        for (int j = 0; j < 8; j++) {
            mt0 = fmaxf(mt0, fmaxf(s[j][0], s[j][1]));
            mt1 = fmaxf(mt1, fmaxf(s[j][2], s[j][3]));
        }
        mt0 = fmaxf(mt0, __shfl_xor_sync(0xffffffffu, mt0, 1));
        mt0 = fmaxf(mt0, __shfl_xor_sync(0xffffffffu, mt0, 2));
        mt1 = fmaxf(mt1, __shfl_xor_sync(0xffffffffu, mt1, 1));
        mt1 = fmaxf(mt1, __shfl_xor_sync(0xffffffffu, mt1, 2));

        const float mn0 = fmaxf(m0, mt0);
        const float mn1 = fmaxf(m1, mt1);
        const float mx0 = fmaxf(mn0, -1e30f);
        const float mx1 = fmaxf(mn1, -1e30f);
        const float f0 = __expf(m0 - mx0);
        const float f1 = __expf(m1 - mx1);
        m0 = mn0; m1 = mn1;

        float rs0 = 0.f, rs1 = 0.f;
#pragma unroll
        for (int j = 0; j < 8; j++) {
            s[j][0] = __expf(s[j][0] - mx0);
            s[j][1] = __expf(s[j][1] - mx0);
            s[j][2] = __expf(s[j][2] - mx1);
            s[j][3] = __expf(s[j][3] - mx1);
            rs0 += s[j][0] + s[j][1];
            rs1 += s[j][2] + s[j][3];
        }
        rs0 += __shfl_xor_sync(0xffffffffu, rs0, 1);
        rs0 += __shfl_xor_sync(0xffffffffu, rs0, 2);
        rs1 += __shfl_xor_sync(0xffffffffu, rs1, 1);
        rs1 += __shfl_xor_sync(0xffffffffu, rs1, 2);
        l0 = l0 * f0 + rs0;
        l1 = l1 * f1 + rs1;

#pragma unroll
        for (int j = 0; j < 8; j++) {
            o[j][0] *= f0; o[j][1] *= f0;
            o[j][2] *= f1; o[j][3] *= f1;
        }

        // ---- pack P into bf16 hi/lo A-fragments (registers only)
        unsigned pha[16], pla[16];
#pragma unroll
        for (int j = 0; j < 8; j++) {
            __nv_bfloat162 h01 = __floats2bfloat162_rn(s[j][0], s[j][1]);
            __nv_bfloat162 h23 = __floats2bfloat162_rn(s[j][2], s[j][3]);
            pha[2*j]   = *reinterpret_cast<unsigned*>(&h01);
            pha[2*j+1] = *reinterpret_cast<unsigned*>(&h23);
            float r0 = s[j][0] - __bfloat162float(h01.x);
            float r1 = s[j][1] - __bfloat162float(h01.y);
            float r2 = s[j][2] - __bfloat162float(h23.x);
            float r3 = s[j][3] - __bfloat162float(h23.y);
            __nv_bfloat162 l01 = __floats2bfloat162_rn(r0, r1);
            __nv_bfloat162 l23 = __floats2bfloat162_rn(r2, r3);
            pla[2*j]   = *reinterpret_cast<unsigned*>(&l01);
            pla[2*j+1] = *reinterpret_cast<unsigned*>(&l23);
        }

        // ---- O += P V, 3-term split
#pragma unroll
        for (int t = 0; t < 4; t++) {
            const unsigned* aph = &pha[4 * t];
            const unsigned* apl = &pla[4 * t];
#pragma unroll
            for (int u = 0; u < 4; u++) {
                unsigned bvh[4], bvl[4];
                const uint32_t va = sb + voff + (uint32_t)(t * 16 * ASTRB + 32 * u);
                ldm4t(bvh, va + AVH);
                ldm4t(bvl, va + AVL);
                mma16816(o[2*u],   aph, bvh[0], bvh[1]);
                mma16816(o[2*u],   aph, bvl[0], bvl[1]);
                mma16816(o[2*u],   apl, bvh[0], bvh[1]);
                mma16816(o[2*u+1], aph, bvh[2], bvh[3]);
                mma16816(o[2*u+1], aph, bvl[2], bvl[3]);
                mma16816(o[2*u+1], apl, bvh[2], bvh[3]);
            }
        }
    }

    // ---- epilogue: normalize, write [B, N, H*64]
    const float inv0 = 1.f / l0;
    const float inv1 = 1.f / l1;
    const int r = qt * AQROWS + wq * 16 + (lane >> 2);
#pragma unroll
    for (int j = 0; j < 8; j++) {
        const int col = h * DK + 8 * j + (lane & 3) * 2;
        float* d0 = O + ((size_t)bb * NN + r)     * DMODEL + col;
        float* d1 = O + ((size_t)bb * NN + r + 8) * DMODEL + col;
        *(float2*)d0 = make_float2(o[j][0] * inv0, o[j][1] * inv0);
        *(float2*)d1 = make_float2(o[j][2] * inv1, o[j][3] * inv1);
    }
}

// ===========================================================================
extern "C" void kernel_launch(void* const* d_in, const int* in_sizes, int n_in,
                              void* d_out, int out_size)
{
    const float* regions   = (const float*)d_in[0];
    const float* grids     = (const float*)d_in[1];
    const float* interests = (const float*)d_in[2];
    const int*   maskR     = (const int*)d_in[3];
    const int*   maskG     = (const int*)d_in[4];
    const float* wts       = (const float*)d_in[5];
    const float* Wq   = (const float*)d_in[6];
    const float* bq   = (const float*)d_in[7];
    const float* Wk   = (const float*)d_in[8];
    const float* bk   = (const float*)d_in[9];
    const float* Wv   = (const float*)d_in[10];
    const float* bv   = (const float*)d_in[11];
    const float* Wq12 = (const float*)d_in[12];
    const float* bq12 = (const float*)d_in[13];
    const float* Wo1  = (const float*)d_in[14];
    const float* bo1  = (const float*)d_in[15];
    const float* Wo2  = (const float*)d_in[16];
    const float* bo2  = (const float*)d_in[17];
    float* out = (float*)d_out;

    float *q, *q1, *q2, *K1, *K2, *V1, *V2, *O1, *O2;
    cudaGetSymbolAddress((void**)&q,  g_q);
    cudaGetSymbolAddress((void**)&q1, g_q1);
    cudaGetSymbolAddress((void**)&q2, g_q2);
    cudaGetSymbolAddress((void**)&K1, g_K1);
    cudaGetSymbolAddress((void**)&K2, g_K2);
    cudaGetSymbolAddress((void**)&V1, g_V1);
    cudaGetSymbolAddress((void**)&V2, g_V2);
    cudaGetSymbolAddress((void**)&O1, g_O1);
    cudaGetSymbolAddress((void**)&O2, g_O2);

    cudaFuncSetAttribute(attn_mma, cudaFuncAttributeMaxDynamicSharedMemorySize, ASMEMB);

    // All 7 projections — one HMMA launch (z selects GEMM)
    GB pj;
    pj.X[0] = interests; pj.W[0] = Wq;   pj.Bi[0] = bq;   pj.D[0] = q;
    pj.X[1] = regions;   pj.W[1] = Wq12; pj.Bi[1] = bq12; pj.D[1] = q1;
    pj.X[2] = grids;     pj.W[2] = Wq12; pj.Bi[2] = bq12; pj.D[2] = q2;
    pj.X[3] = regions;   pj.W[3] = Wk;   pj.Bi[3] = bk;   pj.D[3] = K1;
    pj.X[4] = grids;     pj.W[4] = Wk;   pj.Bi[4] = bk;   pj.D[4] = K2;
    pj.X[5] = regions;   pj.W[5] = Wv;   pj.Bi[5] = bv;   pj.D[5] = V1;
    pj.X[6] = grids;     pj.W[6] = Wv;   pj.Bi[6] = bv;   pj.D[6] = V2;
    gemm_mma<MODE_HEADS><<<dim3(DMODEL / 128, MTOT / 128, 7), 256>>>(pj);

    // Both attentions — HMMA flash kernel
    attn_mma<<<dim3(NN / AQROWS, BB * HH, 2), 256, ASMEMB>>>(maskR, maskG, wts);

    // Output projections — one HMMA launch
    GB po;
    po.X[0] = O1; po.W[0] = Wo1; po.Bi[0] = bo1; po.D[0] = out;
    po.X[1] = O2; po.W[1] = Wo2; po.Bi[1] = bo2; po.D[1] = out + OUTHALF;
    for (int i = 2; i < 7; i++) { po.X[i] = O1; po.W[i] = Wo1; po.Bi[i] = bo1; po.D[i] = out; }
    gemm_mma<MODE_ROW><<<dim3(DMODEL / 128, MTOT / 128, 2), 256>>>(po);
}

// round 8
// speedup vs baseline: 4.6647x; 1.2410x over previous
#include <cuda_runtime.h>
#include <cuda_bf16.h>
#include <math.h>
#include <stdint.h>

#define BB 2
#define NN 2048
#define DMODEL 512
#define HH 8
#define DK 64
#define MTOT (BB*NN)                 // 4096
#define HEADELEMS (BB*HH*NN*DK)      // 2097152
#define OUTHALF (MTOT*DMODEL)        // 2097152
#define INSEG (MTOT*DMODEL)          // 2097152 (one input matrix)
#define WSEG (DMODEL*DMODEL)         // 262144  (one weight matrix)

// ---------------- scratch (__device__ globals; allocation-free rule) --------
__device__ float g_q [HEADELEMS];
__device__ float g_q1[HEADELEMS];
__device__ float g_q2[HEADELEMS];
__device__ __nv_bfloat16 g_ih[3*INSEG];     // inputs hi  (interests, regions, grids)
__device__ __nv_bfloat16 g_il[3*INSEG];     // inputs lo
__device__ __nv_bfloat16 g_wh[6*WSEG];      // weights hi (Wq, Wq12, Wk, Wv, Wo1, Wo2)
__device__ __nv_bfloat16 g_wl[6*WSEG];      // weights lo
__device__ __nv_bfloat16 g_kvh[4*HEADELEMS];// K1,K2,V1,V2 hi
__device__ __nv_bfloat16 g_kvl[4*HEADELEMS];// K1,K2,V1,V2 lo
__device__ __nv_bfloat16 g_oh[2*OUTHALF];   // O1,O2 hi
__device__ __nv_bfloat16 g_ol[2*OUTHALF];   // O1,O2 lo

__device__ __forceinline__ uint32_t smem_u32(const void* p) {
    uint32_t a;
    asm("{ .reg .u64 t; cvta.to.shared.u64 t, %1; cvt.u32.u64 %0, t; }"
        : "=r"(a) : "l"(p));
    return a;
}

// ---- family-common PTX primitives (sm_80+: valid on .target sm_103) --------
__device__ __forceinline__ void ldm4(unsigned r[4], uint32_t addr) {
    asm volatile("ldmatrix.sync.aligned.m8n8.x4.shared.b16 {%0,%1,%2,%3}, [%4];"
        : "=r"(r[0]), "=r"(r[1]), "=r"(r[2]), "=r"(r[3]) : "r"(addr));
}
__device__ __forceinline__ void ldm4t(unsigned r[4], uint32_t addr) {
    asm volatile("ldmatrix.sync.aligned.m8n8.x4.trans.shared.b16 {%0,%1,%2,%3}, [%4];"
        : "=r"(r[0]), "=r"(r[1]), "=r"(r[2]), "=r"(r[3]) : "r"(addr));
}
__device__ __forceinline__ void mma16816(float c[4], const unsigned a[4],
                                         const unsigned b0, const unsigned b1) {
    asm volatile(
        "mma.sync.aligned.m16n8k16.row.col.f32.bf16.bf16.f32 "
        "{%0,%1,%2,%3}, {%4,%5,%6,%7}, {%8,%9}, {%0,%1,%2,%3};"
        : "+f"(c[0]), "+f"(c[1]), "+f"(c[2]), "+f"(c[3])
        : "r"(a[0]), "r"(a[1]), "r"(a[2]), "r"(a[3]), "r"(b0), "r"(b1));
}
#define CP_ASYNC16(dst, src) \
    asm volatile("cp.async.cg.shared.global [%0], [%1], 16;" \
        :: "r"(dst), "l"(src) : "memory")
#define CP_COMMIT() asm volatile("cp.async.commit_group;" ::: "memory")
#define CP_WAIT0()  asm volatile("cp.async.wait_group 0;" ::: "memory")

// split 8 fp32 -> 8 bf16 hi + 8 bf16 lo (residual)
__device__ __forceinline__ void split8(float4 a, float4 b, uint4& hi, uint4& lo) {
    float x[8] = {a.x, a.y, a.z, a.w, b.x, b.y, b.z, b.w};
    unsigned hw[4], lw[4];
#pragma unroll
    for (int i = 0; i < 4; i++) {
        __nv_bfloat16 h0 = __float2bfloat16_rn(x[2*i]);
        __nv_bfloat16 h1 = __float2bfloat16_rn(x[2*i+1]);
        float l0 = x[2*i]   - __bfloat162float(h0);
        float l1 = x[2*i+1] - __bfloat162float(h1);
        __nv_bfloat162 hp; hp.x = h0; hp.y = h1;
        __nv_bfloat162 lp; lp.x = __float2bfloat16_rn(l0); lp.y = __float2bfloat16_rn(l1);
        hw[i] = *reinterpret_cast<unsigned*>(&hp);
        lw[i] = *reinterpret_cast<unsigned*>(&lp);
    }
    hi = make_uint4(hw[0], hw[1], hw[2], hw[3]);
    lo = make_uint4(lw[0], lw[1], lw[2], lw[3]);
}
// split 2 fp32 -> packed bf16x2 hi + lo
__device__ __forceinline__ void split2(float v0, float v1, unsigned& hi, unsigned& lo) {
    __nv_bfloat162 h = __floats2bfloat162_rn(v0, v1);
    float r0 = v0 - __bfloat162float(h.x);
    float r1 = v1 - __bfloat162float(h.y);
    __nv_bfloat162 l = __floats2bfloat162_rn(r0, r1);
    hi = *reinterpret_cast<unsigned*>(&h);
    lo = *reinterpret_cast<unsigned*>(&l);
}

// ===========================================================================
// Prep: fp32 -> bf16 hi/lo for 3 inputs + 6 weights
// ===========================================================================
struct Prep {
    const float* src[9];
    __nv_bfloat16* dh[9];
    __nv_bfloat16* dl[9];
    int n4[9];
};

__global__ __launch_bounds__(256)
void prep_k(Prep pp)
{
    const int z  = blockIdx.y;
    const int i4 = blockIdx.x * 256 + threadIdx.x;
    if (i4 >= pp.n4[z]) return;
    float4 v = ((const float4*)pp.src[z])[i4];
    unsigned h0, l0, h1, l1;
    split2(v.x, v.y, h0, l0);
    split2(v.z, v.w, h1, l1);
    ((uint2*)pp.dh[z])[i4] = make_uint2(h0, h1);
    ((uint2*)pp.dl[z])[i4] = make_uint2(l0, l1);
}

// ===========================================================================
// cp.async double-buffered HMMA GEMM over preconverted bf16 hi/lo:
//   C[m,o] = sum_k X[m,k]*W[o,k] + bias[o]   (3-term split accumulation)
// Block tile 128x128, 8 warps (2Mx4N), warp tile 64x32, K-chunk 32, 2 stages.
// mode: 0 = HEADS fp32 [b,h,n,d], 1 = KV bf16 hi/lo [b,h,n,d], 2 = ROW fp32.
// ===========================================================================
#define GRSTR 80                       // bytes/row: 32 bf16 + 8 pad (16B-mult)
#define GMAT  (128 * GRSTR)            // 10240 per matrix
#define GSTG  (4 * GMAT)               // 40960 per stage
#define GSMEM (2 * GSTG)               // 81920

struct GBF {
    const __nv_bfloat16 *Xh, *Xl, *Wh, *Wl;
    const float* Bi;
    float* D;
    __nv_bfloat16 *Dh, *Dl;
    int mode;
};
struct GBFpack { GBF g[7]; };

__global__ __launch_bounds__(256)
void gemm_bf(GBFpack gp)
{
    extern __shared__ __align__(16) char smc[];
    const uint32_t sb = smem_u32(smc);

    const GBF gb = gp.g[blockIdx.z];
    const int m0 = blockIdx.y * 128;
    const int n0 = blockIdx.x * 128;

    const int tid  = threadIdx.x;
    const int wid  = tid >> 5;
    const int lane = tid & 31;
    const int warpM = wid >> 2;
    const int warpN = wid & 3;

    const int arow  = (lane & 7) + ((lane >> 3) & 1) * 8;
    const int akoff = ((lane >> 4) & 1) * 16;
    const int brow  = (lane & 7) + ((lane >> 4) & 1) * 8;
    const int bkoff = ((lane >> 3) & 1) * 16;

    float c[4][4][4];
#pragma unroll
    for (int im = 0; im < 4; im++)
#pragma unroll
        for (int jn = 0; jn < 4; jn++)
#pragma unroll
            for (int e = 0; e < 4; e++) c[im][jn][e] = 0.f;

    // issue one stage of cp.async copies (A hi/lo 128x32, B hi/lo 128x32)
    auto issue = [&](int s, int kc) {
#pragma unroll
        for (int p = 0; p < 8; p++) {
            const int i = tid + p * 256;        // 0..2047
            const int t = i >> 9;               // 0 Xh,1 Xl,2 Wh,3 Wl
            const int r = (i >> 2) & 127;
            const int cc = i & 3;
            const __nv_bfloat16* src;
            if      (t == 0) src = gb.Xh + (size_t)(m0 + r) * DMODEL + kc * 32 + cc * 8;
            else if (t == 1) src = gb.Xl + (size_t)(m0 + r) * DMODEL + kc * 32 + cc * 8;
            else if (t == 2) src = gb.Wh + (size_t)(n0 + r) * DMODEL + kc * 32 + cc * 8;
            else             src = gb.Wl + (size_t)(n0 + r) * DMODEL + kc * 32 + cc * 8;
            CP_ASYNC16(sb + s * GSTG + t * GMAT + r * GRSTR + cc * 16, src);
        }
    };

    issue(0, 0);
    CP_COMMIT();

#pragma unroll 1
    for (int kc = 0; kc < 16; kc++) {
        const int b = kc & 1;
        CP_WAIT0();
        __syncthreads();
        if (kc < 15) { issue(b ^ 1, kc + 1); CP_COMMIT(); }

        const uint32_t sAh = sb + b * GSTG;
        const uint32_t sAl = sAh + GMAT;
        const uint32_t sBh = sAh + 2 * GMAT;
        const uint32_t sBl = sAh + 3 * GMAT;

#pragma unroll
        for (int ks = 0; ks < 2; ks++) {
            unsigned bh[2][4], bl[2][4];
#pragma unroll
            for (int jp = 0; jp < 2; jp++) {
                const uint32_t bo = (uint32_t)((warpN * 32 + jp * 16 + brow) * GRSTR
                                               + ks * 32 + bkoff);
                ldm4(bh[jp], sBh + bo);
                ldm4(bl[jp], sBl + bo);
            }
#pragma unroll
            for (int im = 0; im < 4; im++) {
                const uint32_t ao = (uint32_t)((warpM * 64 + im * 16 + arow) * GRSTR
                                               + ks * 32 + akoff);
                unsigned ah[4], al[4];
                ldm4(ah, sAh + ao);
                ldm4(al, sAl + ao);
#pragma unroll
                for (int jn = 0; jn < 4; jn++) {
                    const int jp = jn >> 1, jo = (jn & 1) * 2;
                    mma16816(c[im][jn], ah, bh[jp][jo], bh[jp][jo + 1]);
                    mma16816(c[im][jn], ah, bl[jp][jo], bl[jp][jo + 1]);
                    mma16816(c[im][jn], al, bh[jp][jo], bh[jp][jo + 1]);
                }
            }
        }
    }

    // epilogue
    const int rbase = m0 + warpM * 64 + (lane >> 2);
    const int cbase = n0 + warpN * 32 + (lane & 3) * 2;
#pragma unroll
    for (int im = 0; im < 4; im++) {
#pragma unroll
        for (int jn = 0; jn < 4; jn++) {
            const int col = cbase + jn * 8;
            const float b0 = gb.Bi[col], b1 = gb.Bi[col + 1];
#pragma unroll
            for (int half = 0; half < 2; half++) {
                const int m  = rbase + im * 16 + half * 8;
                const float v0 = c[im][jn][half * 2]     + b0;
                const float v1 = c[im][jn][half * 2 + 1] + b1;
                if (gb.mode == 2) {
                    *(float2*)(gb.D + (size_t)m * DMODEL + col) = make_float2(v0, v1);
                } else {
                    const int bb = m >> 11;
                    const int n  = m & 2047;
                    const int h  = col >> 6, d = col & 63;
                    const size_t idx = (((size_t)(bb * HH + h)) * NN + n) * DK + d;
                    if (gb.mode == 0) {
                        *(float2*)(gb.D + idx) = make_float2(v0, v1);
                    } else {
                        unsigned hi, lo; split2(v0, v1, hi, lo);
                        *(unsigned*)(gb.Dh + idx) = hi;
                        *(unsigned*)(gb.Dl + idx) = lo;
                    }
                }
            }
        }
    }
}

// ===========================================================================
// cp.async double-buffered HMMA FlashAttention.
// Block = 128 Q rows of one (b,h,var), 8 warps x 16 rows, key tiles of 64.
// K/V arrive preconverted bf16 hi/lo; Q fused-add + split once per block.
// P stays in registers. Smem rows 144B (16B-mult, conflict-free ldmatrix).
// ===========================================================================
#define AQROWS 128
#define ASTRB 144
#define AQH 0
#define AQL (128*ASTRB)              // 18432
#define KVB (2*128*ASTRB)            // 36864
#define KMAT (64*ASTRB)              // 9216
#define KVS (4*KMAT)                 // 36864 per stage
#define ACF (KVB + 2*KVS)            // 110592
#define ASMEMB (ACF + 2*512)         // 111616

__global__ __launch_bounds__(256)
void attn_mma(const int* __restrict__ mR, const int* __restrict__ mG,
              const float* __restrict__ wts)
{
    extern __shared__ __align__(16) char smn[];
    const uint32_t sb = smem_u32(smn);

    const int var = blockIdx.z;
    const int bh  = blockIdx.y;
    const int bb  = bh >> 3;
    const int h   = bh & 7;
    const int qt  = blockIdx.x;

    const float* Q  = g_q + (size_t)bh * NN * DK + (size_t)qt * AQROWS * DK;
    const float* Qx = (var ? g_q1 : g_q2) + (size_t)bh * NN * DK + (size_t)qt * AQROWS * DK;
    const int*   msk = (var ? mG : mR) + bb * NN;
    const float* w   = wts + bb * NN;

    const int tid  = threadIdx.x;
    const int wq   = tid >> 5;
    const int lane = tid & 31;
    const int lr   = lane & 7;
    const int g    = lane >> 3;

    const uint32_t qoff = (uint32_t)((wq * 16 + lr + (g & 1) * 8) * ASTRB + (g >> 1) * 16);
    const uint32_t koff = (uint32_t)((lr + (g >> 1) * 8) * ASTRB + (g & 1) * 16);
    const uint32_t voff = (uint32_t)((lr + (g & 1) * 8) * ASTRB + (g >> 1) * 16);

    // KV stage copy: Kh,Kl,Vh,Vl each 64 rows x 128B
    auto issueKV = [&](int s, int kt) {
#pragma unroll
        for (int p = 0; p < 8; p++) {
            const int i = tid + p * 256;        // 0..2047
            const int t = i >> 9;               // 0 Kh,1 Kl,2 Vh,3 Vl
            const int r = (i >> 3) & 63;
            const int cc = i & 7;
            const int seg = (t >> 1) ? (2 + var) : var;
            const __nv_bfloat16* base = (t & 1) ? g_kvl : g_kvh;
            const __nv_bfloat16* src = base + (size_t)seg * HEADELEMS
                + (size_t)bh * NN * DK + (size_t)(kt * 64 + r) * DK + cc * 8;
            CP_ASYNC16(sb + KVB + s * KVS + t * KMAT + r * ASTRB + cc * 16, src);
        }
    };

    // Q load (fp32, fused add), split hi/lo — once per block
#pragma unroll
    for (int p = 0; p < 4; p++) {
        const int s   = tid + p * 256;
        const int row = s >> 3;
        const int c8  = (s & 7) * 8;
        float4 a0 = *(const float4*)(Q  + (size_t)row * DK + c8);
        float4 a1 = *(const float4*)(Q  + (size_t)row * DK + c8 + 4);
        float4 b0 = *(const float4*)(Qx + (size_t)row * DK + c8);
        float4 b1 = *(const float4*)(Qx + (size_t)row * DK + c8 + 4);
        a0.x += b0.x; a0.y += b0.y; a0.z += b0.z; a0.w += b0.w;
        a1.x += b1.x; a1.y += b1.y; a1.z += b1.z; a1.w += b1.w;
        uint4 hi, lo; split8(a0, a1, hi, lo);
        const uint32_t soff = (uint32_t)(row * ASTRB + c8 * 2);
        *(uint4*)(smn + AQH + soff) = hi;
        *(uint4*)(smn + AQL + soff) = lo;
    }

    // prologue: stage 0 copies + cf[0]
    issueKV(0, 0);
    CP_COMMIT();
    if (tid < 64) {
        float mul, add;
        if (msk[tid]) { mul = 0.f; add = -1e38f; }
        else          { mul = 0.125f * w[tid]; add = 0.f; }
        *(float2*)(smn + ACF + tid * 8) = make_float2(mul, add);
    }

    float o[8][4];
#pragma unroll
    for (int j = 0; j < 8; j++)
#pragma unroll
        for (int e = 0; e < 4; e++) o[j][e] = 0.f;
    float m0 = -INFINITY, m1 = -INFINITY, l0 = 0.f, l1 = 0.f;

#pragma unroll 1
    for (int kt = 0; kt < NN / 64; kt++) {
        const int b = kt & 1;
        CP_WAIT0();
        __syncthreads();
        if (kt < NN / 64 - 1) {
            issueKV(b ^ 1, kt + 1);
            CP_COMMIT();
            if (tid < 64) {
                const int key = (kt + 1) * 64 + tid;
                float mul, add;
                if (msk[key]) { mul = 0.f; add = -1e38f; }
                else          { mul = 0.125f * w[key]; add = 0.f; }
                *(float2*)(smn + ACF + (b ^ 1) * 512 + tid * 8) = make_float2(mul, add);
            }
        }

        const uint32_t sKh = sb + KVB + b * KVS;
        const uint32_t sKl = sKh + KMAT;
        const uint32_t sVh = sKh + 2 * KMAT;
        const uint32_t sVl = sKh + 3 * KMAT;

        // ---- S = (q+qx) K^T, 3-term split
        float s[8][4];
#pragma unroll
        for (int j = 0; j < 8; j++)
#pragma unroll
            for (int e = 0; e < 4; e++) s[j][e] = 0.f;

#pragma unroll
        for (int t = 0; t < 4; t++) {
            unsigned aqh[4], aql[4];
            ldm4(aqh, sb + AQH + qoff + 32 * t);
            ldm4(aql, sb + AQL + qoff + 32 * t);
#pragma unroll
            for (int u = 0; u < 4; u++) {
                unsigned bkh[4], bkl[4];
                const uint32_t ka = koff + (uint32_t)(u * 16 * ASTRB + 32 * t);
                ldm4(bkh, sKh + ka);
                ldm4(bkl, sKl + ka);
                mma16816(s[2*u],   aqh, bkh[0], bkh[1]);
                mma16816(s[2*u],   aqh, bkl[0], bkl[1]);
                mma16816(s[2*u],   aql, bkh[0], bkh[1]);
                mma16816(s[2*u+1], aqh, bkh[2], bkh[3]);
                mma16816(s[2*u+1], aqh, bkl[2], bkl[3]);
                mma16816(s[2*u+1], aql, bkh[2], bkh[3]);
            }
        }

        // ---- fused scale*weight + mask
#pragma unroll
        for (int j = 0; j < 8; j++) {
            float4 cc = *(const float4*)(smn + ACF + b * 512 + (8 * j + (lane & 3) * 2) * 8);
            s[j][0] = fmaf(s[j][0], cc.x, cc.y);
            s[j][1] = fmaf(s[j][1], cc.z, cc.w);
            s[j][2] = fmaf(s[j][2], cc.x, cc.y);
            s[j][3] = fmaf(s[j][3], cc.z, cc.w);
        }

        // ---- online softmax
        float mt0 = -INFINITY, mt1 = -INFINITY;
#pragma unroll
        for (int j = 0; j < 8; j++) {
            mt0 = fmaxf(mt0, fmaxf(s[j][0], s[j][1]));
            mt1 = fmaxf(mt1, fmaxf(s[j][2], s[j][3]));
        }
        mt0 = fmaxf(mt0, __shfl_xor_sync(0xffffffffu, mt0, 1));
        mt0 = fmaxf(mt0, __shfl_xor_sync(0xffffffffu, mt0, 2));
        mt1 = fmaxf(mt1, __shfl_xor_sync(0xffffffffu, mt1, 1));
        mt1 = fmaxf(mt1, __shfl_xor_sync(0xffffffffu, mt1, 2));

        const float mn0 = fmaxf(m0, mt0);
        const float mn1 = fmaxf(m1, mt1);
        const float mx0 = fmaxf(mn0, -1e30f);
        const float mx1 = fmaxf(mn1, -1e30f);
        const float f0 = __expf(m0 - mx0);
        const float f1 = __expf(m1 - mx1);
        m0 = mn0; m1 = mn1;

        float rs0 = 0.f, rs1 = 0.f;
#pragma unroll
        for (int j = 0; j < 8; j++) {
            s[j][0] = __expf(s[j][0] - mx0);
            s[j][1] = __expf(s[j][1] - mx0);
            s[j][2] = __expf(s[j][2] - mx1);
            s[j][3] = __expf(s[j][3] - mx1);
            rs0 += s[j][0] + s[j][1];
            rs1 += s[j][2] + s[j][3];
        }
        rs0 += __shfl_xor_sync(0xffffffffu, rs0, 1);
        rs0 += __shfl_xor_sync(0xffffffffu, rs0, 2);
        rs1 += __shfl_xor_sync(0xffffffffu, rs1, 1);
        rs1 += __shfl_xor_sync(0xffffffffu, rs1, 2);
        l0 = l0 * f0 + rs0;
        l1 = l1 * f1 + rs1;

#pragma unroll
        for (int j = 0; j < 8; j++) {
            o[j][0] *= f0; o[j][1] *= f0;
            o[j][2] *= f1; o[j][3] *= f1;
        }

        // ---- pack P into bf16 hi/lo A-fragments (registers only)
        unsigned pha[16], pla[16];
#pragma unroll
        for (int j = 0; j < 8; j++) {
            split2(s[j][0], s[j][1], pha[2*j],   pla[2*j]);
            split2(s[j][2], s[j][3], pha[2*j+1], pla[2*j+1]);
        }

        // ---- O += P V, 3-term split
#pragma unroll
        for (int t = 0; t < 4; t++) {
            const unsigned* aph = &pha[4 * t];
            const unsigned* apl = &pla[4 * t];
#pragma unroll
            for (int u = 0; u < 4; u++) {
                unsigned bvh[4], bvl[4];
                const uint32_t va = voff + (uint32_t)(t * 16 * ASTRB + 32 * u);
                ldm4t(bvh, sVh + va);
                ldm4t(bvl, sVl + va);
                mma16816(o[2*u],   aph, bvh[0], bvh[1]);
                mma16816(o[2*u],   aph, bvl[0], bvl[1]);
                mma16816(o[2*u],   apl, bvh[0], bvh[1]);
                mma16816(o[2*u+1], aph, bvh[2], bvh[3]);
                mma16816(o[2*u+1], aph, bvl[2], bvl[3]);
                mma16816(o[2*u+1], apl, bvh[2], bvh[3]);
            }
        }
    }

    // ---- epilogue: normalize, split, store bf16 hi/lo to g_oh/g_ol
    const float inv0 = 1.f / l0;
    const float inv1 = 1.f / l1;
    const int r = qt * AQROWS + wq * 16 + (lane >> 2);
    __nv_bfloat16* Oh = g_oh + (size_t)var * OUTHALF;
    __nv_bfloat16* Ol = g_ol + (size_t)var * OUTHALF;
#pragma unroll
    for (int j = 0; j < 8; j++) {
        const int col = h * DK + 8 * j + (lane & 3) * 2;
        const size_t i0 = ((size_t)bb * NN + r)     * DMODEL + col;
        const size_t i1 = ((size_t)bb * NN + r + 8) * DMODEL + col;
        unsigned hi, lo;
        split2(o[j][0] * inv0, o[j][1] * inv0, hi, lo);
        *(unsigned*)(Oh + i0) = hi;
        *(unsigned*)(Ol + i0) = lo;
        split2(o[j][2] * inv1, o[j][3] * inv1, hi, lo);
        *(unsigned*)(Oh + i1) = hi;
        *(unsigned*)(Ol + i1) = lo;
    }
}

// ===========================================================================
extern "C" void kernel_launch(void* const* d_in, const int* in_sizes, int n_in,
                              void* d_out, int out_size)
{
    const float* regions   = (const float*)d_in[0];
    const float* grids     = (const float*)d_in[1];
    const float* interests = (const float*)d_in[2];
    const int*   maskR     = (const int*)d_in[3];
    const int*   maskG     = (const int*)d_in[4];
    const float* wts       = (const float*)d_in[5];
    const float* Wq   = (const float*)d_in[6];
    const float* bq   = (const float*)d_in[7];
    const float* Wk   = (const float*)d_in[8];
    const float* bk   = (const float*)d_in[9];
    const float* Wv   = (const float*)d_in[10];
    const float* bv   = (const float*)d_in[11];
    const float* Wq12 = (const float*)d_in[12];
    const float* bq12 = (const float*)d_in[13];
    const float* Wo1  = (const float*)d_in[14];
    const float* bo1  = (const float*)d_in[15];
    const float* Wo2  = (const float*)d_in[16];
    const float* bo2  = (const float*)d_in[17];
    float* out = (float*)d_out;

    float *q, *q1, *q2;
    __nv_bfloat16 *ih, *il, *wh, *wl, *kvh, *kvl, *oh, *ol;
    cudaGetSymbolAddress((void**)&q,   g_q);
    cudaGetSymbolAddress((void**)&q1,  g_q1);
    cudaGetSymbolAddress((void**)&q2,  g_q2);
    cudaGetSymbolAddress((void**)&ih,  g_ih);
    cudaGetSymbolAddress((void**)&il,  g_il);
    cudaGetSymbolAddress((void**)&wh,  g_wh);
    cudaGetSymbolAddress((void**)&wl,  g_wl);
    cudaGetSymbolAddress((void**)&kvh, g_kvh);
    cudaGetSymbolAddress((void**)&kvl, g_kvl);
    cudaGetSymbolAddress((void**)&oh,  g_oh);
    cudaGetSymbolAddress((void**)&ol,  g_ol);

    cudaFuncSetAttribute(gemm_bf, cudaFuncAttributeMaxDynamicSharedMemorySize, GSMEM);
    cudaFuncSetAttribute(attn_mma, cudaFuncAttributeMaxDynamicSharedMemorySize, ASMEMB);

    // ---- prep: fp32 -> bf16 hi/lo (3 inputs + 6 weights)
    Prep pp;
    const float* srcs[9] = {interests, regions, grids, Wq, Wq12, Wk, Wv, Wo1, Wo2};
    for (int z = 0; z < 9; z++) {
        pp.src[z] = srcs[z];
        if (z < 3) {
            pp.dh[z] = ih + (size_t)z * INSEG;
            pp.dl[z] = il + (size_t)z * INSEG;
            pp.n4[z] = INSEG / 4;
        } else {
            pp.dh[z] = wh + (size_t)(z - 3) * WSEG;
            pp.dl[z] = wl + (size_t)(z - 3) * WSEG;
            pp.n4[z] = WSEG / 4;
        }
    }
    prep_k<<<dim3(INSEG / 4 / 256, 9), 256>>>(pp);

    const __nv_bfloat16 *Ih = ih, *Rh = ih + INSEG, *Gh = ih + 2 * (size_t)INSEG;
    const __nv_bfloat16 *Il = il, *Rl = il + INSEG, *Gl = il + 2 * (size_t)INSEG;
    const __nv_bfloat16 *Wqh = wh, *Wq12h = wh + WSEG, *Wkh = wh + 2*(size_t)WSEG,
                        *Wvh = wh + 3*(size_t)WSEG, *Wo1h = wh + 4*(size_t)WSEG,
                        *Wo2h = wh + 5*(size_t)WSEG;
    const __nv_bfloat16 *Wql = wl, *Wq12l = wl + WSEG, *Wkl = wl + 2*(size_t)WSEG,
                        *Wvl = wl + 3*(size_t)WSEG, *Wo1l = wl + 4*(size_t)WSEG,
                        *Wo2l = wl + 5*(size_t)WSEG;

    // ---- 7 projections, one launch
    GBFpack pj;
    auto set = [&](int z, const __nv_bfloat16* xh, const __nv_bfloat16* xl,
                   const __nv_bfloat16* wwh, const __nv_bfloat16* wwl,
                   const float* bi, float* D, __nv_bfloat16* Dh, __nv_bfloat16* Dl,
                   int mode) {
        pj.g[z].Xh = xh; pj.g[z].Xl = xl; pj.g[z].Wh = wwh; pj.g[z].Wl = wwl;
        pj.g[z].Bi = bi; pj.g[z].D = D; pj.g[z].Dh = Dh; pj.g[z].Dl = Dl;
        pj.g[z].mode = mode;
    };
    set(0, Ih, Il, Wqh,   Wql,   bq,   q,  nullptr, nullptr, 0);
    set(1, Rh, Rl, Wq12h, Wq12l, bq12, q1, nullptr, nullptr, 0);
    set(2, Gh, Gl, Wq12h, Wq12l, bq12, q2, nullptr, nullptr, 0);
    set(3, Rh, Rl, Wkh,   Wkl,   bk,   nullptr, kvh + 0*(size_t)HEADELEMS, kvl + 0*(size_t)HEADELEMS, 1);
    set(4, Gh, Gl, Wkh,   Wkl,   bk,   nullptr, kvh + 1*(size_t)HEADELEMS, kvl + 1*(size_t)HEADELEMS, 1);
    set(5, Rh, Rl, Wvh,   Wvl,   bv,   nullptr, kvh + 2*(size_t)HEADELEMS, kvl + 2*(size_t)HEADELEMS, 1);
    set(6, Gh, Gl, Wvh,   Wvl,   bv,   nullptr, kvh + 3*(size_t)HEADELEMS, kvl + 3*(size_t)HEADELEMS, 1);
    gemm_bf<<<dim3(DMODEL / 128, MTOT / 128, 7), 256, GSMEM>>>(pj);

    // ---- attention (both variants)
    attn_mma<<<dim3(NN / AQROWS, BB * HH, 2), 256, ASMEMB>>>(maskR, maskG, wts);

    // ---- 2 output projections, one launch
    GBFpack po;
    auto seto = [&](int z, int var, const __nv_bfloat16* wwh, const __nv_bfloat16* wwl,
                    const float* bi, float* D) {
        po.g[z].Xh = oh + (size_t)var * OUTHALF;
        po.g[z].Xl = ol + (size_t)var * OUTHALF;
        po.g[z].Wh = wwh; po.g[z].Wl = wwl; po.g[z].Bi = bi;
        po.g[z].D = D; po.g[z].Dh = nullptr; po.g[z].Dl = nullptr;
        po.g[z].mode = 2;
    };
    seto(0, 0, Wo1h, Wo1l, bo1, out);
    seto(1, 1, Wo2h, Wo2l, bo2, out + OUTHALF);
    for (int z = 2; z < 7; z++) po.g[z] = po.g[0];
    gemm_bf<<<dim3(DMODEL / 128, MTOT / 128, 2), 256, GSMEM>>>(po);
}

// round 9
// speedup vs baseline: 4.6857x; 1.0045x over previous
#include <cuda_runtime.h>
#include <cuda_bf16.h>
#include <math.h>
#include <stdint.h>

#define BB 2
#define NN 2048
#define DMODEL 512
#define HH 8
#define DK 64
#define MTOT (BB*NN)                 // 4096
#define HEADELEMS (BB*HH*NN*DK)      // 2097152
#define OUTHALF (MTOT*DMODEL)        // 2097152
#define INSEG (MTOT*DMODEL)          // 2097152 (one input matrix)
#define WSEG (DMODEL*DMODEL)         // 262144  (one weight matrix)

// ---------------- scratch (__device__ globals; allocation-free rule) --------
__device__ float g_q [HEADELEMS];
__device__ float g_q1[HEADELEMS];
__device__ float g_q2[HEADELEMS];
__device__ __nv_bfloat16 g_ih[3*INSEG];     // inputs hi  (interests, regions, grids)
__device__ __nv_bfloat16 g_il[3*INSEG];     // inputs lo
__device__ __nv_bfloat16 g_wh[6*WSEG];      // weights hi (Wq, Wq12, Wk, Wv, Wo1, Wo2)
__device__ __nv_bfloat16 g_wl[6*WSEG];      // weights lo
__device__ __nv_bfloat16 g_kvh[4*HEADELEMS];// K1,K2,V1,V2 hi
__device__ __nv_bfloat16 g_kvl[4*HEADELEMS];// K1,K2,V1,V2 lo
__device__ __nv_bfloat16 g_oh[2*OUTHALF];   // O1,O2 hi
__device__ __nv_bfloat16 g_ol[2*OUTHALF];   // O1,O2 lo

__device__ __forceinline__ uint32_t smem_u32(const void* p) {
    uint32_t a;
    asm("{ .reg .u64 t; cvta.to.shared.u64 t, %1; cvt.u32.u64 %0, t; }"
        : "=r"(a) : "l"(p));
    return a;
}

// ---- family-common PTX primitives (sm_80+: valid on .target sm_103) --------
__device__ __forceinline__ void ldm4(unsigned r[4], uint32_t addr) {
    asm volatile("ldmatrix.sync.aligned.m8n8.x4.shared.b16 {%0,%1,%2,%3}, [%4];"
        : "=r"(r[0]), "=r"(r[1]), "=r"(r[2]), "=r"(r[3]) : "r"(addr));
}
__device__ __forceinline__ void ldm4t(unsigned r[4], uint32_t addr) {
    asm volatile("ldmatrix.sync.aligned.m8n8.x4.trans.shared.b16 {%0,%1,%2,%3}, [%4];"
        : "=r"(r[0]), "=r"(r[1]), "=r"(r[2]), "=r"(r[3]) : "r"(addr));
}
__device__ __forceinline__ void mma16816(float c[4], const unsigned a[4],
                                         const unsigned b0, const unsigned b1) {
    asm volatile(
        "mma.sync.aligned.m16n8k16.row.col.f32.bf16.bf16.f32 "
        "{%0,%1,%2,%3}, {%4,%5,%6,%7}, {%8,%9}, {%0,%1,%2,%3};"
        : "+f"(c[0]), "+f"(c[1]), "+f"(c[2]), "+f"(c[3])
        : "r"(a[0]), "r"(a[1]), "r"(a[2]), "r"(a[3]), "r"(b0), "r"(b1));
}
#define CP_ASYNC16(dst, src) \
    asm volatile("cp.async.cg.shared.global [%0], [%1], 16;" \
        :: "r"(dst), "l"(src) : "memory")
#define CP_COMMIT() asm volatile("cp.async.commit_group;" ::: "memory")
#define CP_WAIT0()  asm volatile("cp.async.wait_group 0;" ::: "memory")

// split 8 fp32 -> 8 bf16 hi + 8 bf16 lo (residual)
__device__ __forceinline__ void split8(float4 a, float4 b, uint4& hi, uint4& lo) {
    float x[8] = {a.x, a.y, a.z, a.w, b.x, b.y, b.z, b.w};
    unsigned hw[4], lw[4];
#pragma unroll
    for (int i = 0; i < 4; i++) {
        __nv_bfloat16 h0 = __float2bfloat16_rn(x[2*i]);
        __nv_bfloat16 h1 = __float2bfloat16_rn(x[2*i+1]);
        float l0 = x[2*i]   - __bfloat162float(h0);
        float l1 = x[2*i+1] - __bfloat162float(h1);
        __nv_bfloat162 hp; hp.x = h0; hp.y = h1;
        __nv_bfloat162 lp; lp.x = __float2bfloat16_rn(l0); lp.y = __float2bfloat16_rn(l1);
        hw[i] = *reinterpret_cast<unsigned*>(&hp);
        lw[i] = *reinterpret_cast<unsigned*>(&lp);
    }
    hi = make_uint4(hw[0], hw[1], hw[2], hw[3]);
    lo = make_uint4(lw[0], lw[1], lw[2], lw[3]);
}
// split 2 fp32 -> packed bf16x2 hi + lo
__device__ __forceinline__ void split2(float v0, float v1, unsigned& hi, unsigned& lo) {
    __nv_bfloat162 h = __floats2bfloat162_rn(v0, v1);
    float r0 = v0 - __bfloat162float(h.x);
    float r1 = v1 - __bfloat162float(h.y);
    __nv_bfloat162 l = __floats2bfloat162_rn(r0, r1);
    hi = *reinterpret_cast<unsigned*>(&h);
    lo = *reinterpret_cast<unsigned*>(&l);
}

// ===========================================================================
// Prep: fp32 -> bf16 hi/lo for 3 inputs + 6 weights
// ===========================================================================
struct Prep {
    const float* src[9];
    __nv_bfloat16* dh[9];
    __nv_bfloat16* dl[9];
    int n4[9];
};

__global__ __launch_bounds__(256)
void prep_k(Prep pp)
{
    const int z  = blockIdx.y;
    const int i4 = blockIdx.x * 256 + threadIdx.x;
    if (i4 >= pp.n4[z]) return;
    float4 v = ((const float4*)pp.src[z])[i4];
    unsigned h0, l0, h1, l1;
    split2(v.x, v.y, h0, l0);
    split2(v.z, v.w, h1, l1);
    ((uint2*)pp.dh[z])[i4] = make_uint2(h0, h1);
    ((uint2*)pp.dl[z])[i4] = make_uint2(l0, l1);
}

// ===========================================================================
// cp.async double-buffered HMMA GEMM over preconverted bf16 hi/lo.
// Block tile 128x128, 8 warps (2Mx4N), warp tile 64x32, K-chunk 32, 2 stages.
// __launch_bounds__(256,2): 2 CTAs/SM (smem 82KB x2 = 164KB, regs <=128).
// ===========================================================================
#define GRSTR 80
#define GMAT  (128 * GRSTR)            // 10240 per matrix
#define GSTG  (4 * GMAT)               // 40960 per stage
#define GSMEM (2 * GSTG)               // 81920

struct GBF {
    const __nv_bfloat16 *Xh, *Xl, *Wh, *Wl;
    const float* Bi;
    float* D;
    __nv_bfloat16 *Dh, *Dl;
    int mode;                           // 0 HEADS fp32, 1 KV bf16 hi/lo, 2 ROW fp32
};
struct GBFpack { GBF g[7]; };

__global__ __launch_bounds__(256, 2)
void gemm_bf(GBFpack gp)
{
    extern __shared__ __align__(16) char smc[];
    const uint32_t sb = smem_u32(smc);

    const GBF gb = gp.g[blockIdx.z];
    const int m0 = blockIdx.y * 128;
    const int n0 = blockIdx.x * 128;

    const int tid  = threadIdx.x;
    const int wid  = tid >> 5;
    const int lane = tid & 31;
    const int warpM = wid >> 2;
    const int warpN = wid & 3;

    const int arow  = (lane & 7) + ((lane >> 3) & 1) * 8;
    const int akoff = ((lane >> 4) & 1) * 16;
    const int brow  = (lane & 7) + ((lane >> 4) & 1) * 8;
    const int bkoff = ((lane >> 3) & 1) * 16;

    float c[4][4][4];
#pragma unroll
    for (int im = 0; im < 4; im++)
#pragma unroll
        for (int jn = 0; jn < 4; jn++)
#pragma unroll
            for (int e = 0; e < 4; e++) c[im][jn][e] = 0.f;

    auto issue = [&](int s, int kc) {
#pragma unroll
        for (int p = 0; p < 8; p++) {
            const int i = tid + p * 256;
            const int t = i >> 9;               // 0 Xh,1 Xl,2 Wh,3 Wl
            const int r = (i >> 2) & 127;
            const int cc = i & 3;
            const __nv_bfloat16* src;
            if      (t == 0) src = gb.Xh + (size_t)(m0 + r) * DMODEL + kc * 32 + cc * 8;
            else if (t == 1) src = gb.Xl + (size_t)(m0 + r) * DMODEL + kc * 32 + cc * 8;
            else if (t == 2) src = gb.Wh + (size_t)(n0 + r) * DMODEL + kc * 32 + cc * 8;
            else             src = gb.Wl + (size_t)(n0 + r) * DMODEL + kc * 32 + cc * 8;
            CP_ASYNC16(sb + s * GSTG + t * GMAT + r * GRSTR + cc * 16, src);
        }
    };

    issue(0, 0);
    CP_COMMIT();

#pragma unroll 1
    for (int kc = 0; kc < 16; kc++) {
        const int b = kc & 1;
        CP_WAIT0();
        __syncthreads();
        if (kc < 15) { issue(b ^ 1, kc + 1); CP_COMMIT(); }

        const uint32_t sAh = sb + b * GSTG;
        const uint32_t sAl = sAh + GMAT;
        const uint32_t sBh = sAh + 2 * GMAT;
        const uint32_t sBl = sAh + 3 * GMAT;

#pragma unroll
        for (int ks = 0; ks < 2; ks++) {
            unsigned bh[2][4], bl[2][4];
#pragma unroll
            for (int jp = 0; jp < 2; jp++) {
                const uint32_t bo = (uint32_t)((warpN * 32 + jp * 16 + brow) * GRSTR
                                               + ks * 32 + bkoff);
                ldm4(bh[jp], sBh + bo);
                ldm4(bl[jp], sBl + bo);
            }
#pragma unroll
            for (int im = 0; im < 4; im++) {
                const uint32_t ao = (uint32_t)((warpM * 64 + im * 16 + arow) * GRSTR
                                               + ks * 32 + akoff);
                unsigned ah[4], al[4];
                ldm4(ah, sAh + ao);
                ldm4(al, sAl + ao);
#pragma unroll
                for (int jn = 0; jn < 4; jn++) {
                    const int jp = jn >> 1, jo = (jn & 1) * 2;
                    mma16816(c[im][jn], ah, bh[jp][jo], bh[jp][jo + 1]);
                    mma16816(c[im][jn], ah, bl[jp][jo], bl[jp][jo + 1]);
                    mma16816(c[im][jn], al, bh[jp][jo], bh[jp][jo + 1]);
                }
            }
        }
    }

    const int rbase = m0 + warpM * 64 + (lane >> 2);
    const int cbase = n0 + warpN * 32 + (lane & 3) * 2;
#pragma unroll
    for (int im = 0; im < 4; im++) {
#pragma unroll
        for (int jn = 0; jn < 4; jn++) {
            const int col = cbase + jn * 8;
            const float b0 = gb.Bi[col], b1 = gb.Bi[col + 1];
#pragma unroll
            for (int half = 0; half < 2; half++) {
                const int m  = rbase + im * 16 + half * 8;
                const float v0 = c[im][jn][half * 2]     + b0;
                const float v1 = c[im][jn][half * 2 + 1] + b1;
                if (gb.mode == 2) {
                    *(float2*)(gb.D + (size_t)m * DMODEL + col) = make_float2(v0, v1);
                } else {
                    const int bb = m >> 11;
                    const int n  = m & 2047;
                    const int h  = col >> 6, d = col & 63;
                    const size_t idx = (((size_t)(bb * HH + h)) * NN + n) * DK + d;
                    if (gb.mode == 0) {
                        *(float2*)(gb.D + idx) = make_float2(v0, v1);
                    } else {
                        unsigned hi, lo; split2(v0, v1, hi, lo);
                        *(unsigned*)(gb.Dh + idx) = hi;
                        *(unsigned*)(gb.Dl + idx) = lo;
                    }
                }
            }
        }
    }
}

// ===========================================================================
// cp.async double-buffered HMMA FlashAttention.
// Q fragments hoisted to registers (loop-invariant); Q staging smem aliases
// KV stage 0, so total smem = 74.75KB -> 2 CTAs/SM (enforced by launch_bounds).
// ===========================================================================
#define AQROWS 128
#define ASTRB 144
#define KMAT (64*ASTRB)              // 9216
#define KVS (4*KMAT)                 // 36864 per stage
#define ACF (2*KVS)                  // 73728
#define ASMEMB (ACF + 2*512)         // 74752

__global__ __launch_bounds__(256, 2)
void attn_mma(const int* __restrict__ mR, const int* __restrict__ mG,
              const float* __restrict__ wts)
{
    extern __shared__ __align__(16) char smn[];
    const uint32_t sb = smem_u32(smn);

    const int var = blockIdx.z;
    const int bh  = blockIdx.y;
    const int bb  = bh >> 3;
    const int h   = bh & 7;
    const int qt  = blockIdx.x;

    const float* Q  = g_q + (size_t)bh * NN * DK + (size_t)qt * AQROWS * DK;
    const float* Qx = (var ? g_q1 : g_q2) + (size_t)bh * NN * DK + (size_t)qt * AQROWS * DK;
    const int*   msk = (var ? mG : mR) + bb * NN;
    const float* w   = wts + bb * NN;

    const int tid  = threadIdx.x;
    const int wq   = tid >> 5;
    const int lane = tid & 31;
    const int lr   = lane & 7;
    const int g    = lane >> 3;

    const uint32_t qoff = (uint32_t)((wq * 16 + lr + (g & 1) * 8) * ASTRB + (g >> 1) * 16);
    const uint32_t koff = (uint32_t)((lr + (g >> 1) * 8) * ASTRB + (g & 1) * 16);
    const uint32_t voff = (uint32_t)((lr + (g & 1) * 8) * ASTRB + (g >> 1) * 16);

    auto issueKV = [&](int s, int kt) {
#pragma unroll
        for (int p = 0; p < 8; p++) {
            const int i = tid + p * 256;
            const int t = i >> 9;               // 0 Kh,1 Kl,2 Vh,3 Vl
            const int r = (i >> 3) & 63;
            const int cc = i & 7;
            const int seg = (t >> 1) ? (2 + var) : var;
            const __nv_bfloat16* base = (t & 1) ? g_kvl : g_kvh;
            const __nv_bfloat16* src = base + (size_t)seg * HEADELEMS
                + (size_t)bh * NN * DK + (size_t)(kt * 64 + r) * DK + cc * 8;
            CP_ASYNC16(sb + s * KVS + t * KMAT + r * ASTRB + cc * 16, src);
        }
    };

    // ---- stage Q (fp32, fused add, split) into the stage-0 area
#pragma unroll
    for (int p = 0; p < 4; p++) {
        const int s   = tid + p * 256;
        const int row = s >> 3;
        const int c8  = (s & 7) * 8;
        float4 a0 = *(const float4*)(Q  + (size_t)row * DK + c8);
        float4 a1 = *(const float4*)(Q  + (size_t)row * DK + c8 + 4);
        float4 b0 = *(const float4*)(Qx + (size_t)row * DK + c8);
        float4 b1 = *(const float4*)(Qx + (size_t)row * DK + c8 + 4);
        a0.x += b0.x; a0.y += b0.y; a0.z += b0.z; a0.w += b0.w;
        a1.x += b1.x; a1.y += b1.y; a1.z += b1.z; a1.w += b1.w;
        uint4 hi, lo; split8(a0, a1, hi, lo);
        const uint32_t soff = (uint32_t)(row * ASTRB + c8 * 2);
        *(uint4*)(smn + soff) = hi;                 // Qh at stage0 + 0
        *(uint4*)(smn + 128 * ASTRB + soff) = lo;   // Ql at stage0 + 18432
    }
    __syncthreads();

    // ---- hoist Q fragments into registers (loop-invariant)
    unsigned aqh[4][4], aql[4][4];
#pragma unroll
    for (int t = 0; t < 4; t++) {
        ldm4(aqh[t], sb + qoff + 32 * t);
        ldm4(aql[t], sb + 128 * ASTRB + qoff + 32 * t);
    }
    __syncthreads();   // Q staging consumed; stage 0 may be overwritten

    // ---- prologue: stage 0 copies + cf[0]
    issueKV(0, 0);
    CP_COMMIT();
    if (tid < 64) {
        float mul, add;
        if (msk[tid]) { mul = 0.f; add = -1e38f; }
        else          { mul = 0.125f * w[tid]; add = 0.f; }
        *(float2*)(smn + ACF + tid * 8) = make_float2(mul, add);
    }

    float o[8][4];
#pragma unroll
    for (int j = 0; j < 8; j++)
#pragma unroll
        for (int e = 0; e < 4; e++) o[j][e] = 0.f;
    float m0 = -INFINITY, m1 = -INFINITY, l0 = 0.f, l1 = 0.f;

#pragma unroll 1
    for (int kt = 0; kt < NN / 64; kt++) {
        const int b = kt & 1;
        CP_WAIT0();
        __syncthreads();
        if (kt < NN / 64 - 1) {
            issueKV(b ^ 1, kt + 1);
            CP_COMMIT();
            if (tid < 64) {
                const int key = (kt + 1) * 64 + tid;
                float mul, add;
                if (msk[key]) { mul = 0.f; add = -1e38f; }
                else          { mul = 0.125f * w[key]; add = 0.f; }
                *(float2*)(smn + ACF + (b ^ 1) * 512 + tid * 8) = make_float2(mul, add);
            }
        }

        const uint32_t sKh = sb + b * KVS;
        const uint32_t sKl = sKh + KMAT;
        const uint32_t sVh = sKh + 2 * KMAT;
        const uint32_t sVl = sKh + 3 * KMAT;

        // ---- S = (q+qx) K^T, 3-term split
        float s[8][4];
#pragma unroll
        for (int j = 0; j < 8; j++)
#pragma unroll
            for (int e = 0; e < 4; e++) s[j][e] = 0.f;

#pragma unroll
        for (int u = 0; u < 4; u++) {
#pragma unroll
            for (int t = 0; t < 4; t++) {
                unsigned bkh[4], bkl[4];
                const uint32_t ka = koff + (uint32_t)(u * 16 * ASTRB + 32 * t);
                ldm4(bkh, sKh + ka);
                ldm4(bkl, sKl + ka);
                mma16816(s[2*u],   aqh[t], bkh[0], bkh[1]);
                mma16816(s[2*u],   aqh[t], bkl[0], bkl[1]);
                mma16816(s[2*u],   aql[t], bkh[0], bkh[1]);
                mma16816(s[2*u+1], aqh[t], bkh[2], bkh[3]);
                mma16816(s[2*u+1], aqh[t], bkl[2], bkl[3]);
                mma16816(s[2*u+1], aql[t], bkh[2], bkh[3]);
            }
        }

        // ---- fused scale*weight + mask
#pragma unroll
        for (int j = 0; j < 8; j++) {
            float4 cc = *(const float4*)(smn + ACF + b * 512 + (8 * j + (lane & 3) * 2) * 8);
            s[j][0] = fmaf(s[j][0], cc.x, cc.y);
            s[j][1] = fmaf(s[j][1], cc.z, cc.w);
            s[j][2] = fmaf(s[j][2], cc.x, cc.y);
            s[j][3] = fmaf(s[j][3], cc.z, cc.w);
        }

        // ---- online softmax
        float mt0 = -INFINITY, mt1 = -INFINITY;
#pragma unroll
        for (int j = 0; j < 8; j++) {
            mt0 = fmaxf(mt0, fmaxf(s[j][0], s[j][1]));
            mt1 = fmaxf(mt1, fmaxf(s[j][2], s[j][3]));
        }
        mt0 = fmaxf(mt0, __shfl_xor_sync(0xffffffffu, mt0, 1));
        mt0 = fmaxf(mt0, __shfl_xor_sync(0xffffffffu, mt0, 2));
        mt1 = fmaxf(mt1, __shfl_xor_sync(0xffffffffu, mt1, 1));
        mt1 = fmaxf(mt1, __shfl_xor_sync(0xffffffffu, mt1, 2));

        const float mn0 = fmaxf(m0, mt0);
        const float mn1 = fmaxf(m1, mt1);
        const float mx0 = fmaxf(mn0, -1e30f);
        const float mx1 = fmaxf(mn1, -1e30f);
        const float f0 = __expf(m0 - mx0);
        const float f1 = __expf(m1 - mx1);
        m0 = mn0; m1 = mn1;

        float rs0 = 0.f, rs1 = 0.f;
#pragma unroll
        for (int j = 0; j < 8; j++) {
            s[j][0] = __expf(s[j][0] - mx0);
            s[j][1] = __expf(s[j][1] - mx0);
            s[j][2] = __expf(s[j][2] - mx1);
            s[j][3] = __expf(s[j][3] - mx1);
            rs0 += s[j][0] + s[j][1];
            rs1 += s[j][2] + s[j][3];
        }
        rs0 += __shfl_xor_sync(0xffffffffu, rs0, 1);
        rs0 += __shfl_xor_sync(0xffffffffu, rs0, 2);
        rs1 += __shfl_xor_sync(0xffffffffu, rs1, 1);
        rs1 += __shfl_xor_sync(0xffffffffu, rs1, 2);
        l0 = l0 * f0 + rs0;
        l1 = l1 * f1 + rs1;

#pragma unroll
        for (int j = 0; j < 8; j++) {
            o[j][0] *= f0; o[j][1] *= f0;
            o[j][2] *= f1; o[j][3] *= f1;
        }

        // ---- pack P into bf16 hi/lo A-fragments (registers only)
        unsigned pha[16], pla[16];
#pragma unroll
        for (int j = 0; j < 8; j++) {
            split2(s[j][0], s[j][1], pha[2*j],   pla[2*j]);
            split2(s[j][2], s[j][3], pha[2*j+1], pla[2*j+1]);
        }

        // ---- O += P V, 3-term split
#pragma unroll
        for (int t = 0; t < 4; t++) {
            const unsigned* aph = &pha[4 * t];
            const unsigned* apl = &pla[4 * t];
#pragma unroll
            for (int u = 0; u < 4; u++) {
                unsigned bvh[4], bvl[4];
                const uint32_t va = voff + (uint32_t)(t * 16 * ASTRB + 32 * u);
                ldm4t(bvh, sVh + va);
                ldm4t(bvl, sVl + va);
                mma16816(o[2*u],   aph, bvh[0], bvh[1]);
                mma16816(o[2*u],   aph, bvl[0], bvl[1]);
                mma16816(o[2*u],   apl, bvh[0], bvh[1]);
                mma16816(o[2*u+1], aph, bvh[2], bvh[3]);
                mma16816(o[2*u+1], aph, bvl[2], bvl[3]);
                mma16816(o[2*u+1], apl, bvh[2], bvh[3]);
            }
        }
    }

    // ---- epilogue: normalize, split, store bf16 hi/lo to g_oh/g_ol
    const float inv0 = 1.f / l0;
    const float inv1 = 1.f / l1;
    const int r = qt * AQROWS + wq * 16 + (lane >> 2);
    __nv_bfloat16* Oh = g_oh + (size_t)var * OUTHALF;
    __nv_bfloat16* Ol = g_ol + (size_t)var * OUTHALF;
#pragma unroll
    for (int j = 0; j < 8; j++) {
        const int col = h * DK + 8 * j + (lane & 3) * 2;
        const size_t i0 = ((size_t)bb * NN + r)     * DMODEL + col;
        const size_t i1 = ((size_t)bb * NN + r + 8) * DMODEL + col;
        unsigned hi, lo;
        split2(o[j][0] * inv0, o[j][1] * inv0, hi, lo);
        *(unsigned*)(Oh + i0) = hi;
        *(unsigned*)(Ol + i0) = lo;
        split2(o[j][2] * inv1, o[j][3] * inv1, hi, lo);
        *(unsigned*)(Oh + i1) = hi;
        *(unsigned*)(Ol + i1) = lo;
    }
}

// ===========================================================================
extern "C" void kernel_launch(void* const* d_in, const int* in_sizes, int n_in,
                              void* d_out, int out_size)
{
    const float* regions   = (const float*)d_in[0];
    const float* grids     = (const float*)d_in[1];
    const float* interests = (const float*)d_in[2];
    const int*   maskR     = (const int*)d_in[3];
    const int*   maskG     = (const int*)d_in[4];
    const float* wts       = (const float*)d_in[5];
    const float* Wq   = (const float*)d_in[6];
    const float* bq   = (const float*)d_in[7];
    const float* Wk   = (const float*)d_in[8];
    const float* bk   = (const float*)d_in[9];
    const float* Wv   = (const float*)d_in[10];
    const float* bv   = (const float*)d_in[11];
    const float* Wq12 = (const float*)d_in[12];
    const float* bq12 = (const float*)d_in[13];
    const float* Wo1  = (const float*)d_in[14];
    const float* bo1  = (const float*)d_in[15];
    const float* Wo2  = (const float*)d_in[16];
    const float* bo2  = (const float*)d_in[17];
    float* out = (float*)d_out;

    float *q, *q1, *q2;
    __nv_bfloat16 *ih, *il, *wh, *wl, *kvh, *kvl, *oh, *ol;
    cudaGetSymbolAddress((void**)&q,   g_q);
    cudaGetSymbolAddress((void**)&q1,  g_q1);
    cudaGetSymbolAddress((void**)&q2,  g_q2);
    cudaGetSymbolAddress((void**)&ih,  g_ih);
    cudaGetSymbolAddress((void**)&il,  g_il);
    cudaGetSymbolAddress((void**)&wh,  g_wh);
    cudaGetSymbolAddress((void**)&wl,  g_wl);
    cudaGetSymbolAddress((void**)&kvh, g_kvh);
    cudaGetSymbolAddress((void**)&kvl, g_kvl);
    cudaGetSymbolAddress((void**)&oh,  g_oh);
    cudaGetSymbolAddress((void**)&ol,  g_ol);

    cudaFuncSetAttribute(gemm_bf, cudaFuncAttributeMaxDynamicSharedMemorySize, GSMEM);
    cudaFuncSetAttribute(attn_mma, cudaFuncAttributeMaxDynamicSharedMemorySize, ASMEMB);

    // ---- prep: fp32 -> bf16 hi/lo (3 inputs + 6 weights)
    Prep pp;
    const float* srcs[9] = {interests, regions, grids, Wq, Wq12, Wk, Wv, Wo1, Wo2};
    for (int z = 0; z < 9; z++) {
        pp.src[z] = srcs[z];
        if (z < 3) {
            pp.dh[z] = ih + (size_t)z * INSEG;
            pp.dl[z] = il + (size_t)z * INSEG;
            pp.n4[z] = INSEG / 4;
        } else {
            pp.dh[z] = wh + (size_t)(z - 3) * WSEG;
            pp.dl[z] = wl + (size_t)(z - 3) * WSEG;
            pp.n4[z] = WSEG / 4;
        }
    }
    prep_k<<<dim3(INSEG / 4 / 256, 9), 256>>>(pp);

    const __nv_bfloat16 *Ih = ih, *Rh = ih + INSEG, *Gh = ih + 2 * (size_t)INSEG;
    const __nv_bfloat16 *Il = il, *Rl = il + INSEG, *Gl = il + 2 * (size_t)INSEG;
    const __nv_bfloat16 *Wqh = wh, *Wq12h = wh + WSEG, *Wkh = wh + 2*(size_t)WSEG,
                        *Wvh = wh + 3*(size_t)WSEG, *Wo1h = wh + 4*(size_t)WSEG,
                        *Wo2h = wh + 5*(size_t)WSEG;
    const __nv_bfloat16 *Wql = wl, *Wq12l = wl + WSEG, *Wkl = wl + 2*(size_t)WSEG,
                        *Wvl = wl + 3*(size_t)WSEG, *Wo1l = wl + 4*(size_t)WSEG,
                        *Wo2l = wl + 5*(size_t)WSEG;

    // ---- 7 projections, one launch
    GBFpack pj;
    auto set = [&](int z, const __nv_bfloat16* xh, const __nv_bfloat16* xl,
                   const __nv_bfloat16* wwh, const __nv_bfloat16* wwl,
                   const float* bi, float* D, __nv_bfloat16* Dh, __nv_bfloat16* Dl,
                   int mode) {
        pj.g[z].Xh = xh; pj.g[z].Xl = xl; pj.g[z].Wh = wwh; pj.g[z].Wl = wwl;
        pj.g[z].Bi = bi; pj.g[z].D = D; pj.g[z].Dh = Dh; pj.g[z].Dl = Dl;
        pj.g[z].mode = mode;
    };
    set(0, Ih, Il, Wqh,   Wql,   bq,   q,  nullptr, nullptr, 0);
    set(1, Rh, Rl, Wq12h, Wq12l, bq12, q1, nullptr, nullptr, 0);
    set(2, Gh, Gl, Wq12h, Wq12l, bq12, q2, nullptr, nullptr, 0);
    set(3, Rh, Rl, Wkh,   Wkl,   bk,   nullptr, kvh + 0*(size_t)HEADELEMS, kvl + 0*(size_t)HEADELEMS, 1);
    set(4, Gh, Gl, Wkh,   Wkl,   bk,   nullptr, kvh + 1*(size_t)HEADELEMS, kvl + 1*(size_t)HEADELEMS, 1);
    set(5, Rh, Rl, Wvh,   Wvl,   bv,   nullptr, kvh + 2*(size_t)HEADELEMS, kvl + 2*(size_t)HEADELEMS, 1);
    set(6, Gh, Gl, Wvh,   Wvl,   bv,   nullptr, kvh + 3*(size_t)HEADELEMS, kvl + 3*(size_t)HEADELEMS, 1);
    gemm_bf<<<dim3(DMODEL / 128, MTOT / 128, 7), 256, GSMEM>>>(pj);

    // ---- attention (both variants)
    attn_mma<<<dim3(NN / AQROWS, BB * HH, 2), 256, ASMEMB>>>(maskR, maskG, wts);

    // ---- 2 output projections, one launch
    GBFpack po;
    auto seto = [&](int z, int var, const __nv_bfloat16* wwh, const __nv_bfloat16* wwl,
                    const float* bi, float* D) {
        po.g[z].Xh = oh + (size_t)var * OUTHALF;
        po.g[z].Xl = ol + (size_t)var * OUTHALF;
        po.g[z].Wh = wwh; po.g[z].Wl = wwl; po.g[z].Bi = bi;
        po.g[z].D = D; po.g[z].Dh = nullptr; po.g[z].Dl = nullptr;
        po.g[z].mode = 2;
    };
    seto(0, 0, Wo1h, Wo1l, bo1, out);
    seto(1, 1, Wo2h, Wo2l, bo2, out + OUTHALF);
    for (int z = 2; z < 7; z++) po.g[z] = po.g[0];
    gemm_bf<<<dim3(DMODEL / 128, MTOT / 128, 2), 256, GSMEM>>>(po);
}

// round 10
// speedup vs baseline: 6.4309x; 1.3725x over previous
#include <cuda_runtime.h>
#include <cuda_bf16.h>
#include <math.h>
#include <stdint.h>

#define BB 2
#define NN 2048
#define DMODEL 512
#define HH 8
#define DK 64
#define MTOT (BB*NN)                 // 4096
#define HEADELEMS (BB*HH*NN*DK)      // 2097152
#define OUTHALF (MTOT*DMODEL)        // 2097152
#define INSEG (MTOT*DMODEL)          // 2097152 (one input matrix)
#define WSEG (DMODEL*DMODEL)         // 262144  (one weight matrix)

// ---------------- scratch (__device__ globals; allocation-free rule) --------
__device__ float g_q [HEADELEMS];
__device__ float g_q1[HEADELEMS];
__device__ float g_q2[HEADELEMS];
__device__ __nv_bfloat16 g_ih[3*INSEG];     // inputs hi  (interests, regions, grids)
__device__ __nv_bfloat16 g_il[3*INSEG];     // inputs lo
__device__ __nv_bfloat16 g_wh[6*WSEG];      // weights hi (Wq, Wq12, Wk, Wv, Wo1, Wo2)
__device__ __nv_bfloat16 g_wl[6*WSEG];      // weights lo
__device__ __nv_bfloat16 g_kvh[4*HEADELEMS];// K1,K2,V1,V2 hi
__device__ __nv_bfloat16 g_kvl[4*HEADELEMS];// K1,K2,V1,V2 lo
__device__ __nv_bfloat16 g_oh[2*OUTHALF];   // O1,O2 hi
__device__ __nv_bfloat16 g_ol[2*OUTHALF];   // O1,O2 lo
// key compaction per (var, batch): indices, coefficients, padded counts
__device__ int    g_cidx[4*NN];
__device__ float2 g_ccf [4*NN];
__device__ int    g_pcnt[4];

__device__ __forceinline__ uint32_t smem_u32(const void* p) {
    uint32_t a;
    asm("{ .reg .u64 t; cvta.to.shared.u64 t, %1; cvt.u32.u64 %0, t; }"
        : "=r"(a) : "l"(p));
    return a;
}

// ---- family-common PTX primitives (sm_80+: valid on .target sm_103) --------
__device__ __forceinline__ void ldm4(unsigned r[4], uint32_t addr) {
    asm volatile("ldmatrix.sync.aligned.m8n8.x4.shared.b16 {%0,%1,%2,%3}, [%4];"
        : "=r"(r[0]), "=r"(r[1]), "=r"(r[2]), "=r"(r[3]) : "r"(addr));
}
__device__ __forceinline__ void ldm4t(unsigned r[4], uint32_t addr) {
    asm volatile("ldmatrix.sync.aligned.m8n8.x4.trans.shared.b16 {%0,%1,%2,%3}, [%4];"
        : "=r"(r[0]), "=r"(r[1]), "=r"(r[2]), "=r"(r[3]) : "r"(addr));
}
__device__ __forceinline__ void mma16816(float c[4], const unsigned a[4],
                                         const unsigned b0, const unsigned b1) {
    asm volatile(
        "mma.sync.aligned.m16n8k16.row.col.f32.bf16.bf16.f32 "
        "{%0,%1,%2,%3}, {%4,%5,%6,%7}, {%8,%9}, {%0,%1,%2,%3};"
        : "+f"(c[0]), "+f"(c[1]), "+f"(c[2]), "+f"(c[3])
        : "r"(a[0]), "r"(a[1]), "r"(a[2]), "r"(a[3]), "r"(b0), "r"(b1));
}
#define CP_ASYNC16(dst, src) \
    asm volatile("cp.async.cg.shared.global [%0], [%1], 16;" \
        :: "r"(dst), "l"(src) : "memory")
#define CP_COMMIT() asm volatile("cp.async.commit_group;" ::: "memory")
#define CP_WAIT0()  asm volatile("cp.async.wait_group 0;" ::: "memory")

// split 8 fp32 -> 8 bf16 hi + 8 bf16 lo (residual)
__device__ __forceinline__ void split8(float4 a, float4 b, uint4& hi, uint4& lo) {
    float x[8] = {a.x, a.y, a.z, a.w, b.x, b.y, b.z, b.w};
    unsigned hw[4], lw[4];
#pragma unroll
    for (int i = 0; i < 4; i++) {
        __nv_bfloat16 h0 = __float2bfloat16_rn(x[2*i]);
        __nv_bfloat16 h1 = __float2bfloat16_rn(x[2*i+1]);
        float l0 = x[2*i]   - __bfloat162float(h0);
        float l1 = x[2*i+1] - __bfloat162float(h1);
        __nv_bfloat162 hp; hp.x = h0; hp.y = h1;
        __nv_bfloat162 lp; lp.x = __float2bfloat16_rn(l0); lp.y = __float2bfloat16_rn(l1);
        hw[i] = *reinterpret_cast<unsigned*>(&hp);
        lw[i] = *reinterpret_cast<unsigned*>(&lp);
    }
    hi = make_uint4(hw[0], hw[1], hw[2], hw[3]);
    lo = make_uint4(lw[0], lw[1], lw[2], lw[3]);
}
// split 2 fp32 -> packed bf16x2 hi + lo
__device__ __forceinline__ void split2(float v0, float v1, unsigned& hi, unsigned& lo) {
    __nv_bfloat162 h = __floats2bfloat162_rn(v0, v1);
    float r0 = v0 - __bfloat162float(h.x);
    float r1 = v1 - __bfloat162float(h.y);
    __nv_bfloat162 l = __floats2bfloat162_rn(r0, r1);
    hi = *reinterpret_cast<unsigned*>(&h);
    lo = *reinterpret_cast<unsigned*>(&l);
}

// ===========================================================================
// Prep: fp32 -> bf16 hi/lo for 3 inputs + 6 weights
// ===========================================================================
struct Prep {
    const float* src[9];
    __nv_bfloat16* dh[9];
    __nv_bfloat16* dl[9];
    int n4[9];
};

__global__ __launch_bounds__(256)
void prep_k(Prep pp)
{
    const int z  = blockIdx.y;
    const int i4 = blockIdx.x * 256 + threadIdx.x;
    if (i4 >= pp.n4[z]) return;
    float4 v = ((const float4*)pp.src[z])[i4];
    unsigned h0, l0, h1, l1;
    split2(v.x, v.y, h0, l0);
    split2(v.z, v.w, h1, l1);
    ((uint2*)pp.dh[z])[i4] = make_uint2(h0, h1);
    ((uint2*)pp.dl[z])[i4] = make_uint2(l0, l1);
}

// ===========================================================================
// Compact: per (var, batch), deterministic block-scan of the key mask ->
// ascending index list of unmasked keys + (mul, add) coefficients, padded
// to a multiple of 64 with fully-masked entries. grid = 4 blocks.
// ===========================================================================
__global__ __launch_bounds__(256)
void compact_k(const int* __restrict__ mR, const int* __restrict__ mG,
               const float* __restrict__ wts)
{
    const int cvi = blockIdx.x;          // var*2 + bb
    const int var = cvi >> 1, bb = cvi & 1;
    const int* msk = (var ? mG : mR) + bb * NN;
    const float* w = wts + bb * NN;
    __shared__ int sc[256];

    const int t = threadIdx.x;
    int keep[8];
    int cnt = 0;
#pragma unroll
    for (int j = 0; j < 8; j++) {
        const int key = t * 8 + j;
        if (msk[key] == 0) keep[cnt++] = key;
    }
    sc[t] = cnt;
    __syncthreads();
    // Hillis-Steele inclusive scan (deterministic)
    for (int d = 1; d < 256; d <<= 1) {
        int v = (t >= d) ? sc[t - d] : 0;
        __syncthreads();
        sc[t] += v;
        __syncthreads();
    }
    const int off = sc[t] - cnt;         // exclusive offset
    const int total = sc[255];
    for (int j = 0; j < cnt; j++) {
        const int key = keep[j];
        g_cidx[cvi * NN + off + j] = key;
        g_ccf [cvi * NN + off + j] = make_float2(0.125f * w[key], 0.f);
    }
    const int padded = (total + 63) & ~63;
    for (int i = total + t; i < padded; i += 256) {
        g_cidx[cvi * NN + i] = 0;
        g_ccf [cvi * NN + i] = make_float2(0.f, -1e38f);
    }
    if (t == 0) g_pcnt[cvi] = padded;
}

// ===========================================================================
// cp.async double-buffered HMMA GEMM over preconverted bf16 hi/lo (proven).
// ===========================================================================
#define GRSTR 80
#define GMAT  (128 * GRSTR)
#define GSTG  (4 * GMAT)
#define GSMEM (2 * GSTG)               // 81920

struct GBF {
    const __nv_bfloat16 *Xh, *Xl, *Wh, *Wl;
    const float* Bi;
    float* D;
    __nv_bfloat16 *Dh, *Dl;
    int mode;                           // 0 HEADS fp32, 1 KV bf16 hi/lo, 2 ROW fp32
};
struct GBFpack { GBF g[7]; };

__global__ __launch_bounds__(256, 2)
void gemm_bf(GBFpack gp)
{
    extern __shared__ __align__(16) char smc[];
    const uint32_t sb = smem_u32(smc);

    const GBF gb = gp.g[blockIdx.z];
    const int m0 = blockIdx.y * 128;
    const int n0 = blockIdx.x * 128;

    const int tid  = threadIdx.x;
    const int wid  = tid >> 5;
    const int lane = tid & 31;
    const int warpM = wid >> 2;
    const int warpN = wid & 3;

    const int arow  = (lane & 7) + ((lane >> 3) & 1) * 8;
    const int akoff = ((lane >> 4) & 1) * 16;
    const int brow  = (lane & 7) + ((lane >> 4) & 1) * 8;
    const int bkoff = ((lane >> 3) & 1) * 16;

    float c[4][4][4];
#pragma unroll
    for (int im = 0; im < 4; im++)
#pragma unroll
        for (int jn = 0; jn < 4; jn++)
#pragma unroll
            for (int e = 0; e < 4; e++) c[im][jn][e] = 0.f;

    auto issue = [&](int s, int kc) {
#pragma unroll
        for (int p = 0; p < 8; p++) {
            const int i = tid + p * 256;
            const int t = i >> 9;
            const int r = (i >> 2) & 127;
            const int cc = i & 3;
            const __nv_bfloat16* src;
            if      (t == 0) src = gb.Xh + (size_t)(m0 + r) * DMODEL + kc * 32 + cc * 8;
            else if (t == 1) src = gb.Xl + (size_t)(m0 + r) * DMODEL + kc * 32 + cc * 8;
            else if (t == 2) src = gb.Wh + (size_t)(n0 + r) * DMODEL + kc * 32 + cc * 8;
            else             src = gb.Wl + (size_t)(n0 + r) * DMODEL + kc * 32 + cc * 8;
            CP_ASYNC16(sb + s * GSTG + t * GMAT + r * GRSTR + cc * 16, src);
        }
    };

    issue(0, 0);
    CP_COMMIT();

#pragma unroll 1
    for (int kc = 0; kc < 16; kc++) {
        const int b = kc & 1;
        CP_WAIT0();
        __syncthreads();
        if (kc < 15) { issue(b ^ 1, kc + 1); CP_COMMIT(); }

        const uint32_t sAh = sb + b * GSTG;
        const uint32_t sAl = sAh + GMAT;
        const uint32_t sBh = sAh + 2 * GMAT;
        const uint32_t sBl = sAh + 3 * GMAT;

#pragma unroll
        for (int ks = 0; ks < 2; ks++) {
            unsigned bh[2][4], bl[2][4];
#pragma unroll
            for (int jp = 0; jp < 2; jp++) {
                const uint32_t bo = (uint32_t)((warpN * 32 + jp * 16 + brow) * GRSTR
                                               + ks * 32 + bkoff);
                ldm4(bh[jp], sBh + bo);
                ldm4(bl[jp], sBl + bo);
            }
#pragma unroll
            for (int im = 0; im < 4; im++) {
                const uint32_t ao = (uint32_t)((warpM * 64 + im * 16 + arow) * GRSTR
                                               + ks * 32 + akoff);
                unsigned ah[4], al[4];
                ldm4(ah, sAh + ao);
                ldm4(al, sAl + ao);
#pragma unroll
                for (int jn = 0; jn < 4; jn++) {
                    const int jp = jn >> 1, jo = (jn & 1) * 2;
                    mma16816(c[im][jn], ah, bh[jp][jo], bh[jp][jo + 1]);
                    mma16816(c[im][jn], ah, bl[jp][jo], bl[jp][jo + 1]);
                    mma16816(c[im][jn], al, bh[jp][jo], bh[jp][jo + 1]);
                }
            }
        }
    }

    const int rbase = m0 + warpM * 64 + (lane >> 2);
    const int cbase = n0 + warpN * 32 + (lane & 3) * 2;
#pragma unroll
    for (int im = 0; im < 4; im++) {
#pragma unroll
        for (int jn = 0; jn < 4; jn++) {
            const int col = cbase + jn * 8;
            const float b0 = gb.Bi[col], b1 = gb.Bi[col + 1];
#pragma unroll
            for (int half = 0; half < 2; half++) {
                const int m  = rbase + im * 16 + half * 8;
                const float v0 = c[im][jn][half * 2]     + b0;
                const float v1 = c[im][jn][half * 2 + 1] + b1;
                if (gb.mode == 2) {
                    *(float2*)(gb.D + (size_t)m * DMODEL + col) = make_float2(v0, v1);
                } else {
                    const int bb = m >> 11;
                    const int n  = m & 2047;
                    const int h  = col >> 6, d = col & 63;
                    const size_t idx = (((size_t)(bb * HH + h)) * NN + n) * DK + d;
                    if (gb.mode == 0) {
                        *(float2*)(gb.D + idx) = make_float2(v0, v1);
                    } else {
                        unsigned hi, lo; split2(v0, v1, hi, lo);
                        *(unsigned*)(gb.Dh + idx) = hi;
                        *(unsigned*)(gb.Dl + idx) = lo;
                    }
                }
            }
        }
    }
}

// ===========================================================================
// cp.async double-buffered HMMA FlashAttention over COMPACTED keys.
// Q frags in registers; K/V rows gathered via g_cidx; coefficients from g_ccf.
// ===========================================================================
#define AQROWS 128
#define ASTRB 144
#define KMAT (64*ASTRB)              // 9216
#define KVS (4*KMAT)                 // 36864 per stage
#define ACF (2*KVS)                  // 73728
#define ASMEMB (ACF + 2*512)         // 74752

__global__ __launch_bounds__(256, 2)
void attn_mma()
{
    extern __shared__ __align__(16) char smn[];
    const uint32_t sb = smem_u32(smn);

    const int var = blockIdx.z;
    const int bh  = blockIdx.y;
    const int bb  = bh >> 3;
    const int h   = bh & 7;
    const int qt  = blockIdx.x;
    const int cvi = var * 2 + bb;

    const float* Q  = g_q + (size_t)bh * NN * DK + (size_t)qt * AQROWS * DK;
    const float* Qx = (var ? g_q1 : g_q2) + (size_t)bh * NN * DK + (size_t)qt * AQROWS * DK;
    const int*    cidx = g_cidx + cvi * NN;
    const float2* ccf  = g_ccf  + cvi * NN;
    const int ntk = g_pcnt[cvi] >> 6;      // number of 64-key tiles

    const int tid  = threadIdx.x;
    const int wq   = tid >> 5;
    const int lane = tid & 31;
    const int lr   = lane & 7;
    const int g    = lane >> 3;

    const uint32_t qoff = (uint32_t)((wq * 16 + lr + (g & 1) * 8) * ASTRB + (g >> 1) * 16);
    const uint32_t koff = (uint32_t)((lr + (g >> 1) * 8) * ASTRB + (g & 1) * 16);
    const uint32_t voff = (uint32_t)((lr + (g & 1) * 8) * ASTRB + (g >> 1) * 16);

    // gathered KV stage copy; each thread covers smem rows (tid>>3) and +32
    auto issueKV = [&](int s, int kt) {
        const int r0l = tid >> 3;               // local row 0..31
        const int gr0 = cidx[kt * 64 + r0l];
        const int gr1 = cidx[kt * 64 + r0l + 32];
#pragma unroll
        for (int p = 0; p < 8; p++) {
            const int i = tid + p * 256;
            const int t = i >> 9;               // 0 Kh,1 Kl,2 Vh,3 Vl
            const int rl = r0l + 32 * (p & 1);  // local smem row
            const int gr = (p & 1) ? gr1 : gr0; // gathered global key row
            const int cc = tid & 7;
            const int seg = (t >> 1) ? (2 + var) : var;
            const __nv_bfloat16* base = (t & 1) ? g_kvl : g_kvh;
            const __nv_bfloat16* src = base + (size_t)seg * HEADELEMS
                + (size_t)bh * NN * DK + (size_t)gr * DK + cc * 8;
            CP_ASYNC16(sb + s * KVS + t * KMAT + rl * ASTRB + cc * 16, src);
        }
    };

    // ---- stage Q (fp32, fused add, split) into the stage-0 area
#pragma unroll
    for (int p = 0; p < 4; p++) {
        const int s   = tid + p * 256;
        const int row = s >> 3;
        const int c8  = (s & 7) * 8;
        float4 a0 = *(const float4*)(Q  + (size_t)row * DK + c8);
        float4 a1 = *(const float4*)(Q  + (size_t)row * DK + c8 + 4);
        float4 b0 = *(const float4*)(Qx + (size_t)row * DK + c8);
        float4 b1 = *(const float4*)(Qx + (size_t)row * DK + c8 + 4);
        a0.x += b0.x; a0.y += b0.y; a0.z += b0.z; a0.w += b0.w;
        a1.x += b1.x; a1.y += b1.y; a1.z += b1.z; a1.w += b1.w;
        uint4 hi, lo; split8(a0, a1, hi, lo);
        const uint32_t soff = (uint32_t)(row * ASTRB + c8 * 2);
        *(uint4*)(smn + soff) = hi;
        *(uint4*)(smn + 128 * ASTRB + soff) = lo;
    }
    __syncthreads();

    // ---- hoist Q fragments into registers (loop-invariant)
    unsigned aqh[4][4], aql[4][4];
#pragma unroll
    for (int t = 0; t < 4; t++) {
        ldm4(aqh[t], sb + qoff + 32 * t);
        ldm4(aql[t], sb + 128 * ASTRB + qoff + 32 * t);
    }
    __syncthreads();   // Q staging consumed; stage 0 may be overwritten

    // ---- prologue
    issueKV(0, 0);
    CP_COMMIT();
    if (tid < 64)
        *(float2*)(smn + ACF + tid * 8) = ccf[tid];

    float o[8][4];
#pragma unroll
    for (int j = 0; j < 8; j++)
#pragma unroll
        for (int e = 0; e < 4; e++) o[j][e] = 0.f;
    float m0 = -INFINITY, m1 = -INFINITY, l0 = 0.f, l1 = 0.f;

#pragma unroll 1
    for (int kt = 0; kt < ntk; kt++) {
        const int b = kt & 1;
        CP_WAIT0();
        __syncthreads();
        if (kt < ntk - 1) {
            issueKV(b ^ 1, kt + 1);
            CP_COMMIT();
            if (tid < 64)
                *(float2*)(smn + ACF + (b ^ 1) * 512 + tid * 8) = ccf[(kt + 1) * 64 + tid];
        }

        const uint32_t sKh = sb + b * KVS;
        const uint32_t sKl = sKh + KMAT;
        const uint32_t sVh = sKh + 2 * KMAT;
        const uint32_t sVl = sKh + 3 * KMAT;

        // ---- S = (q+qx) K^T, 3-term split
        float s[8][4];
#pragma unroll
        for (int j = 0; j < 8; j++)
#pragma unroll
            for (int e = 0; e < 4; e++) s[j][e] = 0.f;

#pragma unroll
        for (int u = 0; u < 4; u++) {
#pragma unroll
            for (int t = 0; t < 4; t++) {
                unsigned bkh[4], bkl[4];
                const uint32_t ka = koff + (uint32_t)(u * 16 * ASTRB + 32 * t);
                ldm4(bkh, sKh + ka);
                ldm4(bkl, sKl + ka);
                mma16816(s[2*u],   aqh[t], bkh[0], bkh[1]);
                mma16816(s[2*u],   aqh[t], bkl[0], bkl[1]);
                mma16816(s[2*u],   aql[t], bkh[0], bkh[1]);
                mma16816(s[2*u+1], aqh[t], bkh[2], bkh[3]);
                mma16816(s[2*u+1], aqh[t], bkl[2], bkl[3]);
                mma16816(s[2*u+1], aql[t], bkh[2], bkh[3]);
            }
        }

        // ---- fused scale*weight (+mask via add for padding)
#pragma unroll
        for (int j = 0; j < 8; j++) {
            float4 cc = *(const float4*)(smn + ACF + b * 512 + (8 * j + (lane & 3) * 2) * 8);
            s[j][0] = fmaf(s[j][0], cc.x, cc.y);
            s[j][1] = fmaf(s[j][1], cc.z, cc.w);
            s[j][2] = fmaf(s[j][2], cc.x, cc.y);
            s[j][3] = fmaf(s[j][3], cc.z, cc.w);
        }

        // ---- online softmax
        float mt0 = -INFINITY, mt1 = -INFINITY;
#pragma unroll
        for (int j = 0; j < 8; j++) {
            mt0 = fmaxf(mt0, fmaxf(s[j][0], s[j][1]));
            mt1 = fmaxf(mt1, fmaxf(s[j][2], s[j][3]));
        }
        mt0 = fmaxf(mt0, __shfl_xor_sync(0xffffffffu, mt0, 1));
        mt0 = fmaxf(mt0, __shfl_xor_sync(0xffffffffu, mt0, 2));
        mt1 = fmaxf(mt1, __shfl_xor_sync(0xffffffffu, mt1, 1));
        mt1 = fmaxf(mt1, __shfl_xor_sync(0xffffffffu, mt1, 2));

        const float mn0 = fmaxf(m0, mt0);
        const float mn1 = fmaxf(m1, mt1);
        const float mx0 = fmaxf(mn0, -1e30f);
        const float mx1 = fmaxf(mn1, -1e30f);
        const float f0 = __expf(m0 - mx0);
        const float f1 = __expf(m1 - mx1);
        m0 = mn0; m1 = mn1;

        float rs0 = 0.f, rs1 = 0.f;
#pragma unroll
        for (int j = 0; j < 8; j++) {
            s[j][0] = __expf(s[j][0] - mx0);
            s[j][1] = __expf(s[j][1] - mx0);
            s[j][2] = __expf(s[j][2] - mx1);
            s[j][3] = __expf(s[j][3] - mx1);
            rs0 += s[j][0] + s[j][1];
            rs1 += s[j][2] + s[j][3];
        }
        rs0 += __shfl_xor_sync(0xffffffffu, rs0, 1);
        rs0 += __shfl_xor_sync(0xffffffffu, rs0, 2);
        rs1 += __shfl_xor_sync(0xffffffffu, rs1, 1);
        rs1 += __shfl_xor_sync(0xffffffffu, rs1, 2);
        l0 = l0 * f0 + rs0;
        l1 = l1 * f1 + rs1;

#pragma unroll
        for (int j = 0; j < 8; j++) {
            o[j][0] *= f0; o[j][1] *= f0;
            o[j][2] *= f1; o[j][3] *= f1;
        }

        // ---- pack P into bf16 hi/lo A-fragments (registers only)
        unsigned pha[16], pla[16];
#pragma unroll
        for (int j = 0; j < 8; j++) {
            split2(s[j][0], s[j][1], pha[2*j],   pla[2*j]);
            split2(s[j][2], s[j][3], pha[2*j+1], pla[2*j+1]);
        }

        // ---- O += P V, 3-term split
#pragma unroll
        for (int t = 0; t < 4; t++) {
            const unsigned* aph = &pha[4 * t];
            const unsigned* apl = &pla[4 * t];
#pragma unroll
            for (int u = 0; u < 4; u++) {
                unsigned bvh[4], bvl[4];
                const uint32_t va = voff + (uint32_t)(t * 16 * ASTRB + 32 * u);
                ldm4t(bvh, sVh + va);
                ldm4t(bvl, sVl + va);
                mma16816(o[2*u],   aph, bvh[0], bvh[1]);
                mma16816(o[2*u],   aph, bvl[0], bvl[1]);
                mma16816(o[2*u],   apl, bvh[0], bvh[1]);
                mma16816(o[2*u+1], aph, bvh[2], bvh[3]);
                mma16816(o[2*u+1], aph, bvl[2], bvl[3]);
                mma16816(o[2*u+1], apl, bvh[2], bvh[3]);
            }
        }
    }

    // ---- epilogue: normalize, split, store bf16 hi/lo to g_oh/g_ol
    const float inv0 = 1.f / l0;
    const float inv1 = 1.f / l1;
    const int r = qt * AQROWS + wq * 16 + (lane >> 2);
    __nv_bfloat16* Oh = g_oh + (size_t)var * OUTHALF;
    __nv_bfloat16* Ol = g_ol + (size_t)var * OUTHALF;
#pragma unroll
    for (int j = 0; j < 8; j++) {
        const int col = h * DK + 8 * j + (lane & 3) * 2;
        const size_t i0 = ((size_t)bb * NN + r)     * DMODEL + col;
        const size_t i1 = ((size_t)bb * NN + r + 8) * DMODEL + col;
        unsigned hi, lo;
        split2(o[j][0] * inv0, o[j][1] * inv0, hi, lo);
        *(unsigned*)(Oh + i0) = hi;
        *(unsigned*)(Ol + i0) = lo;
        split2(o[j][2] * inv1, o[j][3] * inv1, hi, lo);
        *(unsigned*)(Oh + i1) = hi;
        *(unsigned*)(Ol + i1) = lo;
    }
}

// ===========================================================================
extern "C" void kernel_launch(void* const* d_in, const int* in_sizes, int n_in,
                              void* d_out, int out_size)
{
    const float* regions   = (const float*)d_in[0];
    const float* grids     = (const float*)d_in[1];
    const float* interests = (const float*)d_in[2];
    const int*   maskR     = (const int*)d_in[3];
    const int*   maskG     = (const int*)d_in[4];
    const float* wts       = (const float*)d_in[5];
    const float* Wq   = (const float*)d_in[6];
    const float* bq   = (const float*)d_in[7];
    const float* Wk   = (const float*)d_in[8];
    const float* bk   = (const float*)d_in[9];
    const float* Wv   = (const float*)d_in[10];
    const float* bv   = (const float*)d_in[11];
    const float* Wq12 = (const float*)d_in[12];
    const float* bq12 = (const float*)d_in[13];
    const float* Wo1  = (const float*)d_in[14];
    const float* bo1  = (const float*)d_in[15];
    const float* Wo2  = (const float*)d_in[16];
    const float* bo2  = (const float*)d_in[17];
    float* out = (float*)d_out;

    float *q, *q1, *q2;
    __nv_bfloat16 *ih, *il, *wh, *wl, *kvh, *kvl, *oh, *ol;
    cudaGetSymbolAddress((void**)&q,   g_q);
    cudaGetSymbolAddress((void**)&q1,  g_q1);
    cudaGetSymbolAddress((void**)&q2,  g_q2);
    cudaGetSymbolAddress((void**)&ih,  g_ih);
    cudaGetSymbolAddress((void**)&il,  g_il);
    cudaGetSymbolAddress((void**)&wh,  g_wh);
    cudaGetSymbolAddress((void**)&wl,  g_wl);
    cudaGetSymbolAddress((void**)&kvh, g_kvh);
    cudaGetSymbolAddress((void**)&kvl, g_kvl);
    cudaGetSymbolAddress((void**)&oh,  g_oh);
    cudaGetSymbolAddress((void**)&ol,  g_ol);

    cudaFuncSetAttribute(gemm_bf, cudaFuncAttributeMaxDynamicSharedMemorySize, GSMEM);
    cudaFuncSetAttribute(attn_mma, cudaFuncAttributeMaxDynamicSharedMemorySize, ASMEMB);

    // ---- prep: fp32 -> bf16 hi/lo (3 inputs + 6 weights) + key compaction
    Prep pp;
    const float* srcs[9] = {interests, regions, grids, Wq, Wq12, Wk, Wv, Wo1, Wo2};
    for (int z = 0; z < 9; z++) {
        pp.src[z] = srcs[z];
        if (z < 3) {
            pp.dh[z] = ih + (size_t)z * INSEG;
            pp.dl[z] = il + (size_t)z * INSEG;
            pp.n4[z] = INSEG / 4;
        } else {
            pp.dh[z] = wh + (size_t)(z - 3) * WSEG;
            pp.dl[z] = wl + (size_t)(z - 3) * WSEG;
            pp.n4[z] = WSEG / 4;
        }
    }
    prep_k<<<dim3(INSEG / 4 / 256, 9), 256>>>(pp);
    compact_k<<<4, 256>>>(maskR, maskG, wts);

    const __nv_bfloat16 *Ih = ih, *Rh = ih + INSEG, *Gh = ih + 2 * (size_t)INSEG;
    const __nv_bfloat16 *Il = il, *Rl = il + INSEG, *Gl = il + 2 * (size_t)INSEG;
    const __nv_bfloat16 *Wqh = wh, *Wq12h = wh + WSEG, *Wkh = wh + 2*(size_t)WSEG,
                        *Wvh = wh + 3*(size_t)WSEG, *Wo1h = wh + 4*(size_t)WSEG,
                        *Wo2h = wh + 5*(size_t)WSEG;
    const __nv_bfloat16 *Wql = wl, *Wq12l = wl + WSEG, *Wkl = wl + 2*(size_t)WSEG,
                        *Wvl = wl + 3*(size_t)WSEG, *Wo1l = wl + 4*(size_t)WSEG,
                        *Wo2l = wl + 5*(size_t)WSEG;

    // ---- 7 projections, one launch
    GBFpack pj;
    auto set = [&](int z, const __nv_bfloat16* xh, const __nv_bfloat16* xl,
                   const __nv_bfloat16* wwh, const __nv_bfloat16* wwl,
                   const float* bi, float* D, __nv_bfloat16* Dh, __nv_bfloat16* Dl,
                   int mode) {
        pj.g[z].Xh = xh; pj.g[z].Xl = xl; pj.g[z].Wh = wwh; pj.g[z].Wl = wwl;
        pj.g[z].Bi = bi; pj.g[z].D = D; pj.g[z].Dh = Dh; pj.g[z].Dl = Dl;
        pj.g[z].mode = mode;
    };
    set(0, Ih, Il, Wqh,   Wql,   bq,   q,  nullptr, nullptr, 0);
    set(1, Rh, Rl, Wq12h, Wq12l, bq12, q1, nullptr, nullptr, 0);
    set(2, Gh, Gl, Wq12h, Wq12l, bq12, q2, nullptr, nullptr, 0);
    set(3, Rh, Rl, Wkh,   Wkl,   bk,   nullptr, kvh + 0*(size_t)HEADELEMS, kvl + 0*(size_t)HEADELEMS, 1);
    set(4, Gh, Gl, Wkh,   Wkl,   bk,   nullptr, kvh + 1*(size_t)HEADELEMS, kvl + 1*(size_t)HEADELEMS, 1);
    set(5, Rh, Rl, Wvh,   Wvl,   bv,   nullptr, kvh + 2*(size_t)HEADELEMS, kvl + 2*(size_t)HEADELEMS, 1);
    set(6, Gh, Gl, Wvh,   Wvl,   bv,   nullptr, kvh + 3*(size_t)HEADELEMS, kvl + 3*(size_t)HEADELEMS, 1);
    gemm_bf<<<dim3(DMODEL / 128, MTOT / 128, 7), 256, GSMEM>>>(pj);

    // ---- attention (both variants), compacted keys
    attn_mma<<<dim3(NN / AQROWS, BB * HH, 2), 256, ASMEMB>>>();

    // ---- 2 output projections, one launch
    GBFpack po;
    auto seto = [&](int z, int var, const __nv_bfloat16* wwh, const __nv_bfloat16* wwl,
                    const float* bi, float* D) {
        po.g[z].Xh = oh + (size_t)var * OUTHALF;
        po.g[z].Xl = ol + (size_t)var * OUTHALF;
        po.g[z].Wh = wwh; po.g[z].Wl = wwl; po.g[z].Bi = bi;
        po.g[z].D = D; po.g[z].Dh = nullptr; po.g[z].Dl = nullptr;
        po.g[z].mode = 2;
    };
    seto(0, 0, Wo1h, Wo1l, bo1, out);
    seto(1, 1, Wo2h, Wo2l, bo2, out + OUTHALF);
    for (int z = 2; z < 7; z++) po.g[z] = po.g[0];
    gemm_bf<<<dim3(DMODEL / 128, MTOT / 128, 2), 256, GSMEM>>>(po);
}

// round 11
// speedup vs baseline: 8.6239x; 1.3410x over previous
#include <cuda_runtime.h>
#include <cuda_fp16.h>
#include <math.h>
#include <stdint.h>

#define BB 2
#define NN 2048
#define DMODEL 512
#define HH 8
#define DK 64
#define MTOT (BB*NN)                 // 4096
#define HEADELEMS (BB*HH*NN*DK)      // 2097152
#define OUTHALF (MTOT*DMODEL)        // 2097152
#define INSEG (MTOT*DMODEL)          // 2097152 (one input matrix)
#define WSEG (DMODEL*DMODEL)         // 262144  (one weight matrix)

// ---------------- scratch (__device__ globals; allocation-free rule) --------
__device__ float g_q [HEADELEMS];
__device__ float g_q1[HEADELEMS];
__device__ float g_q2[HEADELEMS];
__device__ __half g_ih[3*INSEG];      // inputs fp16 (A-side: single precision term)
__device__ __half g_wh[6*WSEG];       // weights hi (Wq, Wq12, Wk, Wv, Wo1, Wo2)
__device__ __half g_wl[6*WSEG];       // weights lo
__device__ __half g_kvh[4*HEADELEMS]; // K1,K2,V1,V2 hi (B-side: split)
__device__ __half g_kvl[4*HEADELEMS]; // K1,K2,V1,V2 lo
__device__ __half g_oh[2*OUTHALF];    // O1,O2 fp16 (A-side of out-proj)
// key compaction per (var, batch): indices, coefficients, padded counts
__device__ int    g_cidx[4*NN];
__device__ float2 g_ccf [4*NN];
__device__ int    g_pcnt[4];

__device__ __forceinline__ uint32_t smem_u32(const void* p) {
    uint32_t a;
    asm("{ .reg .u64 t; cvta.to.shared.u64 t, %1; cvt.u32.u64 %0, t; }"
        : "=r"(a) : "l"(p));
    return a;
}

// ---- family-common PTX primitives (sm_80+: valid on .target sm_103) --------
__device__ __forceinline__ void ldm4(unsigned r[4], uint32_t addr) {
    asm volatile("ldmatrix.sync.aligned.m8n8.x4.shared.b16 {%0,%1,%2,%3}, [%4];"
        : "=r"(r[0]), "=r"(r[1]), "=r"(r[2]), "=r"(r[3]) : "r"(addr));
}
__device__ __forceinline__ void ldm4t(unsigned r[4], uint32_t addr) {
    asm volatile("ldmatrix.sync.aligned.m8n8.x4.trans.shared.b16 {%0,%1,%2,%3}, [%4];"
        : "=r"(r[0]), "=r"(r[1]), "=r"(r[2]), "=r"(r[3]) : "r"(addr));
}
__device__ __forceinline__ void mma16816(float c[4], const unsigned a[4],
                                         const unsigned b0, const unsigned b1) {
    asm volatile(
        "mma.sync.aligned.m16n8k16.row.col.f32.f16.f16.f32 "
        "{%0,%1,%2,%3}, {%4,%5,%6,%7}, {%8,%9}, {%0,%1,%2,%3};"
        : "+f"(c[0]), "+f"(c[1]), "+f"(c[2]), "+f"(c[3])
        : "r"(a[0]), "r"(a[1]), "r"(a[2]), "r"(a[3]), "r"(b0), "r"(b1));
}
#define CP_ASYNC16(dst, src) \
    asm volatile("cp.async.cg.shared.global [%0], [%1], 16;" \
        :: "r"(dst), "l"(src) : "memory")
#define CP_COMMIT() asm volatile("cp.async.commit_group;" ::: "memory")
#define CP_WAIT0()  asm volatile("cp.async.wait_group 0;" ::: "memory")

// pack 2 fp32 -> packed half2 (round, no residual)
__device__ __forceinline__ unsigned pack2h(float v0, float v1) {
    __half2 h = __floats2half2_rn(v0, v1);
    return *reinterpret_cast<unsigned*>(&h);
}
// split 2 fp32 -> packed half2 hi + residual lo
__device__ __forceinline__ void split2h(float v0, float v1, unsigned& hi, unsigned& lo) {
    __half2 h = __floats2half2_rn(v0, v1);
    float2 hf = __half22float2(h);
    __half2 l = __floats2half2_rn(v0 - hf.x, v1 - hf.y);
    hi = *reinterpret_cast<unsigned*>(&h);
    lo = *reinterpret_cast<unsigned*>(&l);
}
// 8 fp32 -> 8 fp16 (no residual)
__device__ __forceinline__ uint4 conv8h(float4 a, float4 b) {
    return make_uint4(pack2h(a.x, a.y), pack2h(a.z, a.w),
                      pack2h(b.x, b.y), pack2h(b.z, b.w));
}

// ===========================================================================
// Prep: inputs -> fp16 (hi only); weights -> fp16 hi + lo
// ===========================================================================
struct Prep {
    const float* src[9];
    __half* dh[9];
    __half* dl[9];      // null for inputs
    int n4[9];
};

__global__ __launch_bounds__(256)
void prep_k(Prep pp)
{
    const int z  = blockIdx.y;
    const int i4 = blockIdx.x * 256 + threadIdx.x;
    if (i4 >= pp.n4[z]) return;
    float4 v = ((const float4*)pp.src[z])[i4];
    if (pp.dl[z]) {
        unsigned h0, l0, h1, l1;
        split2h(v.x, v.y, h0, l0);
        split2h(v.z, v.w, h1, l1);
        ((uint2*)pp.dh[z])[i4] = make_uint2(h0, h1);
        ((uint2*)pp.dl[z])[i4] = make_uint2(l0, l1);
    } else {
        ((uint2*)pp.dh[z])[i4] = make_uint2(pack2h(v.x, v.y), pack2h(v.z, v.w));
    }
}

// ===========================================================================
// Compact: per (var, batch), deterministic block-scan of the key mask ->
// ascending index list of unmasked keys + (mul, add) coefficients, padded
// to a multiple of 64 with fully-masked entries. grid = 4 blocks.
// ===========================================================================
__global__ __launch_bounds__(256)
void compact_k(const int* __restrict__ mR, const int* __restrict__ mG,
               const float* __restrict__ wts)
{
    const int cvi = blockIdx.x;          // var*2 + bb
    const int var = cvi >> 1, bb = cvi & 1;
    const int* msk = (var ? mG : mR) + bb * NN;
    const float* w = wts + bb * NN;
    __shared__ int sc[256];

    const int t = threadIdx.x;
    int keep[8];
    int cnt = 0;
#pragma unroll
    for (int j = 0; j < 8; j++) {
        const int key = t * 8 + j;
        if (msk[key] == 0) keep[cnt++] = key;
    }
    sc[t] = cnt;
    __syncthreads();
    for (int d = 1; d < 256; d <<= 1) {
        int v = (t >= d) ? sc[t - d] : 0;
        __syncthreads();
        sc[t] += v;
        __syncthreads();
    }
    const int off = sc[t] - cnt;
    const int total = sc[255];
    for (int j = 0; j < cnt; j++) {
        const int key = keep[j];
        g_cidx[cvi * NN + off + j] = key;
        g_ccf [cvi * NN + off + j] = make_float2(0.125f * w[key], 0.f);
    }
    const int padded = (total + 63) & ~63;
    for (int i = total + t; i < padded; i += 256) {
        g_cidx[cvi * NN + i] = 0;
        g_ccf [cvi * NN + i] = make_float2(0.f, -1e38f);
    }
    if (t == 0) g_pcnt[cvi] = padded;
}

// ===========================================================================
// cp.async double-buffered HMMA GEMM, fp16 2-term: C = X16·Wh + X16·Wl.
// Block tile 128x128, 8 warps (2Mx4N), warp tile 64x32, K-chunk 32, 2 stages.
// Stage holds 3 matrices: Ah, Bh, Bl.
// ===========================================================================
#define GRSTR 80
#define GMAT  (128 * GRSTR)            // 10240 per matrix
#define GSTG  (3 * GMAT)               // 30720 per stage
#define GSMEM (2 * GSTG)               // 61440

struct GBF {
    const __half *Xh, *Wh, *Wl;
    const float* Bi;
    float* D;
    __half *Dh, *Dl;
    int mode;                           // 0 HEADS fp32, 1 KV fp16 hi/lo, 2 ROW fp32
};
struct GBFpack { GBF g[7]; };

__global__ __launch_bounds__(256, 2)
void gemm_bf(GBFpack gp)
{
    extern __shared__ __align__(16) char smc[];
    const uint32_t sb = smem_u32(smc);

    const GBF gb = gp.g[blockIdx.z];
    const int m0 = blockIdx.y * 128;
    const int n0 = blockIdx.x * 128;

    const int tid  = threadIdx.x;
    const int wid  = tid >> 5;
    const int lane = tid & 31;
    const int warpM = wid >> 2;
    const int warpN = wid & 3;

    const int arow  = (lane & 7) + ((lane >> 3) & 1) * 8;
    const int akoff = ((lane >> 4) & 1) * 16;
    const int brow  = (lane & 7) + ((lane >> 4) & 1) * 8;
    const int bkoff = ((lane >> 3) & 1) * 16;

    float c[4][4][4];
#pragma unroll
    for (int im = 0; im < 4; im++)
#pragma unroll
        for (int jn = 0; jn < 4; jn++)
#pragma unroll
            for (int e = 0; e < 4; e++) c[im][jn][e] = 0.f;

    auto issue = [&](int s, int kc) {
#pragma unroll
        for (int p = 0; p < 6; p++) {
            const int i = tid + p * 256;        // 0..1535
            const int t = i >> 9;               // 0 Xh, 1 Wh, 2 Wl
            const int r = (i >> 2) & 127;
            const int cc = i & 3;
            const __half* src;
            if      (t == 0) src = gb.Xh + (size_t)(m0 + r) * DMODEL + kc * 32 + cc * 8;
            else if (t == 1) src = gb.Wh + (size_t)(n0 + r) * DMODEL + kc * 32 + cc * 8;
            else             src = gb.Wl + (size_t)(n0 + r) * DMODEL + kc * 32 + cc * 8;
            CP_ASYNC16(sb + s * GSTG + t * GMAT + r * GRSTR + cc * 16, src);
        }
    };

    issue(0, 0);
    CP_COMMIT();

#pragma unroll 1
    for (int kc = 0; kc < 16; kc++) {
        const int b = kc & 1;
        CP_WAIT0();
        __syncthreads();
        if (kc < 15) { issue(b ^ 1, kc + 1); CP_COMMIT(); }

        const uint32_t sAh = sb + b * GSTG;
        const uint32_t sBh = sAh + GMAT;
        const uint32_t sBl = sAh + 2 * GMAT;

#pragma unroll
        for (int ks = 0; ks < 2; ks++) {
            unsigned bh[2][4], bl[2][4];
#pragma unroll
            for (int jp = 0; jp < 2; jp++) {
                const uint32_t bo = (uint32_t)((warpN * 32 + jp * 16 + brow) * GRSTR
                                               + ks * 32 + bkoff);
                ldm4(bh[jp], sBh + bo);
                ldm4(bl[jp], sBl + bo);
            }
#pragma unroll
            for (int im = 0; im < 4; im++) {
                const uint32_t ao = (uint32_t)((warpM * 64 + im * 16 + arow) * GRSTR
                                               + ks * 32 + akoff);
                unsigned ah[4];
                ldm4(ah, sAh + ao);
#pragma unroll
                for (int jn = 0; jn < 4; jn++) {
                    const int jp = jn >> 1, jo = (jn & 1) * 2;
                    mma16816(c[im][jn], ah, bh[jp][jo], bh[jp][jo + 1]);
                    mma16816(c[im][jn], ah, bl[jp][jo], bl[jp][jo + 1]);
                }
            }
        }
    }

    const int rbase = m0 + warpM * 64 + (lane >> 2);
    const int cbase = n0 + warpN * 32 + (lane & 3) * 2;
#pragma unroll
    for (int im = 0; im < 4; im++) {
#pragma unroll
        for (int jn = 0; jn < 4; jn++) {
            const int col = cbase + jn * 8;
            const float b0 = gb.Bi[col], b1 = gb.Bi[col + 1];
#pragma unroll
            for (int half = 0; half < 2; half++) {
                const int m  = rbase + im * 16 + half * 8;
                const float v0 = c[im][jn][half * 2]     + b0;
                const float v1 = c[im][jn][half * 2 + 1] + b1;
                if (gb.mode == 2) {
                    *(float2*)(gb.D + (size_t)m * DMODEL + col) = make_float2(v0, v1);
                } else {
                    const int bb = m >> 11;
                    const int n  = m & 2047;
                    const int h  = col >> 6, d = col & 63;
                    const size_t idx = (((size_t)(bb * HH + h)) * NN + n) * DK + d;
                    if (gb.mode == 0) {
                        *(float2*)(gb.D + idx) = make_float2(v0, v1);
                    } else {
                        unsigned hi, lo; split2h(v0, v1, hi, lo);
                        *(unsigned*)(gb.Dh + idx) = hi;
                        *(unsigned*)(gb.Dl + idx) = lo;
                    }
                }
            }
        }
    }
}

// ===========================================================================
// cp.async double-buffered HMMA FlashAttention over COMPACTED keys,
// fp16 2-term: S = Q16·Kh + Q16·Kl ; O += P16·Vh + P16·Vl.
// Q/P fragments single-precision-term (registers only).
// ===========================================================================
#define AQROWS 128
#define ASTRB 144
#define KMAT (64*ASTRB)              // 9216
#define KVS (4*KMAT)                 // 36864 per stage (Kh,Kl,Vh,Vl)
#define ACF (2*KVS)                  // 73728
#define ASMEMB (ACF + 2*512)         // 74752

__global__ __launch_bounds__(256, 2)
void attn_mma()
{
    extern __shared__ __align__(16) char smn[];
    const uint32_t sb = smem_u32(smn);

    const int var = blockIdx.z;
    const int bh  = blockIdx.y;
    const int bb  = bh >> 3;
    const int h   = bh & 7;
    const int qt  = blockIdx.x;
    const int cvi = var * 2 + bb;

    const float* Q  = g_q + (size_t)bh * NN * DK + (size_t)qt * AQROWS * DK;
    const float* Qx = (var ? g_q1 : g_q2) + (size_t)bh * NN * DK + (size_t)qt * AQROWS * DK;
    const int*    cidx = g_cidx + cvi * NN;
    const float2* ccf  = g_ccf  + cvi * NN;
    const int ntk = g_pcnt[cvi] >> 6;

    const int tid  = threadIdx.x;
    const int wq   = tid >> 5;
    const int lane = tid & 31;
    const int lr   = lane & 7;
    const int g    = lane >> 3;

    const uint32_t qoff = (uint32_t)((wq * 16 + lr + (g & 1) * 8) * ASTRB + (g >> 1) * 16);
    const uint32_t koff = (uint32_t)((lr + (g >> 1) * 8) * ASTRB + (g & 1) * 16);
    const uint32_t voff = (uint32_t)((lr + (g & 1) * 8) * ASTRB + (g >> 1) * 16);

    auto issueKV = [&](int s, int kt) {
        const int r0l = tid >> 3;
        const int gr0 = cidx[kt * 64 + r0l];
        const int gr1 = cidx[kt * 64 + r0l + 32];
#pragma unroll
        for (int p = 0; p < 8; p++) {
            const int i = tid + p * 256;
            const int t = i >> 9;               // 0 Kh,1 Kl,2 Vh,3 Vl
            const int rl = r0l + 32 * (p & 1);
            const int gr = (p & 1) ? gr1 : gr0;
            const int cc = tid & 7;
            const int seg = (t >> 1) ? (2 + var) : var;
            const __half* base = (t & 1) ? g_kvl : g_kvh;
            const __half* src = base + (size_t)seg * HEADELEMS
                + (size_t)bh * NN * DK + (size_t)gr * DK + cc * 8;
            CP_ASYNC16(sb + s * KVS + t * KMAT + rl * ASTRB + cc * 16, src);
        }
    };

    // ---- stage Q (fp32 fused add -> fp16) into the stage-0 area
#pragma unroll
    for (int p = 0; p < 4; p++) {
        const int s   = tid + p * 256;
        const int row = s >> 3;
        const int c8  = (s & 7) * 8;
        float4 a0 = *(const float4*)(Q  + (size_t)row * DK + c8);
        float4 a1 = *(const float4*)(Q  + (size_t)row * DK + c8 + 4);
        float4 b0 = *(const float4*)(Qx + (size_t)row * DK + c8);
        float4 b1 = *(const float4*)(Qx + (size_t)row * DK + c8 + 4);
        a0.x += b0.x; a0.y += b0.y; a0.z += b0.z; a0.w += b0.w;
        a1.x += b1.x; a1.y += b1.y; a1.z += b1.z; a1.w += b1.w;
        *(uint4*)(smn + (uint32_t)(row * ASTRB + c8 * 2)) = conv8h(a0, a1);
    }
    __syncthreads();

    // ---- hoist Q fragments into registers (loop-invariant)
    unsigned aqh[4][4];
#pragma unroll
    for (int t = 0; t < 4; t++)
        ldm4(aqh[t], sb + qoff + 32 * t);
    __syncthreads();   // Q staging consumed; stage 0 may be overwritten

    // ---- prologue
    issueKV(0, 0);
    CP_COMMIT();
    if (tid < 64)
        *(float2*)(smn + ACF + tid * 8) = ccf[tid];

    float o[8][4];
#pragma unroll
    for (int j = 0; j < 8; j++)
#pragma unroll
        for (int e = 0; e < 4; e++) o[j][e] = 0.f;
    float m0 = -INFINITY, m1 = -INFINITY, l0 = 0.f, l1 = 0.f;

#pragma unroll 1
    for (int kt = 0; kt < ntk; kt++) {
        const int b = kt & 1;
        CP_WAIT0();
        __syncthreads();
        if (kt < ntk - 1) {
            issueKV(b ^ 1, kt + 1);
            CP_COMMIT();
            if (tid < 64)
                *(float2*)(smn + ACF + (b ^ 1) * 512 + tid * 8) = ccf[(kt + 1) * 64 + tid];
        }

        const uint32_t sKh = sb + b * KVS;
        const uint32_t sKl = sKh + KMAT;
        const uint32_t sVh = sKh + 2 * KMAT;
        const uint32_t sVl = sKh + 3 * KMAT;

        // ---- S = Q16 K^T (2-term on K)
        float s[8][4];
#pragma unroll
        for (int j = 0; j < 8; j++)
#pragma unroll
            for (int e = 0; e < 4; e++) s[j][e] = 0.f;

#pragma unroll
        for (int u = 0; u < 4; u++) {
#pragma unroll
            for (int t = 0; t < 4; t++) {
                unsigned bkh[4], bkl[4];
                const uint32_t ka = koff + (uint32_t)(u * 16 * ASTRB + 32 * t);
                ldm4(bkh, sKh + ka);
                ldm4(bkl, sKl + ka);
                mma16816(s[2*u],   aqh[t], bkh[0], bkh[1]);
                mma16816(s[2*u],   aqh[t], bkl[0], bkl[1]);
                mma16816(s[2*u+1], aqh[t], bkh[2], bkh[3]);
                mma16816(s[2*u+1], aqh[t], bkl[2], bkl[3]);
            }
        }

        // ---- fused scale*weight (+mask via add for padding)
#pragma unroll
        for (int j = 0; j < 8; j++) {
            float4 cc = *(const float4*)(smn + ACF + b * 512 + (8 * j + (lane & 3) * 2) * 8);
            s[j][0] = fmaf(s[j][0], cc.x, cc.y);
            s[j][1] = fmaf(s[j][1], cc.z, cc.w);
            s[j][2] = fmaf(s[j][2], cc.x, cc.y);
            s[j][3] = fmaf(s[j][3], cc.z, cc.w);
        }

        // ---- online softmax
        float mt0 = -INFINITY, mt1 = -INFINITY;
#pragma unroll
        for (int j = 0; j < 8; j++) {
            mt0 = fmaxf(mt0, fmaxf(s[j][0], s[j][1]));
            mt1 = fmaxf(mt1, fmaxf(s[j][2], s[j][3]));
        }
        mt0 = fmaxf(mt0, __shfl_xor_sync(0xffffffffu, mt0, 1));
        mt0 = fmaxf(mt0, __shfl_xor_sync(0xffffffffu, mt0, 2));
        mt1 = fmaxf(mt1, __shfl_xor_sync(0xffffffffu, mt1, 1));
        mt1 = fmaxf(mt1, __shfl_xor_sync(0xffffffffu, mt1, 2));

        const float mn0 = fmaxf(m0, mt0);
        const float mn1 = fmaxf(m1, mt1);
        const float mx0 = fmaxf(mn0, -1e30f);
        const float mx1 = fmaxf(mn1, -1e30f);
        const float f0 = __expf(m0 - mx0);
        const float f1 = __expf(m1 - mx1);
        m0 = mn0; m1 = mn1;

        float rs0 = 0.f, rs1 = 0.f;
#pragma unroll
        for (int j = 0; j < 8; j++) {
            s[j][0] = __expf(s[j][0] - mx0);
            s[j][1] = __expf(s[j][1] - mx0);
            s[j][2] = __expf(s[j][2] - mx1);
            s[j][3] = __expf(s[j][3] - mx1);
            rs0 += s[j][0] + s[j][1];
            rs1 += s[j][2] + s[j][3];
        }
        rs0 += __shfl_xor_sync(0xffffffffu, rs0, 1);
        rs0 += __shfl_xor_sync(0xffffffffu, rs0, 2);
        rs1 += __shfl_xor_sync(0xffffffffu, rs1, 1);
        rs1 += __shfl_xor_sync(0xffffffffu, rs1, 2);
        l0 = l0 * f0 + rs0;
        l1 = l1 * f1 + rs1;

#pragma unroll
        for (int j = 0; j < 8; j++) {
            o[j][0] *= f0; o[j][1] *= f0;
            o[j][2] *= f1; o[j][3] *= f1;
        }

        // ---- pack P into fp16 A-fragments (registers only, single term)
        unsigned pha[16];
#pragma unroll
        for (int j = 0; j < 8; j++) {
            pha[2*j]   = pack2h(s[j][0], s[j][1]);
            pha[2*j+1] = pack2h(s[j][2], s[j][3]);
        }

        // ---- O += P16 V (2-term on V)
#pragma unroll
        for (int t = 0; t < 4; t++) {
            const unsigned* aph = &pha[4 * t];
#pragma unroll
            for (int u = 0; u < 4; u++) {
                unsigned bvh[4], bvl[4];
                const uint32_t va = voff + (uint32_t)(t * 16 * ASTRB + 32 * u);
                ldm4t(bvh, sVh + va);
                ldm4t(bvl, sVl + va);
                mma16816(o[2*u],   aph, bvh[0], bvh[1]);
                mma16816(o[2*u],   aph, bvl[0], bvl[1]);
                mma16816(o[2*u+1], aph, bvh[2], bvh[3]);
                mma16816(o[2*u+1], aph, bvl[2], bvl[3]);
            }
        }
    }

    // ---- epilogue: normalize, store fp16 to g_oh
    const float inv0 = 1.f / l0;
    const float inv1 = 1.f / l1;
    const int r = qt * AQROWS + wq * 16 + (lane >> 2);
    __half* Oh = g_oh + (size_t)var * OUTHALF;
#pragma unroll
    for (int j = 0; j < 8; j++) {
        const int col = h * DK + 8 * j + (lane & 3) * 2;
        const size_t i0 = ((size_t)bb * NN + r)     * DMODEL + col;
        const size_t i1 = ((size_t)bb * NN + r + 8) * DMODEL + col;
        *(unsigned*)(Oh + i0) = pack2h(o[j][0] * inv0, o[j][1] * inv0);
        *(unsigned*)(Oh + i1) = pack2h(o[j][2] * inv1, o[j][3] * inv1);
    }
}

// ===========================================================================
extern "C" void kernel_launch(void* const* d_in, const int* in_sizes, int n_in,
                              void* d_out, int out_size)
{
    const float* regions   = (const float*)d_in[0];
    const float* grids     = (const float*)d_in[1];
    const float* interests = (const float*)d_in[2];
    const int*   maskR     = (const int*)d_in[3];
    const int*   maskG     = (const int*)d_in[4];
    const float* wts       = (const float*)d_in[5];
    const float* Wq   = (const float*)d_in[6];
    const float* bq   = (const float*)d_in[7];
    const float* Wk   = (const float*)d_in[8];
    const float* bk   = (const float*)d_in[9];
    const float* Wv   = (const float*)d_in[10];
    const float* bv   = (const float*)d_in[11];
    const float* Wq12 = (const float*)d_in[12];
    const float* bq12 = (const float*)d_in[13];
    const float* Wo1  = (const float*)d_in[14];
    const float* bo1  = (const float*)d_in[15];
    const float* Wo2  = (const float*)d_in[16];
    const float* bo2  = (const float*)d_in[17];
    float* out = (float*)d_out;

    float *q, *q1, *q2;
    __half *ih, *wh, *wl, *kvh, *kvl, *oh;
    cudaGetSymbolAddress((void**)&q,   g_q);
    cudaGetSymbolAddress((void**)&q1,  g_q1);
    cudaGetSymbolAddress((void**)&q2,  g_q2);
    cudaGetSymbolAddress((void**)&ih,  g_ih);
    cudaGetSymbolAddress((void**)&wh,  g_wh);
    cudaGetSymbolAddress((void**)&wl,  g_wl);
    cudaGetSymbolAddress((void**)&kvh, g_kvh);
    cudaGetSymbolAddress((void**)&kvl, g_kvl);
    cudaGetSymbolAddress((void**)&oh,  g_oh);

    cudaFuncSetAttribute(gemm_bf, cudaFuncAttributeMaxDynamicSharedMemorySize, GSMEM);
    cudaFuncSetAttribute(attn_mma, cudaFuncAttributeMaxDynamicSharedMemorySize, ASMEMB);

    // ---- prep: inputs fp16 hi; weights fp16 hi+lo; key compaction
    Prep pp;
    const float* srcs[9] = {interests, regions, grids, Wq, Wq12, Wk, Wv, Wo1, Wo2};
    for (int z = 0; z < 9; z++) {
        pp.src[z] = srcs[z];
        if (z < 3) {
            pp.dh[z] = ih + (size_t)z * INSEG;
            pp.dl[z] = nullptr;
            pp.n4[z] = INSEG / 4;
        } else {
            pp.dh[z] = wh + (size_t)(z - 3) * WSEG;
            pp.dl[z] = wl + (size_t)(z - 3) * WSEG;
            pp.n4[z] = WSEG / 4;
        }
    }
    prep_k<<<dim3(INSEG / 4 / 256, 9), 256>>>(pp);
    compact_k<<<4, 256>>>(maskR, maskG, wts);

    const __half *Ih = ih, *Rh = ih + INSEG, *Gh = ih + 2 * (size_t)INSEG;
    const __half *Wqh = wh, *Wq12h = wh + WSEG, *Wkh = wh + 2*(size_t)WSEG,
                 *Wvh = wh + 3*(size_t)WSEG, *Wo1h = wh + 4*(size_t)WSEG,
                 *Wo2h = wh + 5*(size_t)WSEG;
    const __half *Wql = wl, *Wq12l = wl + WSEG, *Wkl = wl + 2*(size_t)WSEG,
                 *Wvl = wl + 3*(size_t)WSEG, *Wo1l = wl + 4*(size_t)WSEG,
                 *Wo2l = wl + 5*(size_t)WSEG;

    // ---- 7 projections, one launch
    GBFpack pj;
    auto set = [&](int z, const __half* xh, const __half* wwh, const __half* wwl,
                   const float* bi, float* D, __half* Dh, __half* Dl, int mode) {
        pj.g[z].Xh = xh; pj.g[z].Wh = wwh; pj.g[z].Wl = wwl;
        pj.g[z].Bi = bi; pj.g[z].D = D; pj.g[z].Dh = Dh; pj.g[z].Dl = Dl;
        pj.g[z].mode = mode;
    };
    set(0, Ih, Wqh,   Wql,   bq,   q,  nullptr, nullptr, 0);
    set(1, Rh, Wq12h, Wq12l, bq12, q1, nullptr, nullptr, 0);
    set(2, Gh, Wq12h, Wq12l, bq12, q2, nullptr, nullptr, 0);
    set(3, Rh, Wkh,   Wkl,   bk,   nullptr, kvh + 0*(size_t)HEADELEMS, kvl + 0*(size_t)HEADELEMS, 1);
    set(4, Gh, Wkh,   Wkl,   bk,   nullptr, kvh + 1*(size_t)HEADELEMS, kvl + 1*(size_t)HEADELEMS, 1);
    set(5, Rh, Wvh,   Wvl,   bv,   nullptr, kvh + 2*(size_t)HEADELEMS, kvl + 2*(size_t)HEADELEMS, 1);
    set(6, Gh, Wvh,   Wvl,   bv,   nullptr, kvh + 3*(size_t)HEADELEMS, kvl + 3*(size_t)HEADELEMS, 1);
    gemm_bf<<<dim3(DMODEL / 128, MTOT / 128, 7), 256, GSMEM>>>(pj);

    // ---- attention (both variants), compacted keys
    attn_mma<<<dim3(NN / AQROWS, BB * HH, 2), 256, ASMEMB>>>();

    // ---- 2 output projections, one launch
    GBFpack po;
    auto seto = [&](int z, int var, const __half* wwh, const __half* wwl,
                    const float* bi, float* D) {
        po.g[z].Xh = oh + (size_t)var * OUTHALF;
        po.g[z].Wh = wwh; po.g[z].Wl = wwl; po.g[z].Bi = bi;
        po.g[z].D = D; po.g[z].Dh = nullptr; po.g[z].Dl = nullptr;
        po.g[z].mode = 2;
    };
    seto(0, 0, Wo1h, Wo1l, bo1, out);
    seto(1, 1, Wo2h, Wo2l, bo2, out + OUTHALF);
    for (int z = 2; z < 7; z++) po.g[z] = po.g[0];
    gemm_bf<<<dim3(DMODEL / 128, MTOT / 128, 2), 256, GSMEM>>>(po);
}

// round 13
// speedup vs baseline: 8.9645x; 1.0395x over previous
#include <cuda_runtime.h>
#include <cuda_fp16.h>
#include <math.h>
#include <stdint.h>

#define BB 2
#define NN 2048
#define DMODEL 512
#define HH 8
#define DK 64
#define MTOT (BB*NN)                 // 4096
#define HEADELEMS (BB*HH*NN*DK)      // 2097152
#define OUTHALF (MTOT*DMODEL)        // 2097152
#define INSEG (MTOT*DMODEL)          // 2097152 (one input matrix)
#define WSEG (DMODEL*DMODEL)         // 262144  (one weight matrix)

// ---------------- scratch (__device__ globals; allocation-free rule) --------
__device__ float g_q [HEADELEMS];
__device__ float g_q1[HEADELEMS];
__device__ float g_q2[HEADELEMS];
__device__ __half g_ih[3*INSEG];      // inputs fp16
__device__ __half g_wh[6*WSEG];       // weights hi (Wq, Wq12, Wk, Wv, Wo1, Wo2)
__device__ __half g_wl[6*WSEG];       // weights lo (used for Wo1, Wo2 only)
__device__ __half g_kvh[4*HEADELEMS]; // K1,K2,V1,V2 hi (B-side: split)
__device__ __half g_kvl[4*HEADELEMS]; // K1,K2,V1,V2 lo
__device__ __half g_oh[2*OUTHALF];    // O1,O2 fp16 (A-side of out-proj)
// key compaction per (var, batch): indices, coefficients, padded counts
__device__ int    g_cidx[4*NN];
__device__ float2 g_ccf [4*NN];
__device__ int    g_pcnt[4];

__device__ __forceinline__ uint32_t smem_u32(const void* p) {
    uint32_t a;
    asm("{ .reg .u64 t; cvta.to.shared.u64 t, %1; cvt.u32.u64 %0, t; }"
        : "=r"(a) : "l"(p));
    return a;
}

// ---- family-common PTX primitives (sm_80+: valid on .target sm_103) --------
__device__ __forceinline__ void ldm4(unsigned r[4], uint32_t addr) {
    asm volatile("ldmatrix.sync.aligned.m8n8.x4.shared.b16 {%0,%1,%2,%3}, [%4];"
        : "=r"(r[0]), "=r"(r[1]), "=r"(r[2]), "=r"(r[3]) : "r"(addr));
}
__device__ __forceinline__ void ldm4t(unsigned r[4], uint32_t addr) {
    asm volatile("ldmatrix.sync.aligned.m8n8.x4.trans.shared.b16 {%0,%1,%2,%3}, [%4];"
        : "=r"(r[0]), "=r"(r[1]), "=r"(r[2]), "=r"(r[3]) : "r"(addr));
}
__device__ __forceinline__ void mma16816(float c[4], const unsigned a[4],
                                         const unsigned b0, const unsigned b1) {
    asm volatile(
        "mma.sync.aligned.m16n8k16.row.col.f32.f16.f16.f32 "
        "{%0,%1,%2,%3}, {%4,%5,%6,%7}, {%8,%9}, {%0,%1,%2,%3};"
        : "+f"(c[0]), "+f"(c[1]), "+f"(c[2]), "+f"(c[3])
        : "r"(a[0]), "r"(a[1]), "r"(a[2]), "r"(a[3]), "r"(b0), "r"(b1));
}
#define CP_ASYNC16(dst, src) \
    asm volatile("cp.async.cg.shared.global [%0], [%1], 16;" \
        :: "r"(dst), "l"(src) : "memory")
#define CP_COMMIT() asm volatile("cp.async.commit_group;" ::: "memory")
#define CP_WAIT0()  asm volatile("cp.async.wait_group 0;" ::: "memory")

// pack 2 fp32 -> packed half2 (round, no residual)
__device__ __forceinline__ unsigned pack2h(float v0, float v1) {
    __half2 h = __floats2half2_rn(v0, v1);
    return *reinterpret_cast<unsigned*>(&h);
}
// split 2 fp32 -> packed half2 hi + residual lo
__device__ __forceinline__ void split2h(float v0, float v1, unsigned& hi, unsigned& lo) {
    __half2 h = __floats2half2_rn(v0, v1);
    float2 hf = __half22float2(h);
    __half2 l = __floats2half2_rn(v0 - hf.x, v1 - hf.y);
    hi = *reinterpret_cast<unsigned*>(&h);
    lo = *reinterpret_cast<unsigned*>(&l);
}
// 8 fp32 -> 8 fp16 (no residual)
__device__ __forceinline__ uint4 conv8h(float4 a, float4 b) {
    return make_uint4(pack2h(a.x, a.y), pack2h(a.z, a.w),
                      pack2h(b.x, b.y), pack2h(b.z, b.w));
}

// ===========================================================================
// Prep: inputs + Wq/Wq12/Wk/Wv -> fp16 (hi only); Wo1/Wo2 -> fp16 hi + lo
// ===========================================================================
struct Prep {
    const float* src[9];
    __half* dh[9];
    __half* dl[9];      // null when single-term
    int n4[9];
};

__global__ __launch_bounds__(256)
void prep_k(Prep pp)
{
    const int z  = blockIdx.y;
    const int i4 = blockIdx.x * 256 + threadIdx.x;
    if (i4 >= pp.n4[z]) return;
    float4 v = ((const float4*)pp.src[z])[i4];
    if (pp.dl[z]) {
        unsigned h0, l0, h1, l1;
        split2h(v.x, v.y, h0, l0);
        split2h(v.z, v.w, h1, l1);
        ((uint2*)pp.dh[z])[i4] = make_uint2(h0, h1);
        ((uint2*)pp.dl[z])[i4] = make_uint2(l0, l1);
    } else {
        ((uint2*)pp.dh[z])[i4] = make_uint2(pack2h(v.x, v.y), pack2h(v.z, v.w));
    }
}

// ===========================================================================
// Compact: per (var, batch), deterministic block-scan of the key mask ->
// ascending index list of unmasked keys + (mul, add) coefficients, padded
// to a multiple of 64 with fully-masked entries. grid = 4 blocks.
// ===========================================================================
__global__ __launch_bounds__(256)
void compact_k(const int* __restrict__ mR, const int* __restrict__ mG,
               const float* __restrict__ wts)
{
    const int cvi = blockIdx.x;          // var*2 + bb
    const int var = cvi >> 1, bb = cvi & 1;
    const int* msk = (var ? mG : mR) + bb * NN;
    const float* w = wts + bb * NN;
    __shared__ int sc[256];

    const int t = threadIdx.x;
    int keep[8];
    int cnt = 0;
#pragma unroll
    for (int j = 0; j < 8; j++) {
        const int key = t * 8 + j;
        if (msk[key] == 0) keep[cnt++] = key;
    }
    sc[t] = cnt;
    __syncthreads();
    for (int d = 1; d < 256; d <<= 1) {
        int v = (t >= d) ? sc[t - d] : 0;
        __syncthreads();
        sc[t] += v;
        __syncthreads();
    }
    const int off = sc[t] - cnt;
    const int total = sc[255];
    for (int j = 0; j < cnt; j++) {
        const int key = keep[j];
        g_cidx[cvi * NN + off + j] = key;
        g_ccf [cvi * NN + off + j] = make_float2(0.125f * w[key], 0.f);
    }
    const int padded = (total + 63) & ~63;
    for (int i = total + t; i < padded; i += 256) {
        g_cidx[cvi * NN + i] = 0;
        g_ccf [cvi * NN + i] = make_float2(0.f, -1e38f);
    }
    if (t == 0) g_pcnt[cvi] = padded;
}

// ===========================================================================
// cp.async double-buffered HMMA GEMM, templated term count:
//   TERMS==1: C = X16·Wh          (projections)
//   TERMS==2: C = X16·Wh + X16·Wl (output projections)
// Block tile 128x128, 8 warps (2Mx4N), warp tile 64x32, K-chunk 32, 2 stages.
// ===========================================================================
#define GRSTR 80
#define GMAT  (128 * GRSTR)            // 10240 per matrix

struct GBF {
    const __half *Xh, *Wh, *Wl;
    const float* Bi;
    float* D;
    __half *Dh, *Dl;
    int mode;                           // 0 HEADS fp32, 1 KV fp16 hi/lo, 2 ROW fp32
};
struct GBFpack { GBF g[7]; };

template<int TERMS>
__global__ __launch_bounds__(256, 2)
void gemm_bf(GBFpack gp)
{
    constexpr int STG = (1 + TERMS) * GMAT;   // matrices per stage: Xh, Wh[, Wl]
    extern __shared__ __align__(16) char smc[];
    const uint32_t sb = smem_u32(smc);

    const GBF gb = gp.g[blockIdx.z];
    const int m0 = blockIdx.y * 128;
    const int n0 = blockIdx.x * 128;

    const int tid  = threadIdx.x;
    const int wid  = tid >> 5;
    const int lane = tid & 31;
    const int warpM = wid >> 2;
    const int warpN = wid & 3;

    const int arow  = (lane & 7) + ((lane >> 3) & 1) * 8;
    const int akoff = ((lane >> 4) & 1) * 16;
    const int brow  = (lane & 7) + ((lane >> 4) & 1) * 8;
    const int bkoff = ((lane >> 3) & 1) * 16;

    float c[4][4][4];
#pragma unroll
    for (int im = 0; im < 4; im++)
#pragma unroll
        for (int jn = 0; jn < 4; jn++)
#pragma unroll
            for (int e = 0; e < 4; e++) c[im][jn][e] = 0.f;

    auto issue = [&](int s, int kc) {
#pragma unroll
        for (int p = 0; p < (1 + TERMS) * 2; p++) {
            const int i = tid + p * 256;
            const int t = i >> 9;               // 0 Xh, 1 Wh, 2 Wl
            const int r = (i >> 2) & 127;
            const int cc = i & 3;
            const __half* src;
            if      (t == 0) src = gb.Xh + (size_t)(m0 + r) * DMODEL + kc * 32 + cc * 8;
            else if (t == 1) src = gb.Wh + (size_t)(n0 + r) * DMODEL + kc * 32 + cc * 8;
            else             src = gb.Wl + (size_t)(n0 + r) * DMODEL + kc * 32 + cc * 8;
            CP_ASYNC16(sb + s * STG + t * GMAT + r * GRSTR + cc * 16, src);
        }
    };

    issue(0, 0);
    CP_COMMIT();

#pragma unroll 1
    for (int kc = 0; kc < 16; kc++) {
        const int b = kc & 1;
        CP_WAIT0();
        __syncthreads();
        if (kc < 15) { issue(b ^ 1, kc + 1); CP_COMMIT(); }

        const uint32_t sAh = sb + b * STG;
        const uint32_t sBh = sAh + GMAT;
        const uint32_t sBl = sAh + 2 * GMAT;

#pragma unroll
        for (int ks = 0; ks < 2; ks++) {
            unsigned bh[2][4], bl[2][4];
#pragma unroll
            for (int jp = 0; jp < 2; jp++) {
                const uint32_t bo = (uint32_t)((warpN * 32 + jp * 16 + brow) * GRSTR
                                               + ks * 32 + bkoff);
                ldm4(bh[jp], sBh + bo);
                if (TERMS == 2) ldm4(bl[jp], sBl + bo);
            }
#pragma unroll
            for (int im = 0; im < 4; im++) {
                const uint32_t ao = (uint32_t)((warpM * 64 + im * 16 + arow) * GRSTR
                                               + ks * 32 + akoff);
                unsigned ah[4];
                ldm4(ah, sAh + ao);
#pragma unroll
                for (int jn = 0; jn < 4; jn++) {
                    const int jp = jn >> 1, jo = (jn & 1) * 2;
                    mma16816(c[im][jn], ah, bh[jp][jo], bh[jp][jo + 1]);
                    if (TERMS == 2)
                        mma16816(c[im][jn], ah, bl[jp][jo], bl[jp][jo + 1]);
                }
            }
        }
    }

    const int rbase = m0 + warpM * 64 + (lane >> 2);
    const int cbase = n0 + warpN * 32 + (lane & 3) * 2;
#pragma unroll
    for (int im = 0; im < 4; im++) {
#pragma unroll
        for (int jn = 0; jn < 4; jn++) {
            const int col = cbase + jn * 8;
            const float b0 = gb.Bi[col], b1 = gb.Bi[col + 1];
#pragma unroll
            for (int half = 0; half < 2; half++) {
                const int m  = rbase + im * 16 + half * 8;
                const float v0 = c[im][jn][half * 2]     + b0;
                const float v1 = c[im][jn][half * 2 + 1] + b1;
                if (gb.mode == 2) {
                    *(float2*)(gb.D + (size_t)m * DMODEL + col) = make_float2(v0, v1);
                } else {
                    const int bb = m >> 11;
                    const int n  = m & 2047;
                    const int h  = col >> 6, d = col & 63;
                    const size_t idx = (((size_t)(bb * HH + h)) * NN + n) * DK + d;
                    if (gb.mode == 0) {
                        *(float2*)(gb.D + idx) = make_float2(v0, v1);
                    } else {
                        unsigned hi, lo; split2h(v0, v1, hi, lo);
                        *(unsigned*)(gb.Dh + idx) = hi;
                        *(unsigned*)(gb.Dl + idx) = lo;
                    }
                }
            }
        }
    }
}

// ===========================================================================
// cp.async double-buffered HMMA FlashAttention over COMPACTED keys,
// fp16 2-term on K and V; Q/P single-term (registers only). Unchanged (R10).
// ===========================================================================
#define AQROWS 128
#define ASTRB 144
#define KMAT (64*ASTRB)              // 9216
#define KVS (4*KMAT)                 // 36864 per stage (Kh,Kl,Vh,Vl)
#define ACF (2*KVS)                  // 73728
#define ASMEMB (ACF + 2*512)         // 74752

__global__ __launch_bounds__(256, 2)
void attn_mma()
{
    extern __shared__ __align__(16) char smn[];
    const uint32_t sb = smem_u32(smn);

    const int var = blockIdx.z;
    const int bh  = blockIdx.y;
    const int bb  = bh >> 3;
    const int h   = bh & 7;
    const int qt  = blockIdx.x;
    const int cvi = var * 2 + bb;

    const float* Q  = g_q + (size_t)bh * NN * DK + (size_t)qt * AQROWS * DK;
    const float* Qx = (var ? g_q1 : g_q2) + (size_t)bh * NN * DK + (size_t)qt * AQROWS * DK;
    const int*    cidx = g_cidx + cvi * NN;
    const float2* ccf  = g_ccf  + cvi * NN;
    const int ntk = g_pcnt[cvi] >> 6;

    const int tid  = threadIdx.x;
    const int wq   = tid >> 5;
    const int lane = tid & 31;
    const int lr   = lane & 7;
    const int g    = lane >> 3;

    const uint32_t qoff = (uint32_t)((wq * 16 + lr + (g & 1) * 8) * ASTRB + (g >> 1) * 16);
    const uint32_t koff = (uint32_t)((lr + (g >> 1) * 8) * ASTRB + (g & 1) * 16);
    const uint32_t voff = (uint32_t)((lr + (g & 1) * 8) * ASTRB + (g >> 1) * 16);

    auto issueKV = [&](int s, int kt) {
        const int r0l = tid >> 3;
        const int gr0 = cidx[kt * 64 + r0l];
        const int gr1 = cidx[kt * 64 + r0l + 32];
#pragma unroll
        for (int p = 0; p < 8; p++) {
            const int i = tid + p * 256;
            const int t = i >> 9;               // 0 Kh,1 Kl,2 Vh,3 Vl
            const int rl = r0l + 32 * (p & 1);
            const int gr = (p & 1) ? gr1 : gr0;
            const int cc = tid & 7;
            const int seg = (t >> 1) ? (2 + var) : var;
            const __half* base = (t & 1) ? g_kvl : g_kvh;
            const __half* src = base + (size_t)seg * HEADELEMS
                + (size_t)bh * NN * DK + (size_t)gr * DK + cc * 8;
            CP_ASYNC16(sb + s * KVS + t * KMAT + rl * ASTRB + cc * 16, src);
        }
    };

    // ---- stage Q (fp32 fused add -> fp16) into the stage-0 area
#pragma unroll
    for (int p = 0; p < 4; p++) {
        const int s   = tid + p * 256;
        const int row = s >> 3;
        const int c8  = (s & 7) * 8;
        float4 a0 = *(const float4*)(Q  + (size_t)row * DK + c8);
        float4 a1 = *(const float4*)(Q  + (size_t)row * DK + c8 + 4);
        float4 b0 = *(const float4*)(Qx + (size_t)row * DK + c8);
        float4 b1 = *(const float4*)(Qx + (size_t)row * DK + c8 + 4);
        a0.x += b0.x; a0.y += b0.y; a0.z += b0.z; a0.w += b0.w;
        a1.x += b1.x; a1.y += b1.y; a1.z += b1.z; a1.w += b1.w;
        *(uint4*)(smn + (uint32_t)(row * ASTRB + c8 * 2)) = conv8h(a0, a1);
    }
    __syncthreads();

    // ---- hoist Q fragments into registers (loop-invariant)
    unsigned aqh[4][4];
#pragma unroll
    for (int t = 0; t < 4; t++)
        ldm4(aqh[t], sb + qoff + 32 * t);
    __syncthreads();   // Q staging consumed; stage 0 may be overwritten

    // ---- prologue
    issueKV(0, 0);
    CP_COMMIT();
    if (tid < 64)
        *(float2*)(smn + ACF + tid * 8) = ccf[tid];

    float o[8][4];
#pragma unroll
    for (int j = 0; j < 8; j++)
#pragma unroll
        for (int e = 0; e < 4; e++) o[j][e] = 0.f;
    float m0 = -INFINITY, m1 = -INFINITY, l0 = 0.f, l1 = 0.f;

#pragma unroll 1
    for (int kt = 0; kt < ntk; kt++) {
        const int b = kt & 1;
        CP_WAIT0();
        __syncthreads();
        if (kt < ntk - 1) {
            issueKV(b ^ 1, kt + 1);
            CP_COMMIT();
            if (tid < 64)
                *(float2*)(smn + ACF + (b ^ 1) * 512 + tid * 8) = ccf[(kt + 1) * 64 + tid];
        }

        const uint32_t sKh = sb + b * KVS;
        const uint32_t sKl = sKh + KMAT;
        const uint32_t sVh = sKh + 2 * KMAT;
        const uint32_t sVl = sKh + 3 * KMAT;

        // ---- S = Q16 K^T (2-term on K)
        float s[8][4];
#pragma unroll
        for (int j = 0; j < 8; j++)
#pragma unroll
            for (int e = 0; e < 4; e++) s[j][e] = 0.f;

#pragma unroll
        for (int u = 0; u < 4; u++) {
#pragma unroll
            for (int t = 0; t < 4; t++) {
                unsigned bkh[4], bkl[4];
                const uint32_t ka = koff + (uint32_t)(u * 16 * ASTRB + 32 * t);
                ldm4(bkh, sKh + ka);
                ldm4(bkl, sKl + ka);
                mma16816(s[2*u],   aqh[t], bkh[0], bkh[1]);
                mma16816(s[2*u],   aqh[t], bkl[0], bkl[1]);
                mma16816(s[2*u+1], aqh[t], bkh[2], bkh[3]);
                mma16816(s[2*u+1], aqh[t], bkl[2], bkl[3]);
            }
        }

        // ---- fused scale*weight (+mask via add for padding)
#pragma unroll
        for (int j = 0; j < 8; j++) {
            float4 cc = *(const float4*)(smn + ACF + b * 512 + (8 * j + (lane & 3) * 2) * 8);
            s[j][0] = fmaf(s[j][0], cc.x, cc.y);
            s[j][1] = fmaf(s[j][1], cc.z, cc.w);
            s[j][2] = fmaf(s[j][2], cc.x, cc.y);
            s[j][3] = fmaf(s[j][3], cc.z, cc.w);
        }

        // ---- online softmax
        float mt0 = -INFINITY, mt1 = -INFINITY;
#pragma unroll
        for (int j = 0; j < 8; j++) {
            mt0 = fmaxf(mt0, fmaxf(s[j][0], s[j][1]));
            mt1 = fmaxf(mt1, fmaxf(s[j][2], s[j][3]));
        }
        mt0 = fmaxf(mt0, __shfl_xor_sync(0xffffffffu, mt0, 1));
        mt0 = fmaxf(mt0, __shfl_xor_sync(0xffffffffu, mt0, 2));
        mt1 = fmaxf(mt1, __shfl_xor_sync(0xffffffffu, mt1, 1));
        mt1 = fmaxf(mt1, __shfl_xor_sync(0xffffffffu, mt1, 2));

        const float mn0 = fmaxf(m0, mt0);
        const float mn1 = fmaxf(m1, mt1);
        const float mx0 = fmaxf(mn0, -1e30f);
        const float mx1 = fmaxf(mn1, -1e30f);
        const float f0 = __expf(m0 - mx0);
        const float f1 = __expf(m1 - mx1);
        m0 = mn0; m1 = mn1;

        float rs0 = 0.f, rs1 = 0.f;
#pragma unroll
        for (int j = 0; j < 8; j++) {
            s[j][0] = __expf(s[j][0] - mx0);
            s[j][1] = __expf(s[j][1] - mx0);
            s[j][2] = __expf(s[j][2] - mx1);
            s[j][3] = __expf(s[j][3] - mx1);
            rs0 += s[j][0] + s[j][1];
            rs1 += s[j][2] + s[j][3];
        }
        rs0 += __shfl_xor_sync(0xffffffffu, rs0, 1);
        rs0 += __shfl_xor_sync(0xffffffffu, rs0, 2);
        rs1 += __shfl_xor_sync(0xffffffffu, rs1, 1);
        rs1 += __shfl_xor_sync(0xffffffffu, rs1, 2);
        l0 = l0 * f0 + rs0;
        l1 = l1 * f1 + rs1;

#pragma unroll
        for (int j = 0; j < 8; j++) {
            o[j][0] *= f0; o[j][1] *= f0;
            o[j][2] *= f1; o[j][3] *= f1;
        }

        // ---- pack P into fp16 A-fragments (registers only, single term)
        unsigned pha[16];
#pragma unroll
        for (int j = 0; j < 8; j++) {
            pha[2*j]   = pack2h(s[j][0], s[j][1]);
            pha[2*j+1] = pack2h(s[j][2], s[j][3]);
        }

        // ---- O += P16 V (2-term on V)
#pragma unroll
        for (int t = 0; t < 4; t++) {
            const unsigned* aph = &pha[4 * t];
#pragma unroll
            for (int u = 0; u < 4; u++) {
                unsigned bvh[4], bvl[4];
                const uint32_t va = voff + (uint32_t)(t * 16 * ASTRB + 32 * u);
                ldm4t(bvh, sVh + va);
                ldm4t(bvl, sVl + va);
                mma16816(o[2*u],   aph, bvh[0], bvh[1]);
                mma16816(o[2*u],   aph, bvl[0], bvl[1]);
                mma16816(o[2*u+1], aph, bvh[2], bvh[3]);
                mma16816(o[2*u+1], aph, bvl[2], bvl[3]);
            }
        }
    }

    // ---- epilogue: normalize, store fp16 to g_oh
    const float inv0 = 1.f / l0;
    const float inv1 = 1.f / l1;
    const int r = qt * AQROWS + wq * 16 + (lane >> 2);
    __half* Oh = g_oh + (size_t)var * OUTHALF;
#pragma unroll
    for (int j = 0; j < 8; j++) {
        const int col = h * DK + 8 * j + (lane & 3) * 2;
        const size_t i0 = ((size_t)bb * NN + r)     * DMODEL + col;
        const size_t i1 = ((size_t)bb * NN + r + 8) * DMODEL + col;
        *(unsigned*)(Oh + i0) = pack2h(o[j][0] * inv0, o[j][1] * inv0);
        *(unsigned*)(Oh + i1) = pack2h(o[j][2] * inv1, o[j][3] * inv1);
    }
}

// ===========================================================================
extern "C" void kernel_launch(void* const* d_in, const int* in_sizes, int n_in,
                              void* d_out, int out_size)
{
    const float* regions   = (const float*)d_in[0];
    const float* grids     = (const float*)d_in[1];
    const float* interests = (const float*)d_in[2];
    const int*   maskR     = (const int*)d_in[3];
    const int*   maskG     = (const int*)d_in[4];
    const float* wts       = (const float*)d_in[5];
    const float* Wq   = (const float*)d_in[6];
    const float* bq   = (const float*)d_in[7];
    const float* Wk   = (const float*)d_in[8];
    const float* bk   = (const float*)d_in[9];
    const float* Wv   = (const float*)d_in[10];
    const float* bv   = (const float*)d_in[11];
    const float* Wq12 = (const float*)d_in[12];
    const float* bq12 = (const float*)d_in[13];
    const float* Wo1  = (const float*)d_in[14];
    const float* bo1  = (const float*)d_in[15];
    const float* Wo2  = (const float*)d_in[16];
    const float* bo2  = (const float*)d_in[17];
    float* out = (float*)d_out;

    float *q, *q1, *q2;
    __half *ih, *wh, *wl, *kvh, *kvl, *oh;
    cudaGetSymbolAddress((void**)&q,   g_q);
    cudaGetSymbolAddress((void**)&q1,  g_q1);
    cudaGetSymbolAddress((void**)&q2,  g_q2);
    cudaGetSymbolAddress((void**)&ih,  g_ih);
    cudaGetSymbolAddress((void**)&wh,  g_wh);
    cudaGetSymbolAddress((void**)&wl,  g_wl);
    cudaGetSymbolAddress((void**)&kvh, g_kvh);
    cudaGetSymbolAddress((void**)&kvl, g_kvl);
    cudaGetSymbolAddress((void**)&oh,  g_oh);

    const int GSMEM1 = 2 * 2 * GMAT;   // 1-term: Xh + Wh, 2 stages = 40960
    const int GSMEM2 = 2 * 3 * GMAT;   // 2-term: Xh + Wh + Wl, 2 stages = 61440
    cudaFuncSetAttribute(gemm_bf<1>, cudaFuncAttributeMaxDynamicSharedMemorySize, GSMEM1);
    cudaFuncSetAttribute(gemm_bf<2>, cudaFuncAttributeMaxDynamicSharedMemorySize, GSMEM2);
    cudaFuncSetAttribute(attn_mma, cudaFuncAttributeMaxDynamicSharedMemorySize, ASMEMB);

    // ---- prep: inputs + Wq/Wq12/Wk/Wv fp16 single; Wo1/Wo2 hi+lo; compaction
    Prep pp;
    const float* srcs[9] = {interests, regions, grids, Wq, Wq12, Wk, Wv, Wo1, Wo2};
    for (int z = 0; z < 9; z++) {
        pp.src[z] = srcs[z];
        if (z < 3) {
            pp.dh[z] = ih + (size_t)z * INSEG;
            pp.dl[z] = nullptr;
            pp.n4[z] = INSEG / 4;
        } else {
            pp.dh[z] = wh + (size_t)(z - 3) * WSEG;
            pp.dl[z] = (z >= 7) ? (wl + (size_t)(z - 3) * WSEG) : nullptr;
            pp.n4[z] = WSEG / 4;
        }
    }
    prep_k<<<dim3(INSEG / 4 / 256, 9), 256>>>(pp);
    compact_k<<<4, 256>>>(maskR, maskG, wts);

    const __half *Ih = ih, *Rh = ih + INSEG, *Gh = ih + 2 * (size_t)INSEG;
    const __half *Wqh = wh, *Wq12h = wh + WSEG, *Wkh = wh + 2*(size_t)WSEG,
                 *Wvh = wh + 3*(size_t)WSEG, *Wo1h = wh + 4*(size_t)WSEG,
                 *Wo2h = wh + 5*(size_t)WSEG;
    const __half *Wo1l = wl + 4*(size_t)WSEG, *Wo2l = wl + 5*(size_t)WSEG;

    // ---- 7 projections, one 1-term launch
    GBFpack pj;
    auto set = [&](int z, const __half* xh, const __half* wwh,
                   const float* bi, float* D, __half* Dh, __half* Dl, int mode) {
        pj.g[z].Xh = xh; pj.g[z].Wh = wwh; pj.g[z].Wl = nullptr;
        pj.g[z].Bi = bi; pj.g[z].D = D; pj.g[z].Dh = Dh; pj.g[z].Dl = Dl;
        pj.g[z].mode = mode;
    };
    set(0, Ih, Wqh,   bq,   q,  nullptr, nullptr, 0);
    set(1, Rh, Wq12h, bq12, q1, nullptr, nullptr, 0);
    set(2, Gh, Wq12h, bq12, q2, nullptr, nullptr, 0);
    set(3, Rh, Wkh,   bk,   nullptr, kvh + 0*(size_t)HEADELEMS, kvl + 0*(size_t)HEADELEMS, 1);
    set(4, Gh, Wkh,   bk,   nullptr, kvh + 1*(size_t)HEADELEMS, kvl + 1*(size_t)HEADELEMS, 1);
    set(5, Rh, Wvh,   bv,   nullptr, kvh + 2*(size_t)HEADELEMS, kvl + 2*(size_t)HEADELEMS, 1);
    set(6, Gh, Wvh,   bv,   nullptr, kvh + 3*(size_t)HEADELEMS, kvl + 3*(size_t)HEADELEMS, 1);
    gemm_bf<1><<<dim3(DMODEL / 128, MTOT / 128, 7), 256, GSMEM1>>>(pj);

    // ---- attention (both variants), compacted keys
    attn_mma<<<dim3(NN / AQROWS, BB * HH, 2), 256, ASMEMB>>>();

    // ---- 2 output projections, one 2-term launch
    GBFpack po;
    auto seto = [&](int z, int var, const __half* wwh, const __half* wwl,
                    const float* bi, float* D) {
        po.g[z].Xh = oh + (size_t)var * OUTHALF;
        po.g[z].Wh = wwh; po.g[z].Wl = wwl; po.g[z].Bi = bi;
        po.g[z].D = D; po.g[z].Dh = nullptr; po.g[z].Dl = nullptr;
        po.g[z].mode = 2;
    };
    seto(0, 0, Wo1h, Wo1l, bo1, out);
    seto(1, 1, Wo2h, Wo2l, bo2, out + OUTHALF);
    for (int z = 2; z < 7; z++) po.g[z] = po.g[0];
    gemm_bf<2><<<dim3(DMODEL / 128, MTOT / 128, 2), 256, GSMEM2>>>(po);
}

// round 14
// speedup vs baseline: 10.9250x; 1.2187x over previous
#include <cuda_runtime.h>
#include <cuda_fp16.h>
#include <math.h>
#include <stdint.h>

#define BB 2
#define NN 2048
#define DMODEL 512
#define HH 8
#define DK 64
#define MTOT (BB*NN)                 // 4096
#define HEADELEMS (BB*HH*NN*DK)      // 2097152
#define OUTHALF (MTOT*DMODEL)        // 2097152
#define INSEG (MTOT*DMODEL)          // 2097152 (one input matrix)
#define WSEG (DMODEL*DMODEL)         // 262144  (one weight matrix)

// ---------------- scratch (__device__ globals; allocation-free rule) --------
__device__ float g_q [HEADELEMS];
__device__ float g_q1[HEADELEMS];
__device__ float g_q2[HEADELEMS];
__device__ __half g_ih[3*INSEG];      // inputs fp16
__device__ __half g_wh[6*WSEG];       // weights hi (Wq, Wq12, Wk, Wv, Wo1, Wo2)
__device__ __half g_wl[6*WSEG];       // weights lo (used for Wo1, Wo2 only)
__device__ __half g_kvh[4*HEADELEMS]; // K1,K2,V1,V2 hi
__device__ __half g_kvl[4*HEADELEMS]; // K1,K2 lo used; V lo written but unused
__device__ __half g_oh[2*OUTHALF];    // O1,O2 fp16 (A-side of out-proj)
// key compaction per (var, batch): indices, coefficients, padded counts
__device__ int    g_cidx[4*NN];
__device__ float2 g_ccf [4*NN];
__device__ int    g_pcnt[4];

__device__ __forceinline__ uint32_t smem_u32(const void* p) {
    uint32_t a;
    asm("{ .reg .u64 t; cvta.to.shared.u64 t, %1; cvt.u32.u64 %0, t; }"
        : "=r"(a) : "l"(p));
    return a;
}

// ---- family-common PTX primitives (sm_80+: valid on .target sm_103) --------
__device__ __forceinline__ void ldm4(unsigned r[4], uint32_t addr) {
    asm volatile("ldmatrix.sync.aligned.m8n8.x4.shared.b16 {%0,%1,%2,%3}, [%4];"
        : "=r"(r[0]), "=r"(r[1]), "=r"(r[2]), "=r"(r[3]) : "r"(addr));
}
__device__ __forceinline__ void ldm4t(unsigned r[4], uint32_t addr) {
    asm volatile("ldmatrix.sync.aligned.m8n8.x4.trans.shared.b16 {%0,%1,%2,%3}, [%4];"
        : "=r"(r[0]), "=r"(r[1]), "=r"(r[2]), "=r"(r[3]) : "r"(addr));
}
__device__ __forceinline__ void mma16816(float c[4], const unsigned a[4],
                                         const unsigned b0, const unsigned b1) {
    asm volatile(
        "mma.sync.aligned.m16n8k16.row.col.f32.f16.f16.f32 "
        "{%0,%1,%2,%3}, {%4,%5,%6,%7}, {%8,%9}, {%0,%1,%2,%3};"
        : "+f"(c[0]), "+f"(c[1]), "+f"(c[2]), "+f"(c[3])
        : "r"(a[0]), "r"(a[1]), "r"(a[2]), "r"(a[3]), "r"(b0), "r"(b1));
}
#define CP_ASYNC16(dst, src) \
    asm volatile("cp.async.cg.shared.global [%0], [%1], 16;" \
        :: "r"(dst), "l"(src) : "memory")
#define CP_COMMIT() asm volatile("cp.async.commit_group;" ::: "memory")
#define CP_WAIT0()  asm volatile("cp.async.wait_group 0;" ::: "memory")

// pack 2 fp32 -> packed half2 (round, no residual)
__device__ __forceinline__ unsigned pack2h(float v0, float v1) {
    __half2 h = __floats2half2_rn(v0, v1);
    return *reinterpret_cast<unsigned*>(&h);
}
// split 2 fp32 -> packed half2 hi + residual lo
__device__ __forceinline__ void split2h(float v0, float v1, unsigned& hi, unsigned& lo) {
    __half2 h = __floats2half2_rn(v0, v1);
    float2 hf = __half22float2(h);
    __half2 l = __floats2half2_rn(v0 - hf.x, v1 - hf.y);
    hi = *reinterpret_cast<unsigned*>(&h);
    lo = *reinterpret_cast<unsigned*>(&l);
}
// 8 fp32 -> 8 fp16 (no residual)
__device__ __forceinline__ uint4 conv8h(float4 a, float4 b) {
    return make_uint4(pack2h(a.x, a.y), pack2h(a.z, a.w),
                      pack2h(b.x, b.y), pack2h(b.z, b.w));
}

// ===========================================================================
// Prep: inputs + Wq/Wq12/Wk/Wv -> fp16 (hi only); Wo1/Wo2 -> fp16 hi + lo
// ===========================================================================
struct Prep {
    const float* src[9];
    __half* dh[9];
    __half* dl[9];      // null when single-term
    int n4[9];
};

__global__ __launch_bounds__(256)
void prep_k(Prep pp)
{
    const int z  = blockIdx.y;
    const int i4 = blockIdx.x * 256 + threadIdx.x;
    if (i4 >= pp.n4[z]) return;
    float4 v = ((const float4*)pp.src[z])[i4];
    if (pp.dl[z]) {
        unsigned h0, l0, h1, l1;
        split2h(v.x, v.y, h0, l0);
        split2h(v.z, v.w, h1, l1);
        ((uint2*)pp.dh[z])[i4] = make_uint2(h0, h1);
        ((uint2*)pp.dl[z])[i4] = make_uint2(l0, l1);
    } else {
        ((uint2*)pp.dh[z])[i4] = make_uint2(pack2h(v.x, v.y), pack2h(v.z, v.w));
    }
}

// ===========================================================================
// Compact: per (var, batch), deterministic block-scan of the key mask ->
// ascending index list of unmasked keys + (mul, add) coefficients, padded
// to a multiple of 64 with fully-masked entries. grid = 4 blocks.
// ===========================================================================
__global__ __launch_bounds__(256)
void compact_k(const int* __restrict__ mR, const int* __restrict__ mG,
               const float* __restrict__ wts)
{
    const int cvi = blockIdx.x;          // var*2 + bb
    const int var = cvi >> 1, bb = cvi & 1;
    const int* msk = (var ? mG : mR) + bb * NN;
    const float* w = wts + bb * NN;
    __shared__ int sc[256];

    const int t = threadIdx.x;
    int keep[8];
    int cnt = 0;
#pragma unroll
    for (int j = 0; j < 8; j++) {
        const int key = t * 8 + j;
        if (msk[key] == 0) keep[cnt++] = key;
    }
    sc[t] = cnt;
    __syncthreads();
    for (int d = 1; d < 256; d <<= 1) {
        int v = (t >= d) ? sc[t - d] : 0;
        __syncthreads();
        sc[t] += v;
        __syncthreads();
    }
    const int off = sc[t] - cnt;
    const int total = sc[255];
    for (int j = 0; j < cnt; j++) {
        const int key = keep[j];
        g_cidx[cvi * NN + off + j] = key;
        g_ccf [cvi * NN + off + j] = make_float2(0.125f * w[key], 0.f);
    }
    const int padded = (total + 63) & ~63;
    for (int i = total + t; i < padded; i += 256) {
        g_cidx[cvi * NN + i] = 0;
        g_ccf [cvi * NN + i] = make_float2(0.f, -1e38f);
    }
    if (t == 0) g_pcnt[cvi] = padded;
}

// ===========================================================================
// cp.async double-buffered HMMA GEMM, templated term count:
//   TERMS==1: C = X16·Wh          (projections)
//   TERMS==2: C = X16·Wh + X16·Wl (output projections)
// Block tile 128x128, 8 warps (2Mx4N), warp tile 64x32, K-chunk 32, 2 stages.
// ===========================================================================
#define GRSTR 80
#define GMAT  (128 * GRSTR)            // 10240 per matrix

struct GBF {
    const __half *Xh, *Wh, *Wl;
    const float* Bi;
    float* D;
    __half *Dh, *Dl;
    int mode;                           // 0 HEADS fp32, 1 KV fp16 hi/lo, 2 ROW fp32
};
struct GBFpack { GBF g[7]; };

template<int TERMS>
__global__ __launch_bounds__(256, 2)
void gemm_bf(GBFpack gp)
{
    constexpr int STG = (1 + TERMS) * GMAT;   // matrices per stage: Xh, Wh[, Wl]
    extern __shared__ __align__(16) char smc[];
    const uint32_t sb = smem_u32(smc);

    const GBF gb = gp.g[blockIdx.z];
    const int m0 = blockIdx.y * 128;
    const int n0 = blockIdx.x * 128;

    const int tid  = threadIdx.x;
    const int wid  = tid >> 5;
    const int lane = tid & 31;
    const int warpM = wid >> 2;
    const int warpN = wid & 3;

    const int arow  = (lane & 7) + ((lane >> 3) & 1) * 8;
    const int akoff = ((lane >> 4) & 1) * 16;
    const int brow  = (lane & 7) + ((lane >> 4) & 1) * 8;
    const int bkoff = ((lane >> 3) & 1) * 16;

    float c[4][4][4];
#pragma unroll
    for (int im = 0; im < 4; im++)
#pragma unroll
        for (int jn = 0; jn < 4; jn++)
#pragma unroll
            for (int e = 0; e < 4; e++) c[im][jn][e] = 0.f;

    auto issue = [&](int s, int kc) {
#pragma unroll
        for (int p = 0; p < (1 + TERMS) * 2; p++) {
            const int i = tid + p * 256;
            const int t = i >> 9;               // 0 Xh, 1 Wh, 2 Wl
            const int r = (i >> 2) & 127;
            const int cc = i & 3;
            const __half* src;
            if      (t == 0) src = gb.Xh + (size_t)(m0 + r) * DMODEL + kc * 32 + cc * 8;
            else if (t == 1) src = gb.Wh + (size_t)(n0 + r) * DMODEL + kc * 32 + cc * 8;
            else             src = gb.Wl + (size_t)(n0 + r) * DMODEL + kc * 32 + cc * 8;
            CP_ASYNC16(sb + s * STG + t * GMAT + r * GRSTR + cc * 16, src);
        }
    };

    issue(0, 0);
    CP_COMMIT();

#pragma unroll 1
    for (int kc = 0; kc < 16; kc++) {
        const int b = kc & 1;
        CP_WAIT0();
        __syncthreads();
        if (kc < 15) { issue(b ^ 1, kc + 1); CP_COMMIT(); }

        const uint32_t sAh = sb + b * STG;
        const uint32_t sBh = sAh + GMAT;
        const uint32_t sBl = sAh + 2 * GMAT;

#pragma unroll
        for (int ks = 0; ks < 2; ks++) {
            unsigned bh[2][4], bl[2][4];
#pragma unroll
            for (int jp = 0; jp < 2; jp++) {
                const uint32_t bo = (uint32_t)((warpN * 32 + jp * 16 + brow) * GRSTR
                                               + ks * 32 + bkoff);
                ldm4(bh[jp], sBh + bo);
                if (TERMS == 2) ldm4(bl[jp], sBl + bo);
            }
#pragma unroll
            for (int im = 0; im < 4; im++) {
                const uint32_t ao = (uint32_t)((warpM * 64 + im * 16 + arow) * GRSTR
                                               + ks * 32 + akoff);
                unsigned ah[4];
                ldm4(ah, sAh + ao);
#pragma unroll
                for (int jn = 0; jn < 4; jn++) {
                    const int jp = jn >> 1, jo = (jn & 1) * 2;
                    mma16816(c[im][jn], ah, bh[jp][jo], bh[jp][jo + 1]);
                    if (TERMS == 2)
                        mma16816(c[im][jn], ah, bl[jp][jo], bl[jp][jo + 1]);
                }
            }
        }
    }

    const int rbase = m0 + warpM * 64 + (lane >> 2);
    const int cbase = n0 + warpN * 32 + (lane & 3) * 2;
#pragma unroll
    for (int im = 0; im < 4; im++) {
#pragma unroll
        for (int jn = 0; jn < 4; jn++) {
            const int col = cbase + jn * 8;
            const float b0 = gb.Bi[col], b1 = gb.Bi[col + 1];
#pragma unroll
            for (int half = 0; half < 2; half++) {
                const int m  = rbase + im * 16 + half * 8;
                const float v0 = c[im][jn][half * 2]     + b0;
                const float v1 = c[im][jn][half * 2 + 1] + b1;
                if (gb.mode == 2) {
                    *(float2*)(gb.D + (size_t)m * DMODEL + col) = make_float2(v0, v1);
                } else {
                    const int bb = m >> 11;
                    const int n  = m & 2047;
                    const int h  = col >> 6, d = col & 63;
                    const size_t idx = (((size_t)(bb * HH + h)) * NN + n) * DK + d;
                    if (gb.mode == 0) {
                        *(float2*)(gb.D + idx) = make_float2(v0, v1);
                    } else {
                        unsigned hi, lo; split2h(v0, v1, hi, lo);
                        *(unsigned*)(gb.Dh + idx) = hi;
                        *(unsigned*)(gb.Dl + idx) = lo;
                    }
                }
            }
        }
    }
}

// ===========================================================================
// cp.async double-buffered HMMA FlashAttention over COMPACTED keys.
// S: 2-term on K (Q16·Kh + Q16·Kl). PV: SINGLE term (P16·Vh) — V residual
// dropped (weighted-average error ~1e-4, linear through out-proj).
// Stage = 3 matrices (Kh, Kl, Vh) -> smem 55KB.
// ===========================================================================
#define AQROWS 128
#define ASTRB 144
#define KMAT (64*ASTRB)              // 9216
#define KVS (3*KMAT)                 // 27648 per stage (Kh,Kl,Vh)
#define ACF (2*KVS)                  // 55296
#define ASMEMB (ACF + 2*512)         // 56320

__global__ __launch_bounds__(256, 2)
void attn_mma()
{
    extern __shared__ __align__(16) char smn[];
    const uint32_t sb = smem_u32(smn);

    const int var = blockIdx.z;
    const int bh  = blockIdx.y;
    const int bb  = bh >> 3;
    const int h   = bh & 7;
    const int qt  = blockIdx.x;
    const int cvi = var * 2 + bb;

    const float* Q  = g_q + (size_t)bh * NN * DK + (size_t)qt * AQROWS * DK;
    const float* Qx = (var ? g_q1 : g_q2) + (size_t)bh * NN * DK + (size_t)qt * AQROWS * DK;
    const int*    cidx = g_cidx + cvi * NN;
    const float2* ccf  = g_ccf  + cvi * NN;
    const int ntk = g_pcnt[cvi] >> 6;

    const int tid  = threadIdx.x;
    const int wq   = tid >> 5;
    const int lane = tid & 31;
    const int lr   = lane & 7;
    const int g    = lane >> 3;

    const uint32_t qoff = (uint32_t)((wq * 16 + lr + (g & 1) * 8) * ASTRB + (g >> 1) * 16);
    const uint32_t koff = (uint32_t)((lr + (g >> 1) * 8) * ASTRB + (g & 1) * 16);
    const uint32_t voff = (uint32_t)((lr + (g & 1) * 8) * ASTRB + (g >> 1) * 16);

    // KV stage copy: Kh, Kl, Vh (3 matrices, 6 passes of 256)
    auto issueKV = [&](int s, int kt) {
        const int r0l = tid >> 3;
        const int gr0 = cidx[kt * 64 + r0l];
        const int gr1 = cidx[kt * 64 + r0l + 32];
#pragma unroll
        for (int p = 0; p < 6; p++) {
            const int i = tid + p * 256;
            const int t = i >> 9;               // 0 Kh, 1 Kl, 2 Vh
            const int rl = r0l + 32 * (p & 1);
            const int gr = (p & 1) ? gr1 : gr0;
            const int cc = tid & 7;
            const int seg = (t == 2) ? (2 + var) : var;
            const __half* base = (t == 1) ? g_kvl : g_kvh;
            const __half* src = base + (size_t)seg * HEADELEMS
                + (size_t)bh * NN * DK + (size_t)gr * DK + cc * 8;
            CP_ASYNC16(sb + s * KVS + t * KMAT + rl * ASTRB + cc * 16, src);
        }
    };

    // ---- stage Q (fp32 fused add -> fp16) into the stage-0 area
#pragma unroll
    for (int p = 0; p < 4; p++) {
        const int s   = tid + p * 256;
        const int row = s >> 3;
        const int c8  = (s & 7) * 8;
        float4 a0 = *(const float4*)(Q  + (size_t)row * DK + c8);
        float4 a1 = *(const float4*)(Q  + (size_t)row * DK + c8 + 4);
        float4 b0 = *(const float4*)(Qx + (size_t)row * DK + c8);
        float4 b1 = *(const float4*)(Qx + (size_t)row * DK + c8 + 4);
        a0.x += b0.x; a0.y += b0.y; a0.z += b0.z; a0.w += b0.w;
        a1.x += b1.x; a1.y += b1.y; a1.z += b1.z; a1.w += b1.w;
        *(uint4*)(smn + (uint32_t)(row * ASTRB + c8 * 2)) = conv8h(a0, a1);
    }
    __syncthreads();

    // ---- hoist Q fragments into registers (loop-invariant)
    unsigned aqh[4][4];
#pragma unroll
    for (int t = 0; t < 4; t++)
        ldm4(aqh[t], sb + qoff + 32 * t);
    __syncthreads();   // Q staging consumed; stage 0 may be overwritten

    // ---- prologue
    issueKV(0, 0);
    CP_COMMIT();
    if (tid < 64)
        *(float2*)(smn + ACF + tid * 8) = ccf[tid];

    float o[8][4];
#pragma unroll
    for (int j = 0; j < 8; j++)
#pragma unroll
        for (int e = 0; e < 4; e++) o[j][e] = 0.f;
    float m0 = -INFINITY, m1 = -INFINITY, l0 = 0.f, l1 = 0.f;

#pragma unroll 1
    for (int kt = 0; kt < ntk; kt++) {
        const int b = kt & 1;
        CP_WAIT0();
        __syncthreads();
        if (kt < ntk - 1) {
            issueKV(b ^ 1, kt + 1);
            CP_COMMIT();
            if (tid < 64)
                *(float2*)(smn + ACF + (b ^ 1) * 512 + tid * 8) = ccf[(kt + 1) * 64 + tid];
        }

        const uint32_t sKh = sb + b * KVS;
        const uint32_t sKl = sKh + KMAT;
        const uint32_t sVh = sKh + 2 * KMAT;

        // ---- S = Q16 K^T (2-term on K)
        float s[8][4];
#pragma unroll
        for (int j = 0; j < 8; j++)
#pragma unroll
            for (int e = 0; e < 4; e++) s[j][e] = 0.f;

#pragma unroll
        for (int u = 0; u < 4; u++) {
#pragma unroll
            for (int t = 0; t < 4; t++) {
                unsigned bkh[4], bkl[4];
                const uint32_t ka = koff + (uint32_t)(u * 16 * ASTRB + 32 * t);
                ldm4(bkh, sKh + ka);
                ldm4(bkl, sKl + ka);
                mma16816(s[2*u],   aqh[t], bkh[0], bkh[1]);
                mma16816(s[2*u],   aqh[t], bkl[0], bkl[1]);
                mma16816(s[2*u+1], aqh[t], bkh[2], bkh[3]);
                mma16816(s[2*u+1], aqh[t], bkl[2], bkl[3]);
            }
        }

        // ---- fused scale*weight (+mask via add for padding)
#pragma unroll
        for (int j = 0; j < 8; j++) {
            float4 cc = *(const float4*)(smn + ACF + b * 512 + (8 * j + (lane & 3) * 2) * 8);
            s[j][0] = fmaf(s[j][0], cc.x, cc.y);
            s[j][1] = fmaf(s[j][1], cc.z, cc.w);
            s[j][2] = fmaf(s[j][2], cc.x, cc.y);
            s[j][3] = fmaf(s[j][3], cc.z, cc.w);
        }

        // ---- online softmax
        float mt0 = -INFINITY, mt1 = -INFINITY;
#pragma unroll
        for (int j = 0; j < 8; j++) {
            mt0 = fmaxf(mt0, fmaxf(s[j][0], s[j][1]));
            mt1 = fmaxf(mt1, fmaxf(s[j][2], s[j][3]));
        }
        mt0 = fmaxf(mt0, __shfl_xor_sync(0xffffffffu, mt0, 1));
        mt0 = fmaxf(mt0, __shfl_xor_sync(0xffffffffu, mt0, 2));
        mt1 = fmaxf(mt1, __shfl_xor_sync(0xffffffffu, mt1, 1));
        mt1 = fmaxf(mt1, __shfl_xor_sync(0xffffffffu, mt1, 2));

        const float mn0 = fmaxf(m0, mt0);
        const float mn1 = fmaxf(m1, mt1);
        const float mx0 = fmaxf(mn0, -1e30f);
        const float mx1 = fmaxf(mn1, -1e30f);
        const float f0 = __expf(m0 - mx0);
        const float f1 = __expf(m1 - mx1);
        m0 = mn0; m1 = mn1;

        float rs0 = 0.f, rs1 = 0.f;
#pragma unroll
        for (int j = 0; j < 8; j++) {
            s[j][0] = __expf(s[j][0] - mx0);
            s[j][1] = __expf(s[j][1] - mx0);
            s[j][2] = __expf(s[j][2] - mx1);
            s[j][3] = __expf(s[j][3] - mx1);
            rs0 += s[j][0] + s[j][1];
            rs1 += s[j][2] + s[j][3];
        }
        rs0 += __shfl_xor_sync(0xffffffffu, rs0, 1);
        rs0 += __shfl_xor_sync(0xffffffffu, rs0, 2);
        rs1 += __shfl_xor_sync(0xffffffffu, rs1, 1);
        rs1 += __shfl_xor_sync(0xffffffffu, rs1, 2);
        l0 = l0 * f0 + rs0;
        l1 = l1 * f1 + rs1;

#pragma unroll
        for (int j = 0; j < 8; j++) {
            o[j][0] *= f0; o[j][1] *= f0;
            o[j][2] *= f1; o[j][3] *= f1;
        }

        // ---- pack P into fp16 A-fragments (registers only, single term)
        unsigned pha[16];
#pragma unroll
        for (int j = 0; j < 8; j++) {
            pha[2*j]   = pack2h(s[j][0], s[j][1]);
            pha[2*j+1] = pack2h(s[j][2], s[j][3]);
        }

        // ---- O += P16 Vh (single term)
#pragma unroll
        for (int t = 0; t < 4; t++) {
            const unsigned* aph = &pha[4 * t];
#pragma unroll
            for (int u = 0; u < 4; u++) {
                unsigned bvh[4];
                const uint32_t va = voff + (uint32_t)(t * 16 * ASTRB + 32 * u);
                ldm4t(bvh, sVh + va);
                mma16816(o[2*u],   aph, bvh[0], bvh[1]);
                mma16816(o[2*u+1], aph, bvh[2], bvh[3]);
            }
        }
    }

    // ---- epilogue: normalize, store fp16 to g_oh
    const float inv0 = 1.f / l0;
    const float inv1 = 1.f / l1;
    const int r = qt * AQROWS + wq * 16 + (lane >> 2);
    __half* Oh = g_oh + (size_t)var * OUTHALF;
#pragma unroll
    for (int j = 0; j < 8; j++) {
        const int col = h * DK + 8 * j + (lane & 3) * 2;
        const size_t i0 = ((size_t)bb * NN + r)     * DMODEL + col;
        const size_t i1 = ((size_t)bb * NN + r + 8) * DMODEL + col;
        *(unsigned*)(Oh + i0) = pack2h(o[j][0] * inv0, o[j][1] * inv0);
        *(unsigned*)(Oh + i1) = pack2h(o[j][2] * inv1, o[j][3] * inv1);
    }
}

// ===========================================================================
extern "C" void kernel_launch(void* const* d_in, const int* in_sizes, int n_in,
                              void* d_out, int out_size)
{
    const float* regions   = (const float*)d_in[0];
    const float* grids     = (const float*)d_in[1];
    const float* interests = (const float*)d_in[2];
    const int*   maskR     = (const int*)d_in[3];
    const int*   maskG     = (const int*)d_in[4];
    const float* wts       = (const float*)d_in[5];
    const float* Wq   = (const float*)d_in[6];
    const float* bq   = (const float*)d_in[7];
    const float* Wk   = (const float*)d_in[8];
    const float* bk   = (const float*)d_in[9];
    const float* Wv   = (const float*)d_in[10];
    const float* bv   = (const float*)d_in[11];
    const float* Wq12 = (const float*)d_in[12];
    const float* bq12 = (const float*)d_in[13];
    const float* Wo1  = (const float*)d_in[14];
    const float* bo1  = (const float*)d_in[15];
    const float* Wo2  = (const float*)d_in[16];
    const float* bo2  = (const float*)d_in[17];
    float* out = (float*)d_out;

    float *q, *q1, *q2;
    __half *ih, *wh, *wl, *kvh, *kvl, *oh;
    cudaGetSymbolAddress((void**)&q,   g_q);
    cudaGetSymbolAddress((void**)&q1,  g_q1);
    cudaGetSymbolAddress((void**)&q2,  g_q2);
    cudaGetSymbolAddress((void**)&ih,  g_ih);
    cudaGetSymbolAddress((void**)&wh,  g_wh);
    cudaGetSymbolAddress((void**)&wl,  g_wl);
    cudaGetSymbolAddress((void**)&kvh, g_kvh);
    cudaGetSymbolAddress((void**)&kvl, g_kvl);
    cudaGetSymbolAddress((void**)&oh,  g_oh);

    const int GSMEM1 = 2 * 2 * GMAT;   // 1-term: 40960
    const int GSMEM2 = 2 * 3 * GMAT;   // 2-term: 61440
    cudaFuncSetAttribute(gemm_bf<1>, cudaFuncAttributeMaxDynamicSharedMemorySize, GSMEM1);
    cudaFuncSetAttribute(gemm_bf<2>, cudaFuncAttributeMaxDynamicSharedMemorySize, GSMEM2);
    cudaFuncSetAttribute(attn_mma, cudaFuncAttributeMaxDynamicSharedMemorySize, ASMEMB);

    // ---- prep: inputs + Wq/Wq12/Wk/Wv fp16 single; Wo1/Wo2 hi+lo; compaction
    Prep pp;
    const float* srcs[9] = {interests, regions, grids, Wq, Wq12, Wk, Wv, Wo1, Wo2};
    for (int z = 0; z < 9; z++) {
        pp.src[z] = srcs[z];
        if (z < 3) {
            pp.dh[z] = ih + (size_t)z * INSEG;
            pp.dl[z] = nullptr;
            pp.n4[z] = INSEG / 4;
        } else {
            pp.dh[z] = wh + (size_t)(z - 3) * WSEG;
            pp.dl[z] = (z >= 7) ? (wl + (size_t)(z - 3) * WSEG) : nullptr;
            pp.n4[z] = WSEG / 4;
        }
    }
    prep_k<<<dim3(INSEG / 4 / 256, 9), 256>>>(pp);
    compact_k<<<4, 256>>>(maskR, maskG, wts);

    const __half *Ih = ih, *Rh = ih + INSEG, *Gh = ih + 2 * (size_t)INSEG;
    const __half *Wqh = wh, *Wq12h = wh + WSEG, *Wkh = wh + 2*(size_t)WSEG,
                 *Wvh = wh + 3*(size_t)WSEG, *Wo1h = wh + 4*(size_t)WSEG,
                 *Wo2h = wh + 5*(size_t)WSEG;
    const __half *Wo1l = wl + 4*(size_t)WSEG, *Wo2l = wl + 5*(size_t)WSEG;

    // ---- 7 projections, one 1-term launch
    GBFpack pj;
    auto set = [&](int z, const __half* xh, const __half* wwh,
                   const float* bi, float* D, __half* Dh, __half* Dl, int mode) {
        pj.g[z].Xh = xh; pj.g[z].Wh = wwh; pj.g[z].Wl = nullptr;
        pj.g[z].Bi = bi; pj.g[z].D = D; pj.g[z].Dh = Dh; pj.g[z].Dl = Dl;
        pj.g[z].mode = mode;
    };
    set(0, Ih, Wqh,   bq,   q,  nullptr, nullptr, 0);
    set(1, Rh, Wq12h, bq12, q1, nullptr, nullptr, 0);
    set(2, Gh, Wq12h, bq12, q2, nullptr, nullptr, 0);
    set(3, Rh, Wkh,   bk,   nullptr, kvh + 0*(size_t)HEADELEMS, kvl + 0*(size_t)HEADELEMS, 1);
    set(4, Gh, Wkh,   bk,   nullptr, kvh + 1*(size_t)HEADELEMS, kvl + 1*(size_t)HEADELEMS, 1);
    set(5, Rh, Wvh,   bv,   nullptr, kvh + 2*(size_t)HEADELEMS, kvl + 2*(size_t)HEADELEMS, 1);
    set(6, Gh, Wvh,   bv,   nullptr, kvh + 3*(size_t)HEADELEMS, kvl + 3*(size_t)HEADELEMS, 1);
    gemm_bf<1><<<dim3(DMODEL / 128, MTOT / 128, 7), 256, GSMEM1>>>(pj);

    // ---- attention (both variants), compacted keys
    attn_mma<<<dim3(NN / AQROWS, BB * HH, 2), 256, ASMEMB>>>();

    // ---- 2 output projections, one 2-term launch
    GBFpack po;
    auto seto = [&](int z, int var, const __half* wwh, const __half* wwl,
                    const float* bi, float* D) {
        po.g[z].Xh = oh + (size_t)var * OUTHALF;
        po.g[z].Wh = wwh; po.g[z].Wl = wwl; po.g[z].Bi = bi;
        po.g[z].D = D; po.g[z].Dh = nullptr; po.g[z].Dl = nullptr;
        po.g[z].mode = 2;
    };
    seto(0, 0, Wo1h, Wo1l, bo1, out);
    seto(1, 1, Wo2h, Wo2l, bo2, out + OUTHALF);
    for (int z = 2; z < 7; z++) po.g[z] = po.g[0];
    gemm_bf<2><<<dim3(DMODEL / 128, MTOT / 128, 2), 256, GSMEM2>>>(po);
}

// round 16
// speedup vs baseline: 11.9418x; 1.0931x over previous
#include <cuda_runtime.h>
#include <cuda_fp16.h>
#include <math.h>
#include <stdint.h>

#define BB 2
#define NN 2048
#define DMODEL 512
#define HH 8
#define DK 64
#define MTOT (BB*NN)                 // 4096
#define HEADELEMS (BB*HH*NN*DK)      // 2097152
#define OUTHALF (MTOT*DMODEL)        // 2097152
#define INSEG (MTOT*DMODEL)          // 2097152 (one input matrix)
#define WSEG (DMODEL*DMODEL)         // 262144  (one weight matrix)

// ---------------- scratch (__device__ globals; allocation-free rule) --------
__device__ float g_q [HEADELEMS];
__device__ float g_q1[HEADELEMS];
__device__ float g_q2[HEADELEMS];
__device__ __half g_ih[3*INSEG];      // inputs fp16
__device__ __half g_wh[6*WSEG];       // weights fp16 (Wq, Wq12, Wk, Wv, Wo1, Wo2)
__device__ __half g_kvh[4*HEADELEMS]; // K1,K2,V1,V2 hi
__device__ __half g_kvl[2*HEADELEMS]; // K1,K2 lo (V residual dropped)
__device__ __half g_oh[2*OUTHALF];    // O1,O2 fp16 (A-side of out-proj)
// key compaction per (var, batch): indices, coefficients, padded counts
__device__ int    g_cidx[4*NN];
__device__ float2 g_ccf [4*NN];
__device__ int    g_pcnt[4];

__device__ __forceinline__ uint32_t smem_u32(const void* p) {
    uint32_t a;
    asm("{ .reg .u64 t; cvta.to.shared.u64 t, %1; cvt.u32.u64 %0, t; }"
        : "=r"(a) : "l"(p));
    return a;
}

// ---- family-common PTX primitives (sm_80+: valid on .target sm_103) --------
__device__ __forceinline__ void ldm4(unsigned r[4], uint32_t addr) {
    asm volatile("ldmatrix.sync.aligned.m8n8.x4.shared.b16 {%0,%1,%2,%3}, [%4];"
        : "=r"(r[0]), "=r"(r[1]), "=r"(r[2]), "=r"(r[3]) : "r"(addr));
}
__device__ __forceinline__ void ldm4t(unsigned r[4], uint32_t addr) {
    asm volatile("ldmatrix.sync.aligned.m8n8.x4.trans.shared.b16 {%0,%1,%2,%3}, [%4];"
        : "=r"(r[0]), "=r"(r[1]), "=r"(r[2]), "=r"(r[3]) : "r"(addr));
}
__device__ __forceinline__ void mma16816(float c[4], const unsigned a[4],
                                         const unsigned b0, const unsigned b1) {
    asm volatile(
        "mma.sync.aligned.m16n8k16.row.col.f32.f16.f16.f32 "
        "{%0,%1,%2,%3}, {%4,%5,%6,%7}, {%8,%9}, {%0,%1,%2,%3};"
        : "+f"(c[0]), "+f"(c[1]), "+f"(c[2]), "+f"(c[3])
        : "r"(a[0]), "r"(a[1]), "r"(a[2]), "r"(a[3]), "r"(b0), "r"(b1));
}
#define CP_ASYNC16(dst, src) \
    asm volatile("cp.async.cg.shared.global [%0], [%1], 16;" \
        :: "r"(dst), "l"(src) : "memory")
#define CP_COMMIT() asm volatile("cp.async.commit_group;" ::: "memory")
#define CP_WAIT0()  asm volatile("cp.async.wait_group 0;" ::: "memory")

// pack 2 fp32 -> packed half2 (round, no residual)
__device__ __forceinline__ unsigned pack2h(float v0, float v1) {
    __half2 h = __floats2half2_rn(v0, v1);
    return *reinterpret_cast<unsigned*>(&h);
}
// split 2 fp32 -> packed half2 hi + residual lo
__device__ __forceinline__ void split2h(float v0, float v1, unsigned& hi, unsigned& lo) {
    __half2 h = __floats2half2_rn(v0, v1);
    float2 hf = __half22float2(h);
    __half2 l = __floats2half2_rn(v0 - hf.x, v1 - hf.y);
    hi = *reinterpret_cast<unsigned*>(&h);
    lo = *reinterpret_cast<unsigned*>(&l);
}
// 8 fp32 -> 8 fp16 (no residual)
__device__ __forceinline__ uint4 conv8h(float4 a, float4 b) {
    return make_uint4(pack2h(a.x, a.y), pack2h(a.z, a.w),
                      pack2h(b.x, b.y), pack2h(b.z, b.w));
}

// ===========================================================================
// Prep: all 9 fp32 matrices -> fp16 (single term)
// ===========================================================================
struct Prep {
    const float* src[9];
    __half* dh[9];
    int n4[9];
};

__global__ __launch_bounds__(256)
void prep_k(Prep pp)
{
    const int z  = blockIdx.y;
    const int i4 = blockIdx.x * 256 + threadIdx.x;
    if (i4 >= pp.n4[z]) return;
    float4 v = ((const float4*)pp.src[z])[i4];
    ((uint2*)pp.dh[z])[i4] = make_uint2(pack2h(v.x, v.y), pack2h(v.z, v.w));
}

// ===========================================================================
// Compact: per (var, batch), deterministic block-scan of the key mask ->
// ascending index list of unmasked keys + (mul, add) coefficients, padded
// to a multiple of 64 with fully-masked entries. grid = 4 blocks.
// ===========================================================================
__global__ __launch_bounds__(256)
void compact_k(const int* __restrict__ mR, const int* __restrict__ mG,
               const float* __restrict__ wts)
{
    const int cvi = blockIdx.x;          // var*2 + bb
    const int var = cvi >> 1, bb = cvi & 1;
    const int* msk = (var ? mG : mR) + bb * NN;
    const float* w = wts + bb * NN;
    __shared__ int sc[256];

    const int t = threadIdx.x;
    int keep[8];
    int cnt = 0;
#pragma unroll
    for (int j = 0; j < 8; j++) {
        const int key = t * 8 + j;
        if (msk[key] == 0) keep[cnt++] = key;
    }
    sc[t] = cnt;
    __syncthreads();
    for (int d = 1; d < 256; d <<= 1) {
        int v = (t >= d) ? sc[t - d] : 0;
        __syncthreads();
        sc[t] += v;
        __syncthreads();
    }
    const int off = sc[t] - cnt;
    const int total = sc[255];
    for (int j = 0; j < cnt; j++) {
        const int key = keep[j];
        g_cidx[cvi * NN + off + j] = key;
        g_ccf [cvi * NN + off + j] = make_float2(0.125f * w[key], 0.f);
    }
    const int padded = (total + 63) & ~63;
    for (int i = total + t; i < padded; i += 256) {
        g_cidx[cvi * NN + i] = 0;
        g_ccf [cvi * NN + i] = make_float2(0.f, -1e38f);
    }
    if (t == 0) g_pcnt[cvi] = padded;
}

// ===========================================================================
// cp.async double-buffered HMMA GEMM, single term: C = X16·W16 + bias.
// Block tile 128x128, 8 warps (2Mx4N), warp tile 64x32, K-chunk 32, 2 stages.
// mode: 0 HEADS fp32, 1 KV fp16 hi+lo, 2 ROW fp32, 3 KV fp16 hi only.
// ===========================================================================
#define GRSTR 80
#define GMAT  (128 * GRSTR)            // 10240 per matrix
#define GSTG  (2 * GMAT)               // 20480 per stage (Xh, Wh)
#define GSMEM (2 * GSTG)               // 40960

struct GBF {
    const __half *Xh, *Wh;
    const float* Bi;
    float* D;
    __half *Dh, *Dl;
    int mode;
};
struct GBFpack { GBF g[7]; };

__global__ __launch_bounds__(256, 2)
void gemm_hf(GBFpack gp)
{
    extern __shared__ __align__(16) char smc[];
    const uint32_t sb = smem_u32(smc);

    const GBF gb = gp.g[blockIdx.z];
    const int m0 = blockIdx.y * 128;
    const int n0 = blockIdx.x * 128;

    const int tid  = threadIdx.x;
    const int wid  = tid >> 5;
    const int lane = tid & 31;
    const int warpM = wid >> 2;
    const int warpN = wid & 3;

    const int arow  = (lane & 7) + ((lane >> 3) & 1) * 8;
    const int akoff = ((lane >> 4) & 1) * 16;
    const int brow  = (lane & 7) + ((lane >> 4) & 1) * 8;
    const int bkoff = ((lane >> 3) & 1) * 16;

    float c[4][4][4];
#pragma unroll
    for (int im = 0; im < 4; im++)
#pragma unroll
        for (int jn = 0; jn < 4; jn++)
#pragma unroll
            for (int e = 0; e < 4; e++) c[im][jn][e] = 0.f;

    auto issue = [&](int s, int kc) {
#pragma unroll
        for (int p = 0; p < 4; p++) {
            const int i = tid + p * 256;        // 0..1023
            const int t = i >> 9;               // 0 Xh, 1 Wh
            const int r = (i >> 2) & 127;
            const int cc = i & 3;
            const __half* src = (t == 0)
                ? gb.Xh + (size_t)(m0 + r) * DMODEL + kc * 32 + cc * 8
                : gb.Wh + (size_t)(n0 + r) * DMODEL + kc * 32 + cc * 8;
            CP_ASYNC16(sb + s * GSTG + t * GMAT + r * GRSTR + cc * 16, src);
        }
    };

    issue(0, 0);
    CP_COMMIT();

#pragma unroll 1
    for (int kc = 0; kc < 16; kc++) {
        const int b = kc & 1;
        CP_WAIT0();
        __syncthreads();
        if (kc < 15) { issue(b ^ 1, kc + 1); CP_COMMIT(); }

        const uint32_t sAh = sb + b * GSTG;
        const uint32_t sBh = sAh + GMAT;

#pragma unroll
        for (int ks = 0; ks < 2; ks++) {
            unsigned bh[2][4];
#pragma unroll
            for (int jp = 0; jp < 2; jp++) {
                const uint32_t bo = (uint32_t)((warpN * 32 + jp * 16 + brow) * GRSTR
                                               + ks * 32 + bkoff);
                ldm4(bh[jp], sBh + bo);
            }
#pragma unroll
            for (int im = 0; im < 4; im++) {
                const uint32_t ao = (uint32_t)((warpM * 64 + im * 16 + arow) * GRSTR
                                               + ks * 32 + akoff);
                unsigned ah[4];
                ldm4(ah, sAh + ao);
#pragma unroll
                for (int jn = 0; jn < 4; jn++) {
                    const int jp = jn >> 1, jo = (jn & 1) * 2;
                    mma16816(c[im][jn], ah, bh[jp][jo], bh[jp][jo + 1]);
                }
            }
        }
    }

    const int rbase = m0 + warpM * 64 + (lane >> 2);
    const int cbase = n0 + warpN * 32 + (lane & 3) * 2;
#pragma unroll
    for (int im = 0; im < 4; im++) {
#pragma unroll
        for (int jn = 0; jn < 4; jn++) {
            const int col = cbase + jn * 8;
            const float b0 = gb.Bi[col], b1 = gb.Bi[col + 1];
#pragma unroll
            for (int half = 0; half < 2; half++) {
                const int m  = rbase + im * 16 + half * 8;
                const float v0 = c[im][jn][half * 2]     + b0;
                const float v1 = c[im][jn][half * 2 + 1] + b1;
                if (gb.mode == 2) {
                    *(float2*)(gb.D + (size_t)m * DMODEL + col) = make_float2(v0, v1);
                } else {
                    const int bb = m >> 11;
                    const int n  = m & 2047;
                    const int h  = col >> 6, d = col & 63;
                    const size_t idx = (((size_t)(bb * HH + h)) * NN + n) * DK + d;
                    if (gb.mode == 0) {
                        *(float2*)(gb.D + idx) = make_float2(v0, v1);
                    } else if (gb.mode == 1) {
                        unsigned hi, lo; split2h(v0, v1, hi, lo);
                        *(unsigned*)(gb.Dh + idx) = hi;
                        *(unsigned*)(gb.Dl + idx) = lo;
                    } else {   // mode 3: hi only (V)
                        *(unsigned*)(gb.Dh + idx) = pack2h(v0, v1);
                    }
                }
            }
        }
    }
}

// ===========================================================================
// cp.async double-buffered HMMA FlashAttention over COMPACTED keys.
// S: 2-term on K. PV: single term. Softmax WITHOUT running max (logits are
// bounded ~|s|<8 by construction; exp is safe in fp32; softmax shift-invariant).
// Stage = 3 matrices (Kh, Kl, Vh), smem 55KB.
// ===========================================================================
#define AQROWS 128
#define ASTRB 144
#define KMAT (64*ASTRB)              // 9216
#define KVS (3*KMAT)                 // 27648 per stage (Kh,Kl,Vh)
#define ACF (2*KVS)                  // 55296
#define ASMEMB (ACF + 2*512)         // 56320

__global__ __launch_bounds__(256, 2)
void attn_mma()
{
    extern __shared__ __align__(16) char smn[];
    const uint32_t sb = smem_u32(smn);

    const int var = blockIdx.z;
    const int bh  = blockIdx.y;
    const int bb  = bh >> 3;
    const int h   = bh & 7;
    const int qt  = blockIdx.x;
    const int cvi = var * 2 + bb;

    const float* Q  = g_q + (size_t)bh * NN * DK + (size_t)qt * AQROWS * DK;
    const float* Qx = (var ? g_q1 : g_q2) + (size_t)bh * NN * DK + (size_t)qt * AQROWS * DK;
    const int*    cidx = g_cidx + cvi * NN;
    const float2* ccf  = g_ccf  + cvi * NN;
    const int ntk = g_pcnt[cvi] >> 6;

    const int tid  = threadIdx.x;
    const int wq   = tid >> 5;
    const int lane = tid & 31;
    const int lr   = lane & 7;
    const int g    = lane >> 3;

    const uint32_t qoff = (uint32_t)((wq * 16 + lr + (g & 1) * 8) * ASTRB + (g >> 1) * 16);
    const uint32_t koff = (uint32_t)((lr + (g >> 1) * 8) * ASTRB + (g & 1) * 16);
    const uint32_t voff = (uint32_t)((lr + (g & 1) * 8) * ASTRB + (g >> 1) * 16);

    // KV stage copy: Kh, Kl, Vh
    auto issueKV = [&](int s, int kt) {
        const int r0l = tid >> 3;
        const int gr0 = cidx[kt * 64 + r0l];
        const int gr1 = cidx[kt * 64 + r0l + 32];
#pragma unroll
        for (int p = 0; p < 6; p++) {
            const int i = tid + p * 256;
            const int t = i >> 9;               // 0 Kh, 1 Kl, 2 Vh
            const int rl = r0l + 32 * (p & 1);
            const int gr = (p & 1) ? gr1 : gr0;
            const int cc = tid & 7;
            const __half* src;
            if (t == 0)      src = g_kvh + (size_t)var * HEADELEMS;
            else if (t == 1) src = g_kvl + (size_t)var * HEADELEMS;
            else             src = g_kvh + (size_t)(2 + var) * HEADELEMS;
            src += (size_t)bh * NN * DK + (size_t)gr * DK + cc * 8;
            CP_ASYNC16(sb + s * KVS + t * KMAT + rl * ASTRB + cc * 16, src);
        }
    };

    // ---- stage Q (fp32 fused add -> fp16) into the stage-0 area
#pragma unroll
    for (int p = 0; p < 4; p++) {
        const int s   = tid + p * 256;
        const int row = s >> 3;
        const int c8  = (s & 7) * 8;
        float4 a0 = *(const float4*)(Q  + (size_t)row * DK + c8);
        float4 a1 = *(const float4*)(Q  + (size_t)row * DK + c8 + 4);
        float4 b0 = *(const float4*)(Qx + (size_t)row * DK + c8);
        float4 b1 = *(const float4*)(Qx + (size_t)row * DK + c8 + 4);
        a0.x += b0.x; a0.y += b0.y; a0.z += b0.z; a0.w += b0.w;
        a1.x += b1.x; a1.y += b1.y; a1.z += b1.z; a1.w += b1.w;
        *(uint4*)(smn + (uint32_t)(row * ASTRB + c8 * 2)) = conv8h(a0, a1);
    }
    __syncthreads();

    // ---- hoist Q fragments into registers (loop-invariant)
    unsigned aqh[4][4];
#pragma unroll
    for (int t = 0; t < 4; t++)
        ldm4(aqh[t], sb + qoff + 32 * t);
    __syncthreads();   // Q staging consumed; stage 0 may be overwritten

    // ---- prologue
    issueKV(0, 0);
    CP_COMMIT();
    if (tid < 64)
        *(float2*)(smn + ACF + tid * 8) = ccf[tid];

    float o[8][4];
#pragma unroll
    for (int j = 0; j < 8; j++)
#pragma unroll
        for (int e = 0; e < 4; e++) o[j][e] = 0.f;
    float l0 = 0.f, l1 = 0.f;

#pragma unroll 1
    for (int kt = 0; kt < ntk; kt++) {
        const int b = kt & 1;
        CP_WAIT0();
        __syncthreads();
        if (kt < ntk - 1) {
            issueKV(b ^ 1, kt + 1);
            CP_COMMIT();
            if (tid < 64)
                *(float2*)(smn + ACF + (b ^ 1) * 512 + tid * 8) = ccf[(kt + 1) * 64 + tid];
        }

        const uint32_t sKh = sb + b * KVS;
        const uint32_t sKl = sKh + KMAT;
        const uint32_t sVh = sKh + 2 * KMAT;

        // ---- S = Q16 K^T (2-term on K)
        float s[8][4];
#pragma unroll
        for (int j = 0; j < 8; j++)
#pragma unroll
            for (int e = 0; e < 4; e++) s[j][e] = 0.f;

#pragma unroll
        for (int u = 0; u < 4; u++) {
#pragma unroll
            for (int t = 0; t < 4; t++) {
                unsigned bkh[4], bkl[4];
                const uint32_t ka = koff + (uint32_t)(u * 16 * ASTRB + 32 * t);
                ldm4(bkh, sKh + ka);
                ldm4(bkl, sKl + ka);
                mma16816(s[2*u],   aqh[t], bkh[0], bkh[1]);
                mma16816(s[2*u],   aqh[t], bkl[0], bkl[1]);
                mma16816(s[2*u+1], aqh[t], bkh[2], bkh[3]);
                mma16816(s[2*u+1], aqh[t], bkl[2], bkl[3]);
            }
        }

        // ---- p = exp(s*mul + add), accumulate row sums, pack P (no max shift)
        unsigned pha[16];
        float rs0 = 0.f, rs1 = 0.f;
#pragma unroll
        for (int j = 0; j < 8; j++) {
            float4 cc = *(const float4*)(smn + ACF + b * 512 + (8 * j + (lane & 3) * 2) * 8);
            float p0 = __expf(fmaf(s[j][0], cc.x, cc.y));
            float p1 = __expf(fmaf(s[j][1], cc.z, cc.w));
            float p2 = __expf(fmaf(s[j][2], cc.x, cc.y));
            float p3 = __expf(fmaf(s[j][3], cc.z, cc.w));
            rs0 += p0 + p1;
            rs1 += p2 + p3;
            pha[2*j]   = pack2h(p0, p1);
            pha[2*j+1] = pack2h(p2, p3);
        }
        l0 += rs0;
        l1 += rs1;

        // ---- O += P16 Vh (single term)
#pragma unroll
        for (int t = 0; t < 4; t++) {
            const unsigned* aph = &pha[4 * t];
#pragma unroll
            for (int u = 0; u < 4; u++) {
                unsigned bvh[4];
                const uint32_t va = voff + (uint32_t)(t * 16 * ASTRB + 32 * u);
                ldm4t(bvh, sVh + va);
                mma16816(o[2*u],   aph, bvh[0], bvh[1]);
                mma16816(o[2*u+1], aph, bvh[2], bvh[3]);
            }
        }
    }

    // ---- row sums across the 4 lanes of each row-group
    l0 += __shfl_xor_sync(0xffffffffu, l0, 1);
    l0 += __shfl_xor_sync(0xffffffffu, l0, 2);
    l1 += __shfl_xor_sync(0xffffffffu, l1, 1);
    l1 += __shfl_xor_sync(0xffffffffu, l1, 2);

    // ---- epilogue: normalize, store fp16 to g_oh
    const float inv0 = 1.f / l0;
    const float inv1 = 1.f / l1;
    const int r = qt * AQROWS + wq * 16 + (lane >> 2);
    __half* Oh = g_oh + (size_t)var * OUTHALF;
#pragma unroll
    for (int j = 0; j < 8; j++) {
        const int col = h * DK + 8 * j + (lane & 3) * 2;
        const size_t i0 = ((size_t)bb * NN + r)     * DMODEL + col;
        const size_t i1 = ((size_t)bb * NN + r + 8) * DMODEL + col;
        *(unsigned*)(Oh + i0) = pack2h(o[j][0] * inv0, o[j][1] * inv0);
        *(unsigned*)(Oh + i1) = pack2h(o[j][2] * inv1, o[j][3] * inv1);
    }
}

// ===========================================================================
extern "C" void kernel_launch(void* const* d_in, const int* in_sizes, int n_in,
                              void* d_out, int out_size)
{
    const float* regions   = (const float*)d_in[0];
    const float* grids     = (const float*)d_in[1];
    const float* interests = (const float*)d_in[2];
    const int*   maskR     = (const int*)d_in[3];
    const int*   maskG     = (const int*)d_in[4];
    const float* wts       = (const float*)d_in[5];
    const float* Wq   = (const float*)d_in[6];
    const float* bq   = (const float*)d_in[7];
    const float* Wk   = (const float*)d_in[8];
    const float* bk   = (const float*)d_in[9];
    const float* Wv   = (const float*)d_in[10];
    const float* bv   = (const float*)d_in[11];
    const float* Wq12 = (const float*)d_in[12];
    const float* bq12 = (const float*)d_in[13];
    const float* Wo1  = (const float*)d_in[14];
    const float* bo1  = (const float*)d_in[15];
    const float* Wo2  = (const float*)d_in[16];
    const float* bo2  = (const float*)d_in[17];
    float* out = (float*)d_out;

    float *q, *q1, *q2;
    __half *ih, *wh, *kvh, *kvl, *oh;
    cudaGetSymbolAddress((void**)&q,   g_q);
    cudaGetSymbolAddress((void**)&q1,  g_q1);
    cudaGetSymbolAddress((void**)&q2,  g_q2);
    cudaGetSymbolAddress((void**)&ih,  g_ih);
    cudaGetSymbolAddress((void**)&wh,  g_wh);
    cudaGetSymbolAddress((void**)&kvh, g_kvh);
    cudaGetSymbolAddress((void**)&kvl, g_kvl);
    cudaGetSymbolAddress((void**)&oh,  g_oh);

    cudaFuncSetAttribute(gemm_hf, cudaFuncAttributeMaxDynamicSharedMemorySize, GSMEM);
    cudaFuncSetAttribute(attn_mma, cudaFuncAttributeMaxDynamicSharedMemorySize, ASMEMB);

    // ---- prep: all matrices -> fp16 single; key compaction
    Prep pp;
    const float* srcs[9] = {interests, regions, grids, Wq, Wq12, Wk, Wv, Wo1, Wo2};
    for (int z = 0; z < 9; z++) {
        pp.src[z] = srcs[z];
        if (z < 3) { pp.dh[z] = ih + (size_t)z * INSEG;       pp.n4[z] = INSEG / 4; }
        else       { pp.dh[z] = wh + (size_t)(z - 3) * WSEG;  pp.n4[z] = WSEG / 4; }
    }
    prep_k<<<dim3(INSEG / 4 / 256, 9), 256>>>(pp);
    compact_k<<<4, 256>>>(maskR, maskG, wts);

    const __half *Ih = ih, *Rh = ih + INSEG, *Gh = ih + 2 * (size_t)INSEG;
    const __half *Wqh = wh, *Wq12h = wh + WSEG, *Wkh = wh + 2*(size_t)WSEG,
                 *Wvh = wh + 3*(size_t)WSEG, *Wo1h = wh + 4*(size_t)WSEG,
                 *Wo2h = wh + 5*(size_t)WSEG;

    // ---- 7 projections, one launch (K: hi+lo split; V: hi only)
    GBFpack pj;
    auto set = [&](int z, const __half* xh, const __half* wwh,
                   const float* bi, float* D, __half* Dh, __half* Dl, int mode) {
        pj.g[z].Xh = xh; pj.g[z].Wh = wwh;
        pj.g[z].Bi = bi; pj.g[z].D = D; pj.g[z].Dh = Dh; pj.g[z].Dl = Dl;
        pj.g[z].mode = mode;
    };
    set(0, Ih, Wqh,   bq,   q,  nullptr, nullptr, 0);
    set(1, Rh, Wq12h, bq12, q1, nullptr, nullptr, 0);
    set(2, Gh, Wq12h, bq12, q2, nullptr, nullptr, 0);
    set(3, Rh, Wkh,   bk,   nullptr, kvh + 0*(size_t)HEADELEMS, kvl + 0*(size_t)HEADELEMS, 1);
    set(4, Gh, Wkh,   bk,   nullptr, kvh + 1*(size_t)HEADELEMS, kvl + 1*(size_t)HEADELEMS, 1);
    set(5, Rh, Wvh,   bv,   nullptr, kvh + 2*(size_t)HEADELEMS, nullptr, 3);
    set(6, Gh, Wvh,   bv,   nullptr, kvh + 3*(size_t)HEADELEMS, nullptr, 3);
    gemm_hf<<<dim3(DMODEL / 128, MTOT / 128, 7), 256, GSMEM>>>(pj);

    // ---- attention (both variants), compacted keys
    attn_mma<<<dim3(NN / AQROWS, BB * HH, 2), 256, ASMEMB>>>();

    // ---- 2 output projections, one single-term launch
    GBFpack po;
    auto seto = [&](int z, int var, const __half* wwh, const float* bi, float* D) {
        po.g[z].Xh = oh + (size_t)var * OUTHALF;
        po.g[z].Wh = wwh; po.g[z].Bi = bi;
        po.g[z].D = D; po.g[z].Dh = nullptr; po.g[z].Dl = nullptr;
        po.g[z].mode = 2;
    };
    seto(0, 0, Wo1h, bo1, out);
    seto(1, 1, Wo2h, bo2, out + OUTHALF);
    for (int z = 2; z < 7; z++) po.g[z] = po.g[0];
    gemm_hf<<<dim3(DMODEL / 128, MTOT / 128, 2), 256, GSMEM>>>(po);
}

// round 17
// speedup vs baseline: 14.2318x; 1.1918x over previous
#include <cuda_runtime.h>
#include <cuda_fp16.h>
#include <math.h>
#include <stdint.h>

#define BB 2
#define NN 2048
#define DMODEL 512
#define HH 8
#define DK 64
#define MTOT (BB*NN)                 // 4096
#define HEADELEMS (BB*HH*NN*DK)      // 2097152
#define OUTHALF (MTOT*DMODEL)        // 2097152
#define INSEG (MTOT*DMODEL)          // 2097152 (one input matrix)
#define WSEG (DMODEL*DMODEL)         // 262144  (one weight matrix)

// ---------------- scratch (__device__ globals; allocation-free rule) --------
__device__ float g_q [HEADELEMS];
__device__ float g_q1[HEADELEMS];
__device__ float g_q2[HEADELEMS];
__device__ __half g_ih[3*INSEG];      // inputs fp16
__device__ __half g_wh[6*WSEG];       // weights fp16 (Wq, Wq12, Wk, Wv, Wo1, Wo2)
__device__ __half g_kvh[4*HEADELEMS]; // K1,K2,V1,V2 fp16 (single term)
__device__ __half g_oh[2*OUTHALF];    // O1,O2 fp16 (A-side of out-proj)
// key compaction per (var, batch): indices, coefficients, padded counts
__device__ int    g_cidx[4*NN];
__device__ float2 g_ccf [4*NN];
__device__ int    g_pcnt[4];

__device__ __forceinline__ uint32_t smem_u32(const void* p) {
    uint32_t a;
    asm("{ .reg .u64 t; cvta.to.shared.u64 t, %1; cvt.u32.u64 %0, t; }"
        : "=r"(a) : "l"(p));
    return a;
}

// ---- family-common PTX primitives (sm_80+: valid on .target sm_103) --------
__device__ __forceinline__ void ldm4(unsigned r[4], uint32_t addr) {
    asm volatile("ldmatrix.sync.aligned.m8n8.x4.shared.b16 {%0,%1,%2,%3}, [%4];"
        : "=r"(r[0]), "=r"(r[1]), "=r"(r[2]), "=r"(r[3]) : "r"(addr));
}
__device__ __forceinline__ void ldm4t(unsigned r[4], uint32_t addr) {
    asm volatile("ldmatrix.sync.aligned.m8n8.x4.trans.shared.b16 {%0,%1,%2,%3}, [%4];"
        : "=r"(r[0]), "=r"(r[1]), "=r"(r[2]), "=r"(r[3]) : "r"(addr));
}
__device__ __forceinline__ void mma16816(float c[4], const unsigned a[4],
                                         const unsigned b0, const unsigned b1) {
    asm volatile(
        "mma.sync.aligned.m16n8k16.row.col.f32.f16.f16.f32 "
        "{%0,%1,%2,%3}, {%4,%5,%6,%7}, {%8,%9}, {%0,%1,%2,%3};"
        : "+f"(c[0]), "+f"(c[1]), "+f"(c[2]), "+f"(c[3])
        : "r"(a[0]), "r"(a[1]), "r"(a[2]), "r"(a[3]), "r"(b0), "r"(b1));
}
#define CP_ASYNC16(dst, src) \
    asm volatile("cp.async.cg.shared.global [%0], [%1], 16;" \
        :: "r"(dst), "l"(src) : "memory")
#define CP_COMMIT() asm volatile("cp.async.commit_group;" ::: "memory")
#define CP_WAIT0()  asm volatile("cp.async.wait_group 0;" ::: "memory")

// pack 2 fp32 -> packed half2 (round, no residual)
__device__ __forceinline__ unsigned pack2h(float v0, float v1) {
    __half2 h = __floats2half2_rn(v0, v1);
    return *reinterpret_cast<unsigned*>(&h);
}
// 8 fp32 -> 8 fp16 (no residual)
__device__ __forceinline__ uint4 conv8h(float4 a, float4 b) {
    return make_uint4(pack2h(a.x, a.y), pack2h(a.z, a.w),
                      pack2h(b.x, b.y), pack2h(b.z, b.w));
}

// ===========================================================================
// Prep: all 9 fp32 matrices -> fp16 (single term)
// ===========================================================================
struct Prep {
    const float* src[9];
    __half* dh[9];
    int n4[9];
};

__global__ __launch_bounds__(256)
void prep_k(Prep pp)
{
    const int z  = blockIdx.y;
    const int i4 = blockIdx.x * 256 + threadIdx.x;
    if (i4 >= pp.n4[z]) return;
    float4 v = ((const float4*)pp.src[z])[i4];
    ((uint2*)pp.dh[z])[i4] = make_uint2(pack2h(v.x, v.y), pack2h(v.z, v.w));
}

// ===========================================================================
// Compact: per (var, batch), deterministic block-scan of the key mask ->
// ascending index list of unmasked keys + (mul, add) coefficients, padded
// to a multiple of 64 with fully-masked entries. grid = 4 blocks.
// ===========================================================================
__global__ __launch_bounds__(256)
void compact_k(const int* __restrict__ mR, const int* __restrict__ mG,
               const float* __restrict__ wts)
{
    const int cvi = blockIdx.x;          // var*2 + bb
    const int var = cvi >> 1, bb = cvi & 1;
    const int* msk = (var ? mG : mR) + bb * NN;
    const float* w = wts + bb * NN;
    __shared__ int sc[256];

    const int t = threadIdx.x;
    int keep[8];
    int cnt = 0;
#pragma unroll
    for (int j = 0; j < 8; j++) {
        const int key = t * 8 + j;
        if (msk[key] == 0) keep[cnt++] = key;
    }
    sc[t] = cnt;
    __syncthreads();
    for (int d = 1; d < 256; d <<= 1) {
        int v = (t >= d) ? sc[t - d] : 0;
        __syncthreads();
        sc[t] += v;
        __syncthreads();
    }
    const int off = sc[t] - cnt;
    const int total = sc[255];
    for (int j = 0; j < cnt; j++) {
        const int key = keep[j];
        g_cidx[cvi * NN + off + j] = key;
        g_ccf [cvi * NN + off + j] = make_float2(0.125f * w[key], 0.f);
    }
    const int padded = (total + 63) & ~63;
    for (int i = total + t; i < padded; i += 256) {
        g_cidx[cvi * NN + i] = 0;
        g_ccf [cvi * NN + i] = make_float2(0.f, -1e38f);
    }
    if (t == 0) g_pcnt[cvi] = padded;
}

// ===========================================================================
// cp.async double-buffered HMMA GEMM, single term: C = X16·W16 + bias.
// Block tile 128x128, 8 warps (2Mx4N), warp tile 64x32, K-chunk 32, 2 stages.
// mode: 0 HEADS fp32, 2 ROW fp32, 3 KV fp16.
// ===========================================================================
#define GRSTR 80
#define GMAT  (128 * GRSTR)            // 10240 per matrix
#define GSTG  (2 * GMAT)               // 20480 per stage (Xh, Wh)
#define GSMEM (2 * GSTG)               // 40960

struct GBF {
    const __half *Xh, *Wh;
    const float* Bi;
    float* D;
    __half* Dh;
    int mode;
};
struct GBFpack { GBF g[7]; };

__global__ __launch_bounds__(256, 2)
void gemm_hf(GBFpack gp)
{
    extern __shared__ __align__(16) char smc[];
    const uint32_t sb = smem_u32(smc);

    const GBF gb = gp.g[blockIdx.z];
    const int m0 = blockIdx.y * 128;
    const int n0 = blockIdx.x * 128;

    const int tid  = threadIdx.x;
    const int wid  = tid >> 5;
    const int lane = tid & 31;
    const int warpM = wid >> 2;
    const int warpN = wid & 3;

    const int arow  = (lane & 7) + ((lane >> 3) & 1) * 8;
    const int akoff = ((lane >> 4) & 1) * 16;
    const int brow  = (lane & 7) + ((lane >> 4) & 1) * 8;
    const int bkoff = ((lane >> 3) & 1) * 16;

    float c[4][4][4];
#pragma unroll
    for (int im = 0; im < 4; im++)
#pragma unroll
        for (int jn = 0; jn < 4; jn++)
#pragma unroll
            for (int e = 0; e < 4; e++) c[im][jn][e] = 0.f;

    auto issue = [&](int s, int kc) {
#pragma unroll
        for (int p = 0; p < 4; p++) {
            const int i = tid + p * 256;        // 0..1023
            const int t = i >> 9;               // 0 Xh, 1 Wh
            const int r = (i >> 2) & 127;
            const int cc = i & 3;
            const __half* src = (t == 0)
                ? gb.Xh + (size_t)(m0 + r) * DMODEL + kc * 32 + cc * 8
                : gb.Wh + (size_t)(n0 + r) * DMODEL + kc * 32 + cc * 8;
            CP_ASYNC16(sb + s * GSTG + t * GMAT + r * GRSTR + cc * 16, src);
        }
    };

    issue(0, 0);
    CP_COMMIT();

#pragma unroll 1
    for (int kc = 0; kc < 16; kc++) {
        const int b = kc & 1;
        CP_WAIT0();
        __syncthreads();
        if (kc < 15) { issue(b ^ 1, kc + 1); CP_COMMIT(); }

        const uint32_t sAh = sb + b * GSTG;
        const uint32_t sBh = sAh + GMAT;

#pragma unroll
        for (int ks = 0; ks < 2; ks++) {
            unsigned bh[2][4];
#pragma unroll
            for (int jp = 0; jp < 2; jp++) {
                const uint32_t bo = (uint32_t)((warpN * 32 + jp * 16 + brow) * GRSTR
                                               + ks * 32 + bkoff);
                ldm4(bh[jp], sBh + bo);
            }
#pragma unroll
            for (int im = 0; im < 4; im++) {
                const uint32_t ao = (uint32_t)((warpM * 64 + im * 16 + arow) * GRSTR
                                               + ks * 32 + akoff);
                unsigned ah[4];
                ldm4(ah, sAh + ao);
#pragma unroll
                for (int jn = 0; jn < 4; jn++) {
                    const int jp = jn >> 1, jo = (jn & 1) * 2;
                    mma16816(c[im][jn], ah, bh[jp][jo], bh[jp][jo + 1]);
                }
            }
        }
    }

    const int rbase = m0 + warpM * 64 + (lane >> 2);
    const int cbase = n0 + warpN * 32 + (lane & 3) * 2;
#pragma unroll
    for (int im = 0; im < 4; im++) {
#pragma unroll
        for (int jn = 0; jn < 4; jn++) {
            const int col = cbase + jn * 8;
            const float b0 = gb.Bi[col], b1 = gb.Bi[col + 1];
#pragma unroll
            for (int half = 0; half < 2; half++) {
                const int m  = rbase + im * 16 + half * 8;
                const float v0 = c[im][jn][half * 2]     + b0;
                const float v1 = c[im][jn][half * 2 + 1] + b1;
                if (gb.mode == 2) {
                    *(float2*)(gb.D + (size_t)m * DMODEL + col) = make_float2(v0, v1);
                } else {
                    const int bb = m >> 11;
                    const int n  = m & 2047;
                    const int h  = col >> 6, d = col & 63;
                    const size_t idx = (((size_t)(bb * HH + h)) * NN + n) * DK + d;
                    if (gb.mode == 0) {
                        *(float2*)(gb.D + idx) = make_float2(v0, v1);
                    } else {   // mode 3: fp16 single store (K and V)
                        *(unsigned*)(gb.Dh + idx) = pack2h(v0, v1);
                    }
                }
            }
        }
    }
}

// ===========================================================================
// cp.async double-buffered HMMA FlashAttention over COMPACTED keys.
// Single-term fp16 throughout: S = Q16·K16 ; O += P16·V16.
// Static-shift softmax (logits bounded; shift-invariant).
// Stage = 2 matrices (Kh, Vh), smem 37.9KB.
// ===========================================================================
#define AQROWS 128
#define ASTRB 144
#define KMAT (64*ASTRB)              // 9216
#define KVS (2*KMAT)                 // 18432 per stage (Kh,Vh)
#define ACF (2*KVS)                  // 36864
#define ASMEMB (ACF + 2*512)         // 37888

__global__ __launch_bounds__(256, 2)
void attn_mma()
{
    extern __shared__ __align__(16) char smn[];
    const uint32_t sb = smem_u32(smn);

    const int var = blockIdx.z;
    const int bh  = blockIdx.y;
    const int bb  = bh >> 3;
    const int h   = bh & 7;
    const int qt  = blockIdx.x;
    const int cvi = var * 2 + bb;

    const float* Q  = g_q + (size_t)bh * NN * DK + (size_t)qt * AQROWS * DK;
    const float* Qx = (var ? g_q1 : g_q2) + (size_t)bh * NN * DK + (size_t)qt * AQROWS * DK;
    const int*    cidx = g_cidx + cvi * NN;
    const float2* ccf  = g_ccf  + cvi * NN;
    const int ntk = g_pcnt[cvi] >> 6;

    const int tid  = threadIdx.x;
    const int wq   = tid >> 5;
    const int lane = tid & 31;
    const int lr   = lane & 7;
    const int g    = lane >> 3;

    const uint32_t qoff = (uint32_t)((wq * 16 + lr + (g & 1) * 8) * ASTRB + (g >> 1) * 16);
    const uint32_t koff = (uint32_t)((lr + (g >> 1) * 8) * ASTRB + (g & 1) * 16);
    const uint32_t voff = (uint32_t)((lr + (g & 1) * 8) * ASTRB + (g >> 1) * 16);

    // KV stage copy: Kh, Vh (2 matrices, 4 passes of 256)
    auto issueKV = [&](int s, int kt) {
        const int r0l = tid >> 3;
        const int gr0 = cidx[kt * 64 + r0l];
        const int gr1 = cidx[kt * 64 + r0l + 32];
#pragma unroll
        for (int p = 0; p < 4; p++) {
            const int i = tid + p * 256;
            const int t = i >> 9;               // 0 Kh, 1 Vh
            const int rl = r0l + 32 * (p & 1);
            const int gr = (p & 1) ? gr1 : gr0;
            const int cc = tid & 7;
            const __half* src = g_kvh + (size_t)(t ? (2 + var) : var) * HEADELEMS
                + (size_t)bh * NN * DK + (size_t)gr * DK + cc * 8;
            CP_ASYNC16(sb + s * KVS + t * KMAT + rl * ASTRB + cc * 16, src);
        }
    };

    // ---- stage Q (fp32 fused add -> fp16) into the stage-0 area
#pragma unroll
    for (int p = 0; p < 4; p++) {
        const int s   = tid + p * 256;
        const int row = s >> 3;
        const int c8  = (s & 7) * 8;
        float4 a0 = *(const float4*)(Q  + (size_t)row * DK + c8);
        float4 a1 = *(const float4*)(Q  + (size_t)row * DK + c8 + 4);
        float4 b0 = *(const float4*)(Qx + (size_t)row * DK + c8);
        float4 b1 = *(const float4*)(Qx + (size_t)row * DK + c8 + 4);
        a0.x += b0.x; a0.y += b0.y; a0.z += b0.z; a0.w += b0.w;
        a1.x += b1.x; a1.y += b1.y; a1.z += b1.z; a1.w += b1.w;
        *(uint4*)(smn + (uint32_t)(row * ASTRB + c8 * 2)) = conv8h(a0, a1);
    }
    __syncthreads();

    // ---- hoist Q fragments into registers (loop-invariant)
    unsigned aqh[4][4];
#pragma unroll
    for (int t = 0; t < 4; t++)
        ldm4(aqh[t], sb + qoff + 32 * t);
    __syncthreads();   // Q staging consumed; stage 0 may be overwritten

    // ---- prologue
    issueKV(0, 0);
    CP_COMMIT();
    if (tid < 64)
        *(float2*)(smn + ACF + tid * 8) = ccf[tid];

    float o[8][4];
#pragma unroll
    for (int j = 0; j < 8; j++)
#pragma unroll
        for (int e = 0; e < 4; e++) o[j][e] = 0.f;
    float l0 = 0.f, l1 = 0.f;

#pragma unroll 1
    for (int kt = 0; kt < ntk; kt++) {
        const int b = kt & 1;
        CP_WAIT0();
        __syncthreads();
        if (kt < ntk - 1) {
            issueKV(b ^ 1, kt + 1);
            CP_COMMIT();
            if (tid < 64)
                *(float2*)(smn + ACF + (b ^ 1) * 512 + tid * 8) = ccf[(kt + 1) * 64 + tid];
        }

        const uint32_t sKh = sb + b * KVS;
        const uint32_t sVh = sKh + KMAT;

        // ---- S = Q16 K16^T (single term)
        float s[8][4];
#pragma unroll
        for (int j = 0; j < 8; j++)
#pragma unroll
            for (int e = 0; e < 4; e++) s[j][e] = 0.f;

#pragma unroll
        for (int u = 0; u < 4; u++) {
#pragma unroll
            for (int t = 0; t < 4; t++) {
                unsigned bkh[4];
                const uint32_t ka = koff + (uint32_t)(u * 16 * ASTRB + 32 * t);
                ldm4(bkh, sKh + ka);
                mma16816(s[2*u],   aqh[t], bkh[0], bkh[1]);
                mma16816(s[2*u+1], aqh[t], bkh[2], bkh[3]);
            }
        }

        // ---- p = exp(s*mul + add), accumulate row sums, pack P (no max shift)
        unsigned pha[16];
        float rs0 = 0.f, rs1 = 0.f;
#pragma unroll
        for (int j = 0; j < 8; j++) {
            float4 cc = *(const float4*)(smn + ACF + b * 512 + (8 * j + (lane & 3) * 2) * 8);
            float p0 = __expf(fmaf(s[j][0], cc.x, cc.y));
            float p1 = __expf(fmaf(s[j][1], cc.z, cc.w));
            float p2 = __expf(fmaf(s[j][2], cc.x, cc.y));
            float p3 = __expf(fmaf(s[j][3], cc.z, cc.w));
            rs0 += p0 + p1;
            rs1 += p2 + p3;
            pha[2*j]   = pack2h(p0, p1);
            pha[2*j+1] = pack2h(p2, p3);
        }
        l0 += rs0;
        l1 += rs1;

        // ---- O += P16 V16 (single term)
#pragma unroll
        for (int t = 0; t < 4; t++) {
            const unsigned* aph = &pha[4 * t];
#pragma unroll
            for (int u = 0; u < 4; u++) {
                unsigned bvh[4];
                const uint32_t va = voff + (uint32_t)(t * 16 * ASTRB + 32 * u);
                ldm4t(bvh, sVh + va);
                mma16816(o[2*u],   aph, bvh[0], bvh[1]);
                mma16816(o[2*u+1], aph, bvh[2], bvh[3]);
            }
        }
    }

    // ---- row sums across the 4 lanes of each row-group
    l0 += __shfl_xor_sync(0xffffffffu, l0, 1);
    l0 += __shfl_xor_sync(0xffffffffu, l0, 2);
    l1 += __shfl_xor_sync(0xffffffffu, l1, 1);
    l1 += __shfl_xor_sync(0xffffffffu, l1, 2);

    // ---- epilogue: normalize, store fp16 to g_oh
    const float inv0 = 1.f / l0;
    const float inv1 = 1.f / l1;
    const int r = qt * AQROWS + wq * 16 + (lane >> 2);
    __half* Oh = g_oh + (size_t)var * OUTHALF;
#pragma unroll
    for (int j = 0; j < 8; j++) {
        const int col = h * DK + 8 * j + (lane & 3) * 2;
        const size_t i0 = ((size_t)bb * NN + r)     * DMODEL + col;
        const size_t i1 = ((size_t)bb * NN + r + 8) * DMODEL + col;
        *(unsigned*)(Oh + i0) = pack2h(o[j][0] * inv0, o[j][1] * inv0);
        *(unsigned*)(Oh + i1) = pack2h(o[j][2] * inv1, o[j][3] * inv1);
    }
}

// ===========================================================================
extern "C" void kernel_launch(void* const* d_in, const int* in_sizes, int n_in,
                              void* d_out, int out_size)
{
    const float* regions   = (const float*)d_in[0];
    const float* grids     = (const float*)d_in[1];
    const float* interests = (const float*)d_in[2];
    const int*   maskR     = (const int*)d_in[3];
    const int*   maskG     = (const int*)d_in[4];
    const float* wts       = (const float*)d_in[5];
    const float* Wq   = (const float*)d_in[6];
    const float* bq   = (const float*)d_in[7];
    const float* Wk   = (const float*)d_in[8];
    const float* bk   = (const float*)d_in[9];
    const float* Wv   = (const float*)d_in[10];
    const float* bv   = (const float*)d_in[11];
    const float* Wq12 = (const float*)d_in[12];
    const float* bq12 = (const float*)d_in[13];
    const float* Wo1  = (const float*)d_in[14];
    const float* bo1  = (const float*)d_in[15];
    const float* Wo2  = (const float*)d_in[16];
    const float* bo2  = (const float*)d_in[17];
    float* out = (float*)d_out;

    float *q, *q1, *q2;
    __half *ih, *wh, *kvh, *oh;
    cudaGetSymbolAddress((void**)&q,   g_q);
    cudaGetSymbolAddress((void**)&q1,  g_q1);
    cudaGetSymbolAddress((void**)&q2,  g_q2);
    cudaGetSymbolAddress((void**)&ih,  g_ih);
    cudaGetSymbolAddress((void**)&wh,  g_wh);
    cudaGetSymbolAddress((void**)&kvh, g_kvh);
    cudaGetSymbolAddress((void**)&oh,  g_oh);

    cudaFuncSetAttribute(gemm_hf, cudaFuncAttributeMaxDynamicSharedMemorySize, GSMEM);
    cudaFuncSetAttribute(attn_mma, cudaFuncAttributeMaxDynamicSharedMemorySize, ASMEMB);

    // ---- prep: all matrices -> fp16 single; key compaction
    Prep pp;
    const float* srcs[9] = {interests, regions, grids, Wq, Wq12, Wk, Wv, Wo1, Wo2};
    for (int z = 0; z < 9; z++) {
        pp.src[z] = srcs[z];
        if (z < 3) { pp.dh[z] = ih + (size_t)z * INSEG;       pp.n4[z] = INSEG / 4; }
        else       { pp.dh[z] = wh + (size_t)(z - 3) * WSEG;  pp.n4[z] = WSEG / 4; }
    }
    prep_k<<<dim3(INSEG / 4 / 256, 9), 256>>>(pp);
    compact_k<<<4, 256>>>(maskR, maskG, wts);

    const __half *Ih = ih, *Rh = ih + INSEG, *Gh = ih + 2 * (size_t)INSEG;
    const __half *Wqh = wh, *Wq12h = wh + WSEG, *Wkh = wh + 2*(size_t)WSEG,
                 *Wvh = wh + 3*(size_t)WSEG, *Wo1h = wh + 4*(size_t)WSEG,
                 *Wo2h = wh + 5*(size_t)WSEG;

    // ---- 7 projections, one launch (K and V: fp16 single store)
    GBFpack pj;
    auto set = [&](int z, const __half* xh, const __half* wwh,
                   const float* bi, float* D, __half* Dh, int mode) {
        pj.g[z].Xh = xh; pj.g[z].Wh = wwh;
        pj.g[z].Bi = bi; pj.g[z].D = D; pj.g[z].Dh = Dh;
        pj.g[z].mode = mode;
    };
    set(0, Ih, Wqh,   bq,   q,  nullptr, 0);
    set(1, Rh, Wq12h, bq12, q1, nullptr, 0);
    set(2, Gh, Wq12h, bq12, q2, nullptr, 0);
    set(3, Rh, Wkh,   bk,   nullptr, kvh + 0*(size_t)HEADELEMS, 3);
    set(4, Gh, Wkh,   bk,   nullptr, kvh + 1*(size_t)HEADELEMS, 3);
    set(5, Rh, Wvh,   bv,   nullptr, kvh + 2*(size_t)HEADELEMS, 3);
    set(6, Gh, Wvh,   bv,   nullptr, kvh + 3*(size_t)HEADELEMS, 3);
    gemm_hf<<<dim3(DMODEL / 128, MTOT / 128, 7), 256, GSMEM>>>(pj);

    // ---- attention (both variants), compacted keys
    attn_mma<<<dim3(NN / AQROWS, BB * HH, 2), 256, ASMEMB>>>();

    // ---- 2 output projections, one single-term launch
    GBFpack po;
    auto seto = [&](int z, int var, const __half* wwh, const float* bi, float* D) {
        po.g[z].Xh = oh + (size_t)var * OUTHALF;
        po.g[z].Wh = wwh; po.g[z].Bi = bi;
        po.g[z].D = D; po.g[z].Dh = nullptr;
        po.g[z].mode = 2;
    };
    seto(0, 0, Wo1h, bo1, out);
    seto(1, 1, Wo2h, bo2, out + OUTHALF);
    for (int z = 2; z < 7; z++) po.g[z] = po.g[0];
    gemm_hf<<<dim3(DMODEL / 128, MTOT / 128, 2), 256, GSMEM>>>(po);
}